// round 11
// baseline (speedup 1.0000x reference)
#include <cuda_runtime.h>
#include <cuda_bf16.h>
#include <math.h>
#include <cstdint>

// Problem constants
#define BB 2
#define TT 2048
#define CC 1024
#define HH 16
#define HDIM 64
#define BT (BB * TT)      // 4096 rows
#define LOG2T 11

typedef unsigned long long u64;
typedef unsigned int u32;

// ---------------------------------------------------------------------------
// Packed f32x2 helpers (Blackwell sm_103a)
// ---------------------------------------------------------------------------
__device__ __forceinline__ u64 pk2(float lo, float hi) {
    u64 r;
    asm("mov.b64 %0, {%1, %2};" : "=l"(r) : "f"(lo), "f"(hi));
    return r;
}
__device__ __forceinline__ u64 dup2(float v) { return pk2(v, v); }
__device__ __forceinline__ void upk2(float& lo, float& hi, u64 v) {
    asm("mov.b64 {%0, %1}, %2;" : "=f"(lo), "=f"(hi) : "l"(v));
}
__device__ __forceinline__ void fma2(u64& d, u64 a, u64 b) {
    asm("fma.rn.f32x2 %0, %1, %2, %0;" : "+l"(d) : "l"(a), "l"(b));
}
__device__ __forceinline__ void mul2(u64& d, u64 a, u64 b) {
    asm("mul.rn.f32x2 %0, %1, %2;" : "=l"(d) : "l"(a), "l"(b));
}

// ---------------------------------------------------------------------------
// mma.sync / ldmatrix / cp.async helpers (compute_103-legal PTX)
// ---------------------------------------------------------------------------
__device__ __forceinline__ u32 smem_u32(const void* p) {
    u32 a;
    asm("{ .reg .u64 t; cvta.to.shared.u64 t, %1; cvt.u32.u64 %0, t; }"
        : "=r"(a) : "l"(p));
    return a;
}
__device__ __forceinline__ void cpasync16(u32 smem_dst, const void* gptr) {
    asm volatile("cp.async.ca.shared.global [%0], [%1], 16;"
                 :: "r"(smem_dst), "l"(gptr));
}
__device__ __forceinline__ void cpcommit() {
    asm volatile("cp.async.commit_group;");
}
__device__ __forceinline__ void cpwait0() {
    asm volatile("cp.async.wait_group 0;");
}
__device__ __forceinline__ void ldsm_x4(u32& r0, u32& r1, u32& r2, u32& r3,
                                        u32 addr) {
    asm volatile("ldmatrix.sync.aligned.m8n8.x4.shared.b16 {%0,%1,%2,%3}, [%4];"
                 : "=r"(r0), "=r"(r1), "=r"(r2), "=r"(r3) : "r"(addr));
}
__device__ __forceinline__ void mma_bf16(float* c, const u32* a, const u32* b) {
    asm volatile(
        "mma.sync.aligned.m16n8k16.row.col.f32.bf16.bf16.f32 "
        "{%0,%1,%2,%3}, {%4,%5,%6,%7}, {%8,%9}, {%0,%1,%2,%3};"
        : "+f"(c[0]), "+f"(c[1]), "+f"(c[2]), "+f"(c[3])
        : "r"(a[0]), "r"(a[1]), "r"(a[2]), "r"(a[3]), "r"(b[0]), "r"(b[1]));
}

// ----------------------------------------------------------------------------
// Device scratch (static; no allocations allowed)
// ----------------------------------------------------------------------------
static __device__ float g_q[BT * CC];
static __device__ float g_k[BT * CC];
static __device__ float g_v[BT * CC];
static __device__ float g_qr[BT * CC];
static __device__ float g_qi[BT * CC];
static __device__ float g_kr[BT * CC];
static __device__ float g_ki[BT * CC];
static __device__ float g_vr[BT * CC];
static __device__ float g_y[BT * CC];
static __device__ float g_inE[BT];
// bf16x3 splits
static __device__ __nv_bfloat16 g_xh[BT * CC];
static __device__ __nv_bfloat16 g_xm[BT * CC];
static __device__ __nv_bfloat16 g_xl[BT * CC];
static __device__ __nv_bfloat16 g_wt[12 * CC * CC];   // 4 weights x {h,m,l}, [N][K]

// ----------------------------------------------------------------------------
// Reductions
// ----------------------------------------------------------------------------
__device__ __forceinline__ float blockReduceSum256(float v) {
    __shared__ float red[8];
    int lane = threadIdx.x & 31;
    int w = threadIdx.x >> 5;
#pragma unroll
    for (int o = 16; o >= 1; o >>= 1)
        v += __shfl_xor_sync(0xffffffffu, v, o);
    if (lane == 0) red[w] = v;
    __syncthreads();
    if (w == 0) {
        v = (lane < 8) ? red[lane] : 0.f;
#pragma unroll
        for (int o = 4; o >= 1; o >>= 1)
            v += __shfl_xor_sync(0xffffffffu, v, o);
    }
    return v;  // valid in thread 0
}

// ----------------------------------------------------------------------------
// Fused: input energy ||x[row,:]|| + bf16x3 split of x (one pass over x)
// ----------------------------------------------------------------------------
__global__ void energy_split_kernel(const float* __restrict__ x,
                                    __nv_bfloat16* __restrict__ H,
                                    __nv_bfloat16* __restrict__ M,
                                    __nv_bfloat16* __restrict__ L) {
    int row = blockIdx.x;
    const float* xr = x + (size_t)row * CC;
    float s = 0.f;
    for (int c = threadIdx.x; c < CC; c += 256) {
        float v = xr[c];
        s += v * v;
        __nv_bfloat16 h = __float2bfloat16(v);
        float r = v - __bfloat162float(h);
        __nv_bfloat16 m = __float2bfloat16(r);
        r -= __bfloat162float(m);
        size_t o = (size_t)row * CC + c;
        H[o] = h; M[o] = m; L[o] = __float2bfloat16(r);
    }
    float tot = blockReduceSum256(s);
    if (threadIdx.x == 0) g_inE[row] = sqrtf(tot);
}

// ----------------------------------------------------------------------------
// Transpose + split W[k][n] -> WT{h,m,l}[n][k] bf16
// ----------------------------------------------------------------------------
__global__ void wsplit_kernel(const float* __restrict__ W,
                              __nv_bfloat16* __restrict__ H,
                              __nv_bfloat16* __restrict__ M,
                              __nv_bfloat16* __restrict__ L) {
    __shared__ float t[32][33];
    int n0 = blockIdx.x << 5, k0 = blockIdx.y << 5;
    int tx = threadIdx.x, ty = threadIdx.y;
#pragma unroll
    for (int i = 0; i < 4; i++)
        t[ty + i * 8][tx] = W[(size_t)(k0 + ty + i * 8) * CC + n0 + tx];
    __syncthreads();
#pragma unroll
    for (int i = 0; i < 4; i++) {
        int n = n0 + ty + i * 8;
        float x = t[tx][ty + i * 8];
        __nv_bfloat16 h = __float2bfloat16(x);
        float r = x - __bfloat162float(h);
        __nv_bfloat16 m = __float2bfloat16(r);
        r -= __bfloat162float(m);
        size_t o = (size_t)n * CC + k0 + tx;
        H[o] = h; M[o] = m; L[o] = __float2bfloat16(r);
    }
}

// ----------------------------------------------------------------------------
// Tensor-core GEMM via mma.sync bf16x3 (emulated fp32):
// Co[4096,1024] = A @ B^T + bias. A splits [M][K], B(=W^T) splits [N][K].
// Block 128x128, BK=32, 8 warps (2x4), warp tile 64x32 (4x4 m16n8k16 atoms).
// 6 split-products: hh, hm, mh, mm, hl, lh (error ~2^-24).
// ----------------------------------------------------------------------------
#define ASTRIDE 40
#define SPLITB (2 * 128 * ASTRIDE * 2)   // bytes per split (both buffers)
#define BUFB   (128 * ASTRIDE * 2)       // bytes per buffer

__global__ void __launch_bounds__(256, 1)
tc_gemm_kernel(const __nv_bfloat16* __restrict__ Ah,
               const __nv_bfloat16* __restrict__ Am,
               const __nv_bfloat16* __restrict__ Al,
               const __nv_bfloat16* __restrict__ Bh,
               const __nv_bfloat16* __restrict__ Bm,
               const __nv_bfloat16* __restrict__ Bl,
               const float* __restrict__ bias, float* __restrict__ Co) {
    extern __shared__ __align__(16) __nv_bfloat16 smb[];
    __nv_bfloat16* sB = smb + 3 * 2 * 128 * ASTRIDE;
    const u32 sAu = smem_u32(smb);
    const u32 sBu = smem_u32(sB);

    const int tid = threadIdx.x;
    const int wid = tid >> 5, lane = tid & 31;
    const int wm = wid >> 2, wn = wid & 3;        // warps 2 (m) x 4 (n)
    const int m0 = blockIdx.y << 7, n0 = blockIdx.x << 7;

    const __nv_bfloat16* Asrc[3] = {Ah, Am, Al};
    const __nv_bfloat16* Bsrc[3] = {Bh, Bm, Bl};

    float acc[4][4][4];
#pragma unroll
    for (int i = 0; i < 4; i++)
#pragma unroll
        for (int j = 0; j < 4; j++)
#pragma unroll
            for (int r = 0; r < 4; r++) acc[i][j][r] = 0.f;

    const int ldr0 = tid >> 2, ldk0 = (tid & 3) << 3;
    const int ldr1 = (tid + 256) >> 2, ldk1 = ((tid + 256) & 3) << 3;

    const u32 aRowB = (u32)(((lane & 7) + ((lane >> 3) & 1) * 8) * (ASTRIDE * 2));
    const u32 aKB   = (u32)(((lane >> 4) & 1) * 16);
    const u32 bRowB = (u32)(((lane & 7) + ((lane >> 4) & 1) * 8) * (ASTRIDE * 2));
    const u32 bKB   = (u32)(((lane >> 3) & 1) * 16);

#define ISSUE_CHUNK(c, buf)                                                     \
    do {                                                                        \
        _Pragma("unroll")                                                       \
        for (int t_ = 0; t_ < 3; t_++) {                                        \
            const __nv_bfloat16* ga = Asrc[t_] + (size_t)(m0 + ldr0) * CC +     \
                                      (c) * 32 + ldk0;                          \
            const __nv_bfloat16* ga1 = Asrc[t_] + (size_t)(m0 + ldr1) * CC +    \
                                       (c) * 32 + ldk1;                         \
            const __nv_bfloat16* gb = Bsrc[t_] + (size_t)(n0 + ldr0) * CC +     \
                                      (c) * 32 + ldk0;                          \
            const __nv_bfloat16* gb1 = Bsrc[t_] + (size_t)(n0 + ldr1) * CC +    \
                                       (c) * 32 + ldk1;                         \
            u32 d0 = (u32)(t_ * SPLITB + (buf) * BUFB +                         \
                           (ldr0 * ASTRIDE + ldk0) * 2);                        \
            u32 d1 = (u32)(t_ * SPLITB + (buf) * BUFB +                         \
                           (ldr1 * ASTRIDE + ldk1) * 2);                        \
            cpasync16(sAu + d0, ga);                                            \
            cpasync16(sAu + d1, ga1);                                           \
            cpasync16(sBu + d0, gb);                                            \
            cpasync16(sBu + d1, gb1);                                           \
        }                                                                       \
        cpcommit();                                                             \
    } while (0)

    ISSUE_CHUNK(0, 0);

    for (int c = 0; c < 32; c++) {
        const int buf = c & 1;
        cpwait0();
        __syncthreads();
        if (c + 1 < 32) ISSUE_CHUNK(c + 1, buf ^ 1);

#pragma unroll
        for (int ks = 0; ks < 2; ks++) {
            u32 af[3][4][4];
#pragma unroll
            for (int t = 0; t < 3; t++)
#pragma unroll
                for (int mi = 0; mi < 4; mi++) {
                    u32 addr = sAu + (u32)(t * SPLITB + buf * BUFB) +
                               (u32)((wm * 64 + mi * 16) * (ASTRIDE * 2)) +
                               aRowB + (u32)(ks * 32) + aKB;
                    ldsm_x4(af[t][mi][0], af[t][mi][1], af[t][mi][2],
                            af[t][mi][3], addr);
                }
#pragma unroll
            for (int bt = 0; bt < 3; bt++) {
                u32 bfr[2][4];
#pragma unroll
                for (int np = 0; np < 2; np++) {
                    u32 addr = sBu + (u32)(bt * SPLITB + buf * BUFB) +
                               (u32)((wn * 32 + np * 16) * (ASTRIDE * 2)) +
                               bRowB + (u32)(ks * 32) + bKB;
                    ldsm_x4(bfr[np][0], bfr[np][1], bfr[np][2], bfr[np][3],
                            addr);
                }
                const int nA = (bt == 0) ? 3 : (bt == 1) ? 2 : 1;
#pragma unroll
                for (int ia = 0; ia < 3; ia++) {
                    if (ia >= nA) break;
#pragma unroll
                    for (int mi = 0; mi < 4; mi++)
#pragma unroll
                        for (int ni = 0; ni < 4; ni++)
                            mma_bf16(acc[mi][ni], af[ia][mi],
                                     &bfr[ni >> 1][(ni & 1) * 2]);
                }
            }
        }
        __syncthreads();
    }

    const int grp = lane >> 2, qd = lane & 3;
#pragma unroll
    for (int mi = 0; mi < 4; mi++) {
#pragma unroll
        for (int ni = 0; ni < 4; ni++) {
            int row = m0 + wm * 64 + mi * 16 + grp;
            int col = n0 + wn * 32 + ni * 8 + qd * 2;
            float b0 = bias[col], b1 = bias[col + 1];
            float2 o0 = make_float2(acc[mi][ni][0] + b0, acc[mi][ni][1] + b1);
            float2 o1 = make_float2(acc[mi][ni][2] + b0, acc[mi][ni][3] + b1);
            *(float2*)&Co[(size_t)row * CC + col] = o0;
            *(float2*)&Co[(size_t)(row + 8) * CC + col] = o1;
        }
    }
}

// ----------------------------------------------------------------------------
// Batched FFT: one block per (tensor, b, h, 8-dim group). All three tensors
// (Q, K, V) handled by one launch; twiddles shared across the 8 columns.
// ----------------------------------------------------------------------------
#define FSTR 9
__global__ void __launch_bounds__(256, 1)
fft_filter_kernel(const float* __restrict__ inQ, const float* __restrict__ inK,
                  const float* __restrict__ inV,
                  float* __restrict__ oQr, float* __restrict__ oQi,
                  float* __restrict__ oKr, float* __restrict__ oKi,
                  float* __restrict__ oVr,
                  const float* __restrict__ fd,
                  const float* __restrict__ alpha,
                  const float* __restrict__ fas) {
    extern __shared__ __align__(16) float2 sh[];   // sh[t*FSTR + c], c<8
    const int dg = blockIdx.x;          // d-group 0..7
    const int which = blockIdx.y >> 4;  // 0=Q 1=K 2=V
    const int h = blockIdx.y & 15;
    const int b = blockIdx.z;
    const float* in = (which == 0) ? inQ : (which == 1) ? inK : inV;
    float* outRe = (which == 0) ? oQr : (which == 1) ? oKr : oVr;
    float* outIm = (which == 0) ? oQi : (which == 1) ? oKi : (float*)0;

    const int col0 = h * HDIM + dg * 8;
    const float* src = in + (size_t)b * TT * CC + col0;
    const int tid = threadIdx.x;

#pragma unroll
    for (int i = 0; i < 32; i++) {
        int e = tid + i * 256;
        int t = e >> 2, pr = e & 3;
        float2 v = *(const float2*)&src[(size_t)t * CC + pr * 2];
        unsigned r = __brev((unsigned)t) >> (32 - LOG2T);
        sh[r * FSTR + pr * 2]     = make_float2(v.x, 0.f);
        sh[r * FSTR + pr * 2 + 1] = make_float2(v.y, 0.f);
    }
    __syncthreads();

    for (int st = 1; st <= LOG2T; st++) {
        const int half = 1 << (st - 1);
        const float wstep = -6.283185307179586f / (float)(half * 2);
#pragma unroll
        for (int w = 0; w < 4; w++) {
            int idx = tid + w * 256;
            int pos = idx & (half - 1);
            int grp = idx >> (st - 1);
            int i0 = (grp << st) + pos;
            int i1 = i0 + half;
            float sn, cs;
            __sincosf(wstep * (float)pos, &sn, &cs);
            float2* p0 = &sh[i0 * FSTR];
            float2* p1 = &sh[i1 * FSTR];
#pragma unroll
            for (int c = 0; c < 8; c++) {
                float2 u = p0[c], v = p1[c];
                float tr = cs * v.x - sn * v.y;
                float ti = cs * v.y + sn * v.x;
                p0[c] = make_float2(u.x + tr, u.y + ti);
                p1[c] = make_float2(u.x - tr, u.y - ti);
            }
        }
        __syncthreads();
    }

    const float aal = alpha[0] + fas[0] * (fd[0] - 1.5f);
    const size_t obase = ((size_t)(b * HH + h)) * TT * HDIM + dg * 8;
#pragma unroll
    for (int i = 0; i < 8; i++) {
        int t = tid + i * 256;
        float fr = (float)(t < TT / 2 ? t : t - TT) * (1.0f / (float)TT);
        float phase = aal * atanf(logf(fabsf(fr) + 1e-10f));
        float sp, cp;
        sincosf(phase, &sp, &cp);
        const float2* p = &sh[t * FSTR];
        float re[8], im[8];
#pragma unroll
        for (int c = 0; c < 8; c++) {
            float2 X = p[c];
            re[c] = X.x * cp - X.y * sp;
            im[c] = X.x * sp + X.y * cp;
        }
        size_t o = obase + (size_t)t * HDIM;
        *(float4*)&outRe[o]     = make_float4(re[0], re[1], re[2], re[3]);
        *(float4*)&outRe[o + 4] = make_float4(re[4], re[5], re[6], re[7]);
        if (outIm) {
            *(float4*)&outIm[o]     = make_float4(im[0], im[1], im[2], im[3]);
            *(float4*)&outIm[o + 4] = make_float4(im[4], im[5], im[6], im[7]);
        }
    }
}

// ----------------------------------------------------------------------------
// Flash attention per (b,h). 128x128 tiles, 1024 threads (8 warps/SMSP for
// latency hiding), per-thread 2x8 tile, column-packed f32x2. Epilogue writes
// the bf16x3 split of O directly (feeds the wo tc-GEMM).
// ----------------------------------------------------------------------------
__global__ void __launch_bounds__(1024, 1)
attn_kernel(const float* __restrict__ Qr, const float* __restrict__ Qi,
            const float* __restrict__ Kr, const float* __restrict__ Ki,
            const float* __restrict__ Vr,
            __nv_bfloat16* __restrict__ Oh, __nv_bfloat16* __restrict__ Om,
            __nv_bfloat16* __restrict__ Ol) {
    extern __shared__ __align__(16) float smbuf[];
    float* sQr = smbuf;                 // [d=64][132]
    float* sQi = sQr + 64 * 132;
    float* sKr = sQi + 64 * 132;        // [d=64][132]
    float* sKi = sKr + 64 * 132;        // holds -Ki
    float* sV  = sKi + 64 * 132;        // [s=128][68]
    float* sP  = sKr;                   // [t=128][132], aliases Kr+Ki

    const int tid = threadIdx.x;
    const int ty = tid >> 4, tx = tid & 15;   // ty 0..63, tx 0..15
    const int t0 = blockIdx.x << 7;
    const int h = blockIdx.y, b = blockIdx.z;
    const size_t base = ((size_t)(b * HH + h)) * TT * HDIM;
    const int r0 = ty << 1;                   // 2 rows per thread
    const int c0 = tx << 2;                   // 4+4 cols per thread

    // load Q tile (transposed into [d][t])
#pragma unroll
    for (int i = 0; i < 2; i++) {
        int e = tid + i * 1024;         // 0..2047
        int r = e >> 4, c4 = (e & 15) << 2;
        size_t g = base + (size_t)(t0 + r) * HDIM + c4;
        float4 qr = *(const float4*)&Qr[g];
        float4 qi = *(const float4*)&Qi[g];
        sQr[(c4 + 0) * 132 + r] = qr.x;
        sQr[(c4 + 1) * 132 + r] = qr.y;
        sQr[(c4 + 2) * 132 + r] = qr.z;
        sQr[(c4 + 3) * 132 + r] = qr.w;
        sQi[(c4 + 0) * 132 + r] = qi.x;
        sQi[(c4 + 1) * 132 + r] = qi.y;
        sQi[(c4 + 2) * 132 + r] = qi.z;
        sQi[(c4 + 3) * 132 + r] = qi.w;
    }

    float m[2], l[2];
    u64 acc2[2][2];                     // [row][col-pair]
#pragma unroll
    for (int i = 0; i < 2; i++) { m[i] = -INFINITY; l[i] = 0.f; }
#pragma unroll
    for (int i = 0; i < 2; i++) { acc2[i][0] = 0ull; acc2[i][1] = 0ull; }

    for (int s0 = 0; s0 < TT; s0 += 128) {
        __syncthreads();  // P/V consumed (and Q visible on first iter)
#pragma unroll
        for (int i = 0; i < 2; i++) {
            int e = tid + i * 1024;
            int r = e >> 4, c4 = (e & 15) << 2;
            size_t g = base + (size_t)(s0 + r) * HDIM + c4;
            float4 kr = *(const float4*)&Kr[g];
            float4 ki = *(const float4*)&Ki[g];
            sKr[(c4 + 0) * 132 + r] = kr.x;
            sKr[(c4 + 1) * 132 + r] = kr.y;
            sKr[(c4 + 2) * 132 + r] = kr.z;
            sKr[(c4 + 3) * 132 + r] = kr.w;
            sKi[(c4 + 0) * 132 + r] = -ki.x;
            sKi[(c4 + 1) * 132 + r] = -ki.y;
            sKi[(c4 + 2) * 132 + r] = -ki.z;
            sKi[(c4 + 3) * 132 + r] = -ki.w;
            *(float4*)&sV[r * 68 + c4] = *(const float4*)&Vr[g];
        }
        __syncthreads();

        // ---- S tile: [2 rows][4 col-pairs]; K pairs direct from smem ----
        u64 S2[2][4];
#pragma unroll
        for (int i = 0; i < 2; i++)
#pragma unroll
            for (int j = 0; j < 4; j++) S2[i][j] = 0ull;

#pragma unroll 8
        for (int d = 0; d < 64; d++) {
            float2 q2 = *(const float2*)&sQr[d * 132 + r0];
            float2 p2 = *(const float2*)&sQi[d * 132 + r0];
            ulonglong2 K0 = *(const ulonglong2*)&sKr[d * 132 + c0];
            ulonglong2 K1 = *(const ulonglong2*)&sKr[d * 132 + 64 + c0];
            ulonglong2 J0 = *(const ulonglong2*)&sKi[d * 132 + c0];
            ulonglong2 J1 = *(const ulonglong2*)&sKi[d * 132 + 64 + c0];
            u64 kp[4] = {K0.x, K0.y, K1.x, K1.y};
            u64 jp[4] = {J0.x, J0.y, J1.x, J1.y};
            float qv[2] = {q2.x, q2.y};
            float pv_[2] = {p2.x, p2.y};
#pragma unroll
            for (int i = 0; i < 2; i++) {
                u64 qd = dup2(qv[i]);
                u64 pd = dup2(pv_[i]);
#pragma unroll
                for (int cp = 0; cp < 4; cp++) {
                    fma2(S2[i][cp], qd, kp[cp]);
                    fma2(S2[i][cp], pd, jp[cp]);
                }
            }
        }
        __syncthreads();  // all K reads done before P overwrites that smem

        float S[2][8];
#pragma unroll
        for (int i = 0; i < 2; i++)
#pragma unroll
            for (int cp = 0; cp < 4; cp++)
                upk2(S[i][2 * cp], S[i][2 * cp + 1], S2[i][cp]);

        // ---- online softmax; write P into aliased smem ----
        float corr[2];
#pragma unroll
        for (int i = 0; i < 2; i++) {
            float mx = S[i][0];
#pragma unroll
            for (int j = 1; j < 8; j++) mx = fmaxf(mx, S[i][j]);
            mx *= 0.125f;
#pragma unroll
            for (int o = 8; o >= 1; o >>= 1)
                mx = fmaxf(mx, __shfl_xor_sync(0xffffffffu, mx, o));
            float mn = fmaxf(m[i], mx);
            corr[i] = __expf(m[i] - mn);
            float ps = 0.f;
            float pv[8];
#pragma unroll
            for (int j = 0; j < 8; j++) {
                float p = __expf(S[i][j] * 0.125f - mn);
                pv[j] = p;
                ps += p;
            }
            *(float4*)&sP[(r0 + i) * 132 + c0] =
                make_float4(pv[0], pv[1], pv[2], pv[3]);
            *(float4*)&sP[(r0 + i) * 132 + 64 + c0] =
                make_float4(pv[4], pv[5], pv[6], pv[7]);
#pragma unroll
            for (int o = 8; o >= 1; o >>= 1)
                ps += __shfl_xor_sync(0xffffffffu, ps, o);
            l[i] = l[i] * corr[i] + ps;
            m[i] = mn;
        }
#pragma unroll
        for (int i = 0; i < 2; i++) {
            u64 cd = dup2(corr[i]);
            u64 t0r, t1r;
            mul2(t0r, acc2[i][0], cd);
            mul2(t1r, acc2[i][1], cd);
            acc2[i][0] = t0r;
            acc2[i][1] = t1r;
        }
        __syncthreads();

        // ---- O += P @ V: V pairs direct from smem, P scalars dup'd ----
#pragma unroll 8
        for (int s = 0; s < 128; s += 2) {
            ulonglong2 V0 = *(const ulonglong2*)&sV[s * 68 + c0];
            ulonglong2 V1 = *(const ulonglong2*)&sV[(s + 1) * 68 + c0];
#pragma unroll
            for (int i = 0; i < 2; i++) {
                float2 pp = *(const float2*)&sP[(r0 + i) * 132 + s];
                u64 pd0 = dup2(pp.x);
                u64 pd1 = dup2(pp.y);
                fma2(acc2[i][0], pd0, V0.x);
                fma2(acc2[i][1], pd0, V0.y);
                fma2(acc2[i][0], pd1, V1.x);
                fma2(acc2[i][1], pd1, V1.y);
            }
        }
    }

    // epilogue: normalize and write bf16x3 splits at [b, t, h*64+d]
#pragma unroll
    for (int i = 0; i < 2; i++) {
        float a[4];
        upk2(a[0], a[1], acc2[i][0]);
        upk2(a[2], a[3], acc2[i][1]);
        float inv = 1.f / l[i];
        size_t off = ((size_t)(b * TT + t0 + r0 + i)) * CC + h * HDIM + c0;
        __nv_bfloat162 h2[2], m2[2], l2[2];
#pragma unroll
        for (int c = 0; c < 4; c++) {
            float v = a[c] * inv;
            __nv_bfloat16 hb = __float2bfloat16(v);
            float r = v - __bfloat162float(hb);
            __nv_bfloat16 mb = __float2bfloat16(r);
            r -= __bfloat162float(mb);
            __nv_bfloat16 lb = __float2bfloat16(r);
            if (c & 1) {
                h2[c >> 1].y = hb; m2[c >> 1].y = mb; l2[c >> 1].y = lb;
            } else {
                h2[c >> 1].x = hb; m2[c >> 1].x = mb; l2[c >> 1].x = lb;
            }
        }
        *(__nv_bfloat162*)&Oh[off]     = h2[0];
        *(__nv_bfloat162*)&Oh[off + 2] = h2[1];
        *(__nv_bfloat162*)&Om[off]     = m2[0];
        *(__nv_bfloat162*)&Om[off + 2] = m2[1];
        *(__nv_bfloat162*)&Ol[off]     = l2[0];
        *(__nv_bfloat162*)&Ol[off + 2] = l2[1];
    }
}

// ----------------------------------------------------------------------------
// Final energy ratio: out = Y * (inE / (||Y row|| + 1e-8)) * energy_normalizer
// ----------------------------------------------------------------------------
__global__ void finalize_kernel(const float* __restrict__ Y,
                                const float* __restrict__ enorm,
                                float* __restrict__ out) {
    int row = blockIdx.x;
    const float* yr = Y + (size_t)row * CC;
    float s = 0.f;
    for (int c = threadIdx.x; c < CC; c += 256) {
        float v = yr[c];
        s += v * v;
    }
    float tot = blockReduceSum256(s);
    __shared__ float ratio;
    if (threadIdx.x == 0)
        ratio = g_inE[row] / (sqrtf(tot) + 1e-8f) * enorm[0];
    __syncthreads();
    for (int c = threadIdx.x; c < CC; c += 256)
        out[(size_t)row * CC + c] = yr[c] * ratio;
}

// ----------------------------------------------------------------------------
// Launch
// ----------------------------------------------------------------------------
extern "C" void kernel_launch(void* const* d_in, const int* in_sizes, int n_in,
                              void* d_out, int out_size) {
    const float* x      = (const float*)d_in[0];
    const float* fd     = (const float*)d_in[1];
    const float* wq     = (const float*)d_in[2];
    const float* bq     = (const float*)d_in[3];
    const float* wk     = (const float*)d_in[4];
    const float* bk     = (const float*)d_in[5];
    const float* wv     = (const float*)d_in[6];
    const float* bv     = (const float*)d_in[7];
    const float* wo     = (const float*)d_in[8];
    const float* bo     = (const float*)d_in[9];
    const float* alpha  = (const float*)d_in[10];
    const float* fas    = (const float*)d_in[11];
    const float* enorm  = (const float*)d_in[12];
    float* out = (float*)d_out;

    float *q, *k, *v, *qr, *qi, *kr, *ki, *vr, *y;
    __nv_bfloat16 *xh, *xm, *xl, *wt;
    cudaGetSymbolAddress((void**)&q,  g_q);
    cudaGetSymbolAddress((void**)&k,  g_k);
    cudaGetSymbolAddress((void**)&v,  g_v);
    cudaGetSymbolAddress((void**)&qr, g_qr);
    cudaGetSymbolAddress((void**)&qi, g_qi);
    cudaGetSymbolAddress((void**)&kr, g_kr);
    cudaGetSymbolAddress((void**)&ki, g_ki);
    cudaGetSymbolAddress((void**)&vr, g_vr);
    cudaGetSymbolAddress((void**)&y,  g_y);
    cudaGetSymbolAddress((void**)&xh, g_xh);
    cudaGetSymbolAddress((void**)&xm, g_xm);
    cudaGetSymbolAddress((void**)&xl, g_xl);
    cudaGetSymbolAddress((void**)&wt, g_wt);
    const size_t WSZ = (size_t)CC * CC;

    // fused: input energies + x split
    energy_split_kernel<<<BT, 256>>>(x, xh, xm, xl);

    // weight transpose+split
    dim3 wg(32, 32), wb(32, 8);
    wsplit_kernel<<<wg, wb>>>(wq, wt + 0 * WSZ, wt + 1 * WSZ, wt + 2 * WSZ);
    wsplit_kernel<<<wg, wb>>>(wk, wt + 3 * WSZ, wt + 4 * WSZ, wt + 5 * WSZ);
    wsplit_kernel<<<wg, wb>>>(wv, wt + 6 * WSZ, wt + 7 * WSZ, wt + 8 * WSZ);
    wsplit_kernel<<<wg, wb>>>(wo, wt + 9 * WSZ, wt + 10 * WSZ, wt + 11 * WSZ);

    // QKV projections on tensor cores (mma.sync bf16x3)
    static const int kTcSmem = 2 * 3 * 2 * 128 * ASTRIDE * (int)sizeof(__nv_bfloat16);
    cudaFuncSetAttribute(tc_gemm_kernel,
                         cudaFuncAttributeMaxDynamicSharedMemorySize, kTcSmem);
    dim3 gg(CC / 128, BT / 128);
    tc_gemm_kernel<<<gg, 256, kTcSmem>>>(xh, xm, xl,
                                         wt + 0 * WSZ, wt + 1 * WSZ, wt + 2 * WSZ,
                                         bq, q);
    tc_gemm_kernel<<<gg, 256, kTcSmem>>>(xh, xm, xl,
                                         wt + 3 * WSZ, wt + 4 * WSZ, wt + 5 * WSZ,
                                         bk, k);
    tc_gemm_kernel<<<gg, 256, kTcSmem>>>(xh, xm, xl,
                                         wt + 6 * WSZ, wt + 7 * WSZ, wt + 8 * WSZ,
                                         bv, v);

    // FFT + spectral filter, all three tensors in one launch
    static const int kFftSmem = TT * FSTR * (int)sizeof(float2);  // 147456
    cudaFuncSetAttribute(fft_filter_kernel,
                         cudaFuncAttributeMaxDynamicSharedMemorySize, kFftSmem);
    dim3 gf(HDIM / 8, HH * 3, BB);
    fft_filter_kernel<<<gf, 256, kFftSmem>>>(q, k, v, qr, qi, kr, ki, vr,
                                             fd, alpha, fas);

    // attention (writes O splits directly into xh/xm/xl)
    static const int kAttnSmem = (4 * 64 * 132 + 128 * 68) * (int)sizeof(float);
    cudaFuncSetAttribute(attn_kernel, cudaFuncAttributeMaxDynamicSharedMemorySize,
                         kAttnSmem);
    dim3 ga(TT / 128, HH, BB);
    attn_kernel<<<ga, 1024, kAttnSmem>>>(qr, qi, kr, ki, vr, xh, xm, xl);

    // output projection
    tc_gemm_kernel<<<gg, 256, kTcSmem>>>(xh, xm, xl,
                                         wt + 9 * WSZ, wt + 10 * WSZ, wt + 11 * WSZ,
                                         bo, y);

    // energy-ratio epilogue
    finalize_kernel<<<BT, 256>>>(y, enorm, out);
}

// round 12
// speedup vs baseline: 1.3426x; 1.3426x over previous
#include <cuda_runtime.h>
#include <cuda_bf16.h>
#include <math.h>
#include <cstdint>

// Problem constants
#define BB 2
#define TT 2048
#define CC 1024
#define HH 16
#define HDIM 64
#define BT (BB * TT)      // 4096 rows
#define LOG2T 11

typedef unsigned long long u64;
typedef unsigned int u32;

// ---------------------------------------------------------------------------
// Packed f32x2 helpers (Blackwell sm_103a)
// ---------------------------------------------------------------------------
__device__ __forceinline__ u64 pk2(float lo, float hi) {
    u64 r;
    asm("mov.b64 %0, {%1, %2};" : "=l"(r) : "f"(lo), "f"(hi));
    return r;
}
__device__ __forceinline__ u64 dup2(float v) { return pk2(v, v); }
__device__ __forceinline__ void upk2(float& lo, float& hi, u64 v) {
    asm("mov.b64 {%0, %1}, %2;" : "=f"(lo), "=f"(hi) : "l"(v));
}
__device__ __forceinline__ void fma2(u64& d, u64 a, u64 b) {
    asm("fma.rn.f32x2 %0, %1, %2, %0;" : "+l"(d) : "l"(a), "l"(b));
}
__device__ __forceinline__ void mul2(u64& d, u64 a, u64 b) {
    asm("mul.rn.f32x2 %0, %1, %2;" : "=l"(d) : "l"(a), "l"(b));
}

// ---------------------------------------------------------------------------
// mma.sync / ldmatrix / cp.async helpers (compute_103-legal PTX)
// ---------------------------------------------------------------------------
__device__ __forceinline__ u32 smem_u32(const void* p) {
    u32 a;
    asm("{ .reg .u64 t; cvta.to.shared.u64 t, %1; cvt.u32.u64 %0, t; }"
        : "=r"(a) : "l"(p));
    return a;
}
__device__ __forceinline__ void cpasync16(u32 smem_dst, const void* gptr) {
    asm volatile("cp.async.ca.shared.global [%0], [%1], 16;"
                 :: "r"(smem_dst), "l"(gptr));
}
__device__ __forceinline__ void cpcommit() {
    asm volatile("cp.async.commit_group;");
}
__device__ __forceinline__ void cpwait0() {
    asm volatile("cp.async.wait_group 0;");
}
__device__ __forceinline__ void ldsm_x4(u32& r0, u32& r1, u32& r2, u32& r3,
                                        u32 addr) {
    asm volatile("ldmatrix.sync.aligned.m8n8.x4.shared.b16 {%0,%1,%2,%3}, [%4];"
                 : "=r"(r0), "=r"(r1), "=r"(r2), "=r"(r3) : "r"(addr));
}
__device__ __forceinline__ void mma_bf16(float* c, const u32* a, const u32* b) {
    asm volatile(
        "mma.sync.aligned.m16n8k16.row.col.f32.bf16.bf16.f32 "
        "{%0,%1,%2,%3}, {%4,%5,%6,%7}, {%8,%9}, {%0,%1,%2,%3};"
        : "+f"(c[0]), "+f"(c[1]), "+f"(c[2]), "+f"(c[3])
        : "r"(a[0]), "r"(a[1]), "r"(a[2]), "r"(a[3]), "r"(b[0]), "r"(b[1]));
}

// ----------------------------------------------------------------------------
// Device scratch (static; no allocations allowed)
// ----------------------------------------------------------------------------
static __device__ float g_q[BT * CC];
static __device__ float g_k[BT * CC];
static __device__ float g_v[BT * CC];
static __device__ float g_qr[BT * CC];
static __device__ float g_qi[BT * CC];
static __device__ float g_kr[BT * CC];
static __device__ float g_ki[BT * CC];
static __device__ float g_vr[BT * CC];
static __device__ float g_y[BT * CC];
static __device__ float g_inE[BT];
// bf16x3 splits
static __device__ __nv_bfloat16 g_xh[BT * CC];
static __device__ __nv_bfloat16 g_xm[BT * CC];
static __device__ __nv_bfloat16 g_xl[BT * CC];
static __device__ __nv_bfloat16 g_wt[12 * CC * CC];   // 4 weights x {h,m,l}, [N][K]

// ----------------------------------------------------------------------------
// Reductions
// ----------------------------------------------------------------------------
__device__ __forceinline__ float blockReduceSum256(float v) {
    __shared__ float red[8];
    int lane = threadIdx.x & 31;
    int w = threadIdx.x >> 5;
#pragma unroll
    for (int o = 16; o >= 1; o >>= 1)
        v += __shfl_xor_sync(0xffffffffu, v, o);
    if (lane == 0) red[w] = v;
    __syncthreads();
    if (w == 0) {
        v = (lane < 8) ? red[lane] : 0.f;
#pragma unroll
        for (int o = 4; o >= 1; o >>= 1)
            v += __shfl_xor_sync(0xffffffffu, v, o);
    }
    return v;  // valid in thread 0
}

// ----------------------------------------------------------------------------
// Fused: input energy ||x[row,:]|| + bf16x3 split of x (one pass over x)
// ----------------------------------------------------------------------------
__global__ void energy_split_kernel(const float* __restrict__ x,
                                    __nv_bfloat16* __restrict__ H,
                                    __nv_bfloat16* __restrict__ M,
                                    __nv_bfloat16* __restrict__ L) {
    int row = blockIdx.x;
    const float* xr = x + (size_t)row * CC;
    float s = 0.f;
    for (int c = threadIdx.x; c < CC; c += 256) {
        float v = xr[c];
        s += v * v;
        __nv_bfloat16 h = __float2bfloat16(v);
        float r = v - __bfloat162float(h);
        __nv_bfloat16 m = __float2bfloat16(r);
        r -= __bfloat162float(m);
        size_t o = (size_t)row * CC + c;
        H[o] = h; M[o] = m; L[o] = __float2bfloat16(r);
    }
    float tot = blockReduceSum256(s);
    if (threadIdx.x == 0) g_inE[row] = sqrtf(tot);
}

// ----------------------------------------------------------------------------
// Transpose + split W[k][n] -> WT{h,m,l}[n][k] bf16; grid.z selects weight
// ----------------------------------------------------------------------------
__global__ void wsplit4_kernel(const float* __restrict__ W0,
                               const float* __restrict__ W1,
                               const float* __restrict__ W2,
                               const float* __restrict__ W3,
                               __nv_bfloat16* __restrict__ WT) {
    __shared__ float t[32][33];
    const int wsel = blockIdx.z;
    const float* W = (wsel == 0) ? W0 : (wsel == 1) ? W1 : (wsel == 2) ? W2 : W3;
    __nv_bfloat16* H = WT + (size_t)(3 * wsel + 0) * CC * CC;
    __nv_bfloat16* M = WT + (size_t)(3 * wsel + 1) * CC * CC;
    __nv_bfloat16* L = WT + (size_t)(3 * wsel + 2) * CC * CC;
    int n0 = blockIdx.x << 5, k0 = blockIdx.y << 5;
    int tx = threadIdx.x, ty = threadIdx.y;
#pragma unroll
    for (int i = 0; i < 4; i++)
        t[ty + i * 8][tx] = W[(size_t)(k0 + ty + i * 8) * CC + n0 + tx];
    __syncthreads();
#pragma unroll
    for (int i = 0; i < 4; i++) {
        int n = n0 + ty + i * 8;
        float x = t[tx][ty + i * 8];
        __nv_bfloat16 h = __float2bfloat16(x);
        float r = x - __bfloat162float(h);
        __nv_bfloat16 m = __float2bfloat16(r);
        r -= __bfloat162float(m);
        size_t o = (size_t)n * CC + k0 + tx;
        H[o] = h; M[o] = m; L[o] = __float2bfloat16(r);
    }
}

// ----------------------------------------------------------------------------
// Tensor-core GEMM body via mma.sync bf16x3 (emulated fp32):
// Co[4096,1024] = A @ B^T + bias. Block 128x128, BK=32, 8 warps.
// ----------------------------------------------------------------------------
#define ASTRIDE 40
#define SPLITB (2 * 128 * ASTRIDE * 2)   // bytes per split (both buffers)
#define BUFB   (128 * ASTRIDE * 2)       // bytes per buffer

__device__ __forceinline__ void tc_gemm_body(
    const __nv_bfloat16* __restrict__ Ah, const __nv_bfloat16* __restrict__ Am,
    const __nv_bfloat16* __restrict__ Al, const __nv_bfloat16* __restrict__ Bh,
    const __nv_bfloat16* __restrict__ Bm, const __nv_bfloat16* __restrict__ Bl,
    const float* __restrict__ bias, float* __restrict__ Co,
    __nv_bfloat16* smb, int m0, int n0) {
    __nv_bfloat16* sB = smb + 3 * 2 * 128 * ASTRIDE;
    const u32 sAu = smem_u32(smb);
    const u32 sBu = smem_u32(sB);

    const int tid = threadIdx.x;
    const int wid = tid >> 5, lane = tid & 31;
    const int wm = wid >> 2, wn = wid & 3;        // warps 2 (m) x 4 (n)

    const __nv_bfloat16* Asrc[3] = {Ah, Am, Al};
    const __nv_bfloat16* Bsrc[3] = {Bh, Bm, Bl};

    float acc[4][4][4];
#pragma unroll
    for (int i = 0; i < 4; i++)
#pragma unroll
        for (int j = 0; j < 4; j++)
#pragma unroll
            for (int r = 0; r < 4; r++) acc[i][j][r] = 0.f;

    const int ldr0 = tid >> 2, ldk0 = (tid & 3) << 3;
    const int ldr1 = (tid + 256) >> 2, ldk1 = ((tid + 256) & 3) << 3;

    const u32 aRowB = (u32)(((lane & 7) + ((lane >> 3) & 1) * 8) * (ASTRIDE * 2));
    const u32 aKB   = (u32)(((lane >> 4) & 1) * 16);
    const u32 bRowB = (u32)(((lane & 7) + ((lane >> 4) & 1) * 8) * (ASTRIDE * 2));
    const u32 bKB   = (u32)(((lane >> 3) & 1) * 16);

#define ISSUE_CHUNK(c, buf)                                                     \
    do {                                                                        \
        _Pragma("unroll")                                                       \
        for (int t_ = 0; t_ < 3; t_++) {                                        \
            const __nv_bfloat16* ga = Asrc[t_] + (size_t)(m0 + ldr0) * CC +     \
                                      (c) * 32 + ldk0;                          \
            const __nv_bfloat16* ga1 = Asrc[t_] + (size_t)(m0 + ldr1) * CC +    \
                                       (c) * 32 + ldk1;                         \
            const __nv_bfloat16* gb = Bsrc[t_] + (size_t)(n0 + ldr0) * CC +     \
                                      (c) * 32 + ldk0;                          \
            const __nv_bfloat16* gb1 = Bsrc[t_] + (size_t)(n0 + ldr1) * CC +    \
                                       (c) * 32 + ldk1;                         \
            u32 d0 = (u32)(t_ * SPLITB + (buf) * BUFB +                         \
                           (ldr0 * ASTRIDE + ldk0) * 2);                        \
            u32 d1 = (u32)(t_ * SPLITB + (buf) * BUFB +                         \
                           (ldr1 * ASTRIDE + ldk1) * 2);                        \
            cpasync16(sAu + d0, ga);                                            \
            cpasync16(sAu + d1, ga1);                                           \
            cpasync16(sBu + d0, gb);                                            \
            cpasync16(sBu + d1, gb1);                                           \
        }                                                                       \
        cpcommit();                                                             \
    } while (0)

    ISSUE_CHUNK(0, 0);

    for (int c = 0; c < 32; c++) {
        const int buf = c & 1;
        cpwait0();
        __syncthreads();
        if (c + 1 < 32) ISSUE_CHUNK(c + 1, buf ^ 1);

#pragma unroll
        for (int ks = 0; ks < 2; ks++) {
            u32 af[3][4][4];
#pragma unroll
            for (int t = 0; t < 3; t++)
#pragma unroll
                for (int mi = 0; mi < 4; mi++) {
                    u32 addr = sAu + (u32)(t * SPLITB + buf * BUFB) +
                               (u32)((wm * 64 + mi * 16) * (ASTRIDE * 2)) +
                               aRowB + (u32)(ks * 32) + aKB;
                    ldsm_x4(af[t][mi][0], af[t][mi][1], af[t][mi][2],
                            af[t][mi][3], addr);
                }
#pragma unroll
            for (int bt = 0; bt < 3; bt++) {
                u32 bfr[2][4];
#pragma unroll
                for (int np = 0; np < 2; np++) {
                    u32 addr = sBu + (u32)(bt * SPLITB + buf * BUFB) +
                               (u32)((wn * 32 + np * 16) * (ASTRIDE * 2)) +
                               bRowB + (u32)(ks * 32) + bKB;
                    ldsm_x4(bfr[np][0], bfr[np][1], bfr[np][2], bfr[np][3],
                            addr);
                }
                const int nA = (bt == 0) ? 3 : (bt == 1) ? 2 : 1;
#pragma unroll
                for (int ia = 0; ia < 3; ia++) {
                    if (ia >= nA) break;
#pragma unroll
                    for (int mi = 0; mi < 4; mi++)
#pragma unroll
                        for (int ni = 0; ni < 4; ni++)
                            mma_bf16(acc[mi][ni], af[ia][mi],
                                     &bfr[ni >> 1][(ni & 1) * 2]);
                }
            }
        }
        __syncthreads();
    }

    const int grp = lane >> 2, qd = lane & 3;
#pragma unroll
    for (int mi = 0; mi < 4; mi++) {
#pragma unroll
        for (int ni = 0; ni < 4; ni++) {
            int row = m0 + wm * 64 + mi * 16 + grp;
            int col = n0 + wn * 32 + ni * 8 + qd * 2;
            float b0 = bias[col], b1 = bias[col + 1];
            float2 o0 = make_float2(acc[mi][ni][0] + b0, acc[mi][ni][1] + b1);
            float2 o1 = make_float2(acc[mi][ni][2] + b0, acc[mi][ni][3] + b1);
            *(float2*)&Co[(size_t)row * CC + col] = o0;
            *(float2*)&Co[(size_t)(row + 8) * CC + col] = o1;
        }
    }
}

// single-output GEMM (wo projection)
__global__ void __launch_bounds__(256, 1)
tc_gemm_kernel(const __nv_bfloat16* __restrict__ Ah,
               const __nv_bfloat16* __restrict__ Am,
               const __nv_bfloat16* __restrict__ Al,
               const __nv_bfloat16* __restrict__ Bh,
               const __nv_bfloat16* __restrict__ Bm,
               const __nv_bfloat16* __restrict__ Bl,
               const float* __restrict__ bias, float* __restrict__ Co) {
    extern __shared__ __align__(16) __nv_bfloat16 smb[];
    tc_gemm_body(Ah, Am, Al, Bh, Bm, Bl, bias, Co, smb,
                 blockIdx.y << 7, blockIdx.x << 7);
}

// batched QKV GEMM: grid.z = 0/1/2 -> (wq->q), (wk->k), (wv->v)
__global__ void __launch_bounds__(256, 1)
tc_gemm3_kernel(const __nv_bfloat16* __restrict__ Ah,
                const __nv_bfloat16* __restrict__ Am,
                const __nv_bfloat16* __restrict__ Al,
                const __nv_bfloat16* __restrict__ WT,
                const float* __restrict__ bq, const float* __restrict__ bk,
                const float* __restrict__ bv,
                float* __restrict__ Q, float* __restrict__ K,
                float* __restrict__ V) {
    extern __shared__ __align__(16) __nv_bfloat16 smb[];
    const int z = blockIdx.z;
    const __nv_bfloat16* B = WT + (size_t)(3 * z) * CC * CC;
    const float* bias = (z == 0) ? bq : (z == 1) ? bk : bv;
    float* Co = (z == 0) ? Q : (z == 1) ? K : V;
    tc_gemm_body(Ah, Am, Al, B, B + (size_t)CC * CC, B + (size_t)2 * CC * CC,
                 bias, Co, smb, blockIdx.y << 7, blockIdx.x << 7);
}

// ----------------------------------------------------------------------------
// Batched FFT: one block per (tensor, b, h, 8-dim group). All three tensors
// (Q, K, V) handled by one launch; twiddles shared across the 8 columns.
// ----------------------------------------------------------------------------
#define FSTR 9
__global__ void __launch_bounds__(256, 1)
fft_filter_kernel(const float* __restrict__ inQ, const float* __restrict__ inK,
                  const float* __restrict__ inV,
                  float* __restrict__ oQr, float* __restrict__ oQi,
                  float* __restrict__ oKr, float* __restrict__ oKi,
                  float* __restrict__ oVr,
                  const float* __restrict__ fd,
                  const float* __restrict__ alpha,
                  const float* __restrict__ fas) {
    extern __shared__ __align__(16) float2 sh[];   // sh[t*FSTR + c], c<8
    const int dg = blockIdx.x;          // d-group 0..7
    const int which = blockIdx.y >> 4;  // 0=Q 1=K 2=V
    const int h = blockIdx.y & 15;
    const int b = blockIdx.z;
    const float* in = (which == 0) ? inQ : (which == 1) ? inK : inV;
    float* outRe = (which == 0) ? oQr : (which == 1) ? oKr : oVr;
    float* outIm = (which == 0) ? oQi : (which == 1) ? oKi : (float*)0;

    const int col0 = h * HDIM + dg * 8;
    const float* src = in + (size_t)b * TT * CC + col0;
    const int tid = threadIdx.x;

#pragma unroll
    for (int i = 0; i < 32; i++) {
        int e = tid + i * 256;
        int t = e >> 2, pr = e & 3;
        float2 v = *(const float2*)&src[(size_t)t * CC + pr * 2];
        unsigned r = __brev((unsigned)t) >> (32 - LOG2T);
        sh[r * FSTR + pr * 2]     = make_float2(v.x, 0.f);
        sh[r * FSTR + pr * 2 + 1] = make_float2(v.y, 0.f);
    }
    __syncthreads();

    for (int st = 1; st <= LOG2T; st++) {
        const int half = 1 << (st - 1);
        const float wstep = -6.283185307179586f / (float)(half * 2);
#pragma unroll
        for (int w = 0; w < 4; w++) {
            int idx = tid + w * 256;
            int pos = idx & (half - 1);
            int grp = idx >> (st - 1);
            int i0 = (grp << st) + pos;
            int i1 = i0 + half;
            float sn, cs;
            __sincosf(wstep * (float)pos, &sn, &cs);
            float2* p0 = &sh[i0 * FSTR];
            float2* p1 = &sh[i1 * FSTR];
#pragma unroll
            for (int c = 0; c < 8; c++) {
                float2 u = p0[c], v = p1[c];
                float tr = cs * v.x - sn * v.y;
                float ti = cs * v.y + sn * v.x;
                p0[c] = make_float2(u.x + tr, u.y + ti);
                p1[c] = make_float2(u.x - tr, u.y - ti);
            }
        }
        __syncthreads();
    }

    const float aal = alpha[0] + fas[0] * (fd[0] - 1.5f);
    const size_t obase = ((size_t)(b * HH + h)) * TT * HDIM + dg * 8;
#pragma unroll
    for (int i = 0; i < 8; i++) {
        int t = tid + i * 256;
        float fr = (float)(t < TT / 2 ? t : t - TT) * (1.0f / (float)TT);
        float phase = aal * atanf(logf(fabsf(fr) + 1e-10f));
        float sp, cp;
        sincosf(phase, &sp, &cp);
        const float2* p = &sh[t * FSTR];
        float re[8], im[8];
#pragma unroll
        for (int c = 0; c < 8; c++) {
            float2 X = p[c];
            re[c] = X.x * cp - X.y * sp;
            im[c] = X.x * sp + X.y * cp;
        }
        size_t o = obase + (size_t)t * HDIM;
        *(float4*)&outRe[o]     = make_float4(re[0], re[1], re[2], re[3]);
        *(float4*)&outRe[o + 4] = make_float4(re[4], re[5], re[6], re[7]);
        if (outIm) {
            *(float4*)&outIm[o]     = make_float4(im[0], im[1], im[2], im[3]);
            *(float4*)&outIm[o + 4] = make_float4(im[4], im[5], im[6], im[7]);
        }
    }
}

// ----------------------------------------------------------------------------
// Flash attention per (b,h). 128x128 tiles, 512 threads, column-packed f32x2.
// (Round-10 configuration — measured best; 1024-thread variant regressed.)
// Epilogue writes the bf16x3 split of O directly.
// ----------------------------------------------------------------------------
__global__ void __launch_bounds__(512, 1)
attn_kernel(const float* __restrict__ Qr, const float* __restrict__ Qi,
            const float* __restrict__ Kr, const float* __restrict__ Ki,
            const float* __restrict__ Vr,
            __nv_bfloat16* __restrict__ Oh, __nv_bfloat16* __restrict__ Om,
            __nv_bfloat16* __restrict__ Ol) {
    extern __shared__ __align__(16) float smbuf[];
    float* sQr = smbuf;                 // [d=64][132]
    float* sQi = sQr + 64 * 132;
    float* sKr = sQi + 64 * 132;        // [d=64][132]
    float* sKi = sKr + 64 * 132;        // holds -Ki
    float* sV  = sKi + 64 * 132;        // [s=128][68]
    float* sP  = sKr;                   // [t=128][132], aliases Kr+Ki

    const int tid = threadIdx.x;
    const int ty = tid >> 4, tx = tid & 15;   // ty 0..31, tx 0..15
    const int t0 = blockIdx.x << 7;
    const int h = blockIdx.y, b = blockIdx.z;
    const size_t base = ((size_t)(b * HH + h)) * TT * HDIM;
    const int r0 = ty << 2;                   // 4 rows per thread
    const int c0 = tx << 2;                   // 4+4 cols per thread

    // load Q tile (transposed into [d][t])
#pragma unroll
    for (int i = 0; i < 4; i++) {
        int e = tid + i * 512;          // 0..2047
        int r = e >> 4, c4 = (e & 15) << 2;
        size_t g = base + (size_t)(t0 + r) * HDIM + c4;
        float4 qr = *(const float4*)&Qr[g];
        float4 qi = *(const float4*)&Qi[g];
        sQr[(c4 + 0) * 132 + r] = qr.x;
        sQr[(c4 + 1) * 132 + r] = qr.y;
        sQr[(c4 + 2) * 132 + r] = qr.z;
        sQr[(c4 + 3) * 132 + r] = qr.w;
        sQi[(c4 + 0) * 132 + r] = qi.x;
        sQi[(c4 + 1) * 132 + r] = qi.y;
        sQi[(c4 + 2) * 132 + r] = qi.z;
        sQi[(c4 + 3) * 132 + r] = qi.w;
    }

    float m[4], l[4];
    u64 acc2[4][2];                     // [row][col-pair]
#pragma unroll
    for (int i = 0; i < 4; i++) { m[i] = -INFINITY; l[i] = 0.f; }
#pragma unroll
    for (int i = 0; i < 4; i++) { acc2[i][0] = 0ull; acc2[i][1] = 0ull; }

    for (int s0 = 0; s0 < TT; s0 += 128) {
        __syncthreads();  // P/V consumed (and Q visible on first iter)
#pragma unroll
        for (int i = 0; i < 4; i++) {
            int e = tid + i * 512;
            int r = e >> 4, c4 = (e & 15) << 2;
            size_t g = base + (size_t)(s0 + r) * HDIM + c4;
            float4 kr = *(const float4*)&Kr[g];
            float4 ki = *(const float4*)&Ki[g];
            sKr[(c4 + 0) * 132 + r] = kr.x;
            sKr[(c4 + 1) * 132 + r] = kr.y;
            sKr[(c4 + 2) * 132 + r] = kr.z;
            sKr[(c4 + 3) * 132 + r] = kr.w;
            sKi[(c4 + 0) * 132 + r] = -ki.x;
            sKi[(c4 + 1) * 132 + r] = -ki.y;
            sKi[(c4 + 2) * 132 + r] = -ki.z;
            sKi[(c4 + 3) * 132 + r] = -ki.w;
            *(float4*)&sV[r * 68 + c4] = *(const float4*)&Vr[g];
        }
        __syncthreads();

        // ---- S tile: [4 rows][4 col-pairs]; K pairs direct from smem ----
        u64 S2[4][4];
#pragma unroll
        for (int i = 0; i < 4; i++)
#pragma unroll
            for (int j = 0; j < 4; j++) S2[i][j] = 0ull;

#pragma unroll 8
        for (int d = 0; d < 64; d++) {
            float4 q4 = *(const float4*)&sQr[d * 132 + r0];
            float4 p4 = *(const float4*)&sQi[d * 132 + r0];
            ulonglong2 K0 = *(const ulonglong2*)&sKr[d * 132 + c0];
            ulonglong2 K1 = *(const ulonglong2*)&sKr[d * 132 + 64 + c0];
            ulonglong2 J0 = *(const ulonglong2*)&sKi[d * 132 + c0];
            ulonglong2 J1 = *(const ulonglong2*)&sKi[d * 132 + 64 + c0];
            u64 kp[4] = {K0.x, K0.y, K1.x, K1.y};
            u64 jp[4] = {J0.x, J0.y, J1.x, J1.y};
            float qv[4] = {q4.x, q4.y, q4.z, q4.w};
            float pv_[4] = {p4.x, p4.y, p4.z, p4.w};
#pragma unroll
            for (int i = 0; i < 4; i++) {
                u64 qd = dup2(qv[i]);
                u64 pd = dup2(pv_[i]);
#pragma unroll
                for (int cp = 0; cp < 4; cp++) {
                    fma2(S2[i][cp], qd, kp[cp]);
                    fma2(S2[i][cp], pd, jp[cp]);
                }
            }
        }
        __syncthreads();  // all K reads done before P overwrites that smem

        float S[4][8];
#pragma unroll
        for (int i = 0; i < 4; i++)
#pragma unroll
            for (int cp = 0; cp < 4; cp++)
                upk2(S[i][2 * cp], S[i][2 * cp + 1], S2[i][cp]);

        // ---- online softmax; write P into aliased smem ----
        float corr[4];
#pragma unroll
        for (int i = 0; i < 4; i++) {
            float mx = S[i][0];
#pragma unroll
            for (int j = 1; j < 8; j++) mx = fmaxf(mx, S[i][j]);
            mx *= 0.125f;
#pragma unroll
            for (int o = 8; o >= 1; o >>= 1)
                mx = fmaxf(mx, __shfl_xor_sync(0xffffffffu, mx, o));
            float mn = fmaxf(m[i], mx);
            corr[i] = __expf(m[i] - mn);
            float ps = 0.f;
            float pv[8];
#pragma unroll
            for (int j = 0; j < 8; j++) {
                float p = __expf(S[i][j] * 0.125f - mn);
                pv[j] = p;
                ps += p;
            }
            *(float4*)&sP[(r0 + i) * 132 + c0] =
                make_float4(pv[0], pv[1], pv[2], pv[3]);
            *(float4*)&sP[(r0 + i) * 132 + 64 + c0] =
                make_float4(pv[4], pv[5], pv[6], pv[7]);
#pragma unroll
            for (int o = 8; o >= 1; o >>= 1)
                ps += __shfl_xor_sync(0xffffffffu, ps, o);
            l[i] = l[i] * corr[i] + ps;
            m[i] = mn;
        }
#pragma unroll
        for (int i = 0; i < 4; i++) {
            u64 cd = dup2(corr[i]);
            u64 t0r, t1r;
            mul2(t0r, acc2[i][0], cd);
            mul2(t1r, acc2[i][1], cd);
            acc2[i][0] = t0r;
            acc2[i][1] = t1r;
        }
        __syncthreads();

        // ---- O += P @ V: V pairs direct from smem, P scalars dup'd ----
#pragma unroll 8
        for (int s = 0; s < 128; s += 2) {
            ulonglong2 V0 = *(const ulonglong2*)&sV[s * 68 + c0];
            ulonglong2 V1 = *(const ulonglong2*)&sV[(s + 1) * 68 + c0];
#pragma unroll
            for (int i = 0; i < 4; i++) {
                float2 pp = *(const float2*)&sP[(r0 + i) * 132 + s];
                u64 pd0 = dup2(pp.x);
                u64 pd1 = dup2(pp.y);
                fma2(acc2[i][0], pd0, V0.x);
                fma2(acc2[i][1], pd0, V0.y);
                fma2(acc2[i][0], pd1, V1.x);
                fma2(acc2[i][1], pd1, V1.y);
            }
        }
    }

    // epilogue: normalize and write bf16x3 splits at [b, t, h*64+d]
#pragma unroll
    for (int i = 0; i < 4; i++) {
        float a[4];
        upk2(a[0], a[1], acc2[i][0]);
        upk2(a[2], a[3], acc2[i][1]);
        float inv = 1.f / l[i];
        size_t off = ((size_t)(b * TT + t0 + r0 + i)) * CC + h * HDIM + c0;
        __nv_bfloat162 h2[2], m2[2], l2[2];
#pragma unroll
        for (int c = 0; c < 4; c++) {
            float v = a[c] * inv;
            __nv_bfloat16 hb = __float2bfloat16(v);
            float r = v - __bfloat162float(hb);
            __nv_bfloat16 mb = __float2bfloat16(r);
            r -= __bfloat162float(mb);
            __nv_bfloat16 lb = __float2bfloat16(r);
            if (c & 1) {
                h2[c >> 1].y = hb; m2[c >> 1].y = mb; l2[c >> 1].y = lb;
            } else {
                h2[c >> 1].x = hb; m2[c >> 1].x = mb; l2[c >> 1].x = lb;
            }
        }
        *(__nv_bfloat162*)&Oh[off]     = h2[0];
        *(__nv_bfloat162*)&Oh[off + 2] = h2[1];
        *(__nv_bfloat162*)&Om[off]     = m2[0];
        *(__nv_bfloat162*)&Om[off + 2] = m2[1];
        *(__nv_bfloat162*)&Ol[off]     = l2[0];
        *(__nv_bfloat162*)&Ol[off + 2] = l2[1];
    }
}

// ----------------------------------------------------------------------------
// Final energy ratio: out = Y * (inE / (||Y row|| + 1e-8)) * energy_normalizer
// ----------------------------------------------------------------------------
__global__ void finalize_kernel(const float* __restrict__ Y,
                                const float* __restrict__ enorm,
                                float* __restrict__ out) {
    int row = blockIdx.x;
    const float* yr = Y + (size_t)row * CC;
    float s = 0.f;
    for (int c = threadIdx.x; c < CC; c += 256) {
        float v = yr[c];
        s += v * v;
    }
    float tot = blockReduceSum256(s);
    __shared__ float ratio;
    if (threadIdx.x == 0)
        ratio = g_inE[row] / (sqrtf(tot) + 1e-8f) * enorm[0];
    __syncthreads();
    for (int c = threadIdx.x; c < CC; c += 256)
        out[(size_t)row * CC + c] = yr[c] * ratio;
}

// ----------------------------------------------------------------------------
// Launch
// ----------------------------------------------------------------------------
extern "C" void kernel_launch(void* const* d_in, const int* in_sizes, int n_in,
                              void* d_out, int out_size) {
    const float* x      = (const float*)d_in[0];
    const float* fd     = (const float*)d_in[1];
    const float* wq     = (const float*)d_in[2];
    const float* bq     = (const float*)d_in[3];
    const float* wk     = (const float*)d_in[4];
    const float* bk     = (const float*)d_in[5];
    const float* wv     = (const float*)d_in[6];
    const float* bv     = (const float*)d_in[7];
    const float* wo     = (const float*)d_in[8];
    const float* bo     = (const float*)d_in[9];
    const float* alpha  = (const float*)d_in[10];
    const float* fas    = (const float*)d_in[11];
    const float* enorm  = (const float*)d_in[12];
    float* out = (float*)d_out;

    float *q, *k, *v, *qr, *qi, *kr, *ki, *vr, *y;
    __nv_bfloat16 *xh, *xm, *xl, *wt;
    cudaGetSymbolAddress((void**)&q,  g_q);
    cudaGetSymbolAddress((void**)&k,  g_k);
    cudaGetSymbolAddress((void**)&v,  g_v);
    cudaGetSymbolAddress((void**)&qr, g_qr);
    cudaGetSymbolAddress((void**)&qi, g_qi);
    cudaGetSymbolAddress((void**)&kr, g_kr);
    cudaGetSymbolAddress((void**)&ki, g_ki);
    cudaGetSymbolAddress((void**)&vr, g_vr);
    cudaGetSymbolAddress((void**)&y,  g_y);
    cudaGetSymbolAddress((void**)&xh, g_xh);
    cudaGetSymbolAddress((void**)&xm, g_xm);
    cudaGetSymbolAddress((void**)&xl, g_xl);
    cudaGetSymbolAddress((void**)&wt, g_wt);
    const size_t WSZ = (size_t)CC * CC;

    // fused: input energies + x split
    energy_split_kernel<<<BT, 256>>>(x, xh, xm, xl);

    // weight transpose+split (all 4 weights, one launch)
    dim3 wg(32, 32, 4), wb(32, 8);
    wsplit4_kernel<<<wg, wb>>>(wq, wk, wv, wo, wt);

    // QKV projections on tensor cores (one batched launch, grid.z = tensor)
    static const int kTcSmem = 2 * 3 * 2 * 128 * ASTRIDE * (int)sizeof(__nv_bfloat16);
    cudaFuncSetAttribute(tc_gemm3_kernel,
                         cudaFuncAttributeMaxDynamicSharedMemorySize, kTcSmem);
    cudaFuncSetAttribute(tc_gemm_kernel,
                         cudaFuncAttributeMaxDynamicSharedMemorySize, kTcSmem);
    dim3 gg3(CC / 128, BT / 128, 3);
    tc_gemm3_kernel<<<gg3, 256, kTcSmem>>>(xh, xm, xl, wt, bq, bk, bv, q, k, v);

    // FFT + spectral filter, all three tensors in one launch
    static const int kFftSmem = TT * FSTR * (int)sizeof(float2);  // 147456
    cudaFuncSetAttribute(fft_filter_kernel,
                         cudaFuncAttributeMaxDynamicSharedMemorySize, kFftSmem);
    dim3 gf(HDIM / 8, HH * 3, BB);
    fft_filter_kernel<<<gf, 256, kFftSmem>>>(q, k, v, qr, qi, kr, ki, vr,
                                             fd, alpha, fas);

    // attention (writes O splits directly into xh/xm/xl)
    static const int kAttnSmem = (4 * 64 * 132 + 128 * 68) * (int)sizeof(float);
    cudaFuncSetAttribute(attn_kernel, cudaFuncAttributeMaxDynamicSharedMemorySize,
                         kAttnSmem);
    dim3 ga(TT / 128, HH, BB);
    attn_kernel<<<ga, 512, kAttnSmem>>>(qr, qi, kr, ki, vr, xh, xm, xl);

    // output projection
    dim3 gg(CC / 128, BT / 128);
    tc_gemm_kernel<<<gg, 256, kTcSmem>>>(xh, xm, xl,
                                         wt + 9 * WSZ, wt + 10 * WSZ, wt + 11 * WSZ,
                                         bo, y);

    // energy-ratio epilogue
    finalize_kernel<<<BT, 256>>>(y, enorm, out);
}

// round 13
// speedup vs baseline: 1.3816x; 1.0291x over previous
#include <cuda_runtime.h>
#include <cuda_bf16.h>
#include <math.h>
#include <cstdint>

// Problem constants
#define BB 2
#define TT 2048
#define CC 1024
#define HH 16
#define HDIM 64
#define BT (BB * TT)      // 4096 rows
#define LOG2T 11

typedef unsigned long long u64;
typedef unsigned int u32;

// ---------------------------------------------------------------------------
// Packed f32x2 helpers (Blackwell sm_103a)
// ---------------------------------------------------------------------------
__device__ __forceinline__ u64 pk2(float lo, float hi) {
    u64 r;
    asm("mov.b64 %0, {%1, %2};" : "=l"(r) : "f"(lo), "f"(hi));
    return r;
}
__device__ __forceinline__ u64 dup2(float v) { return pk2(v, v); }
__device__ __forceinline__ void upk2(float& lo, float& hi, u64 v) {
    asm("mov.b64 {%0, %1}, %2;" : "=f"(lo), "=f"(hi) : "l"(v));
}
__device__ __forceinline__ void fma2(u64& d, u64 a, u64 b) {
    asm("fma.rn.f32x2 %0, %1, %2, %0;" : "+l"(d) : "l"(a), "l"(b));
}
__device__ __forceinline__ void mul2(u64& d, u64 a, u64 b) {
    asm("mul.rn.f32x2 %0, %1, %2;" : "=l"(d) : "l"(a), "l"(b));
}

// ---------------------------------------------------------------------------
// mma.sync / ldmatrix / cp.async helpers (compute_103-legal PTX)
// ---------------------------------------------------------------------------
__device__ __forceinline__ u32 smem_u32(const void* p) {
    u32 a;
    asm("{ .reg .u64 t; cvta.to.shared.u64 t, %1; cvt.u32.u64 %0, t; }"
        : "=r"(a) : "l"(p));
    return a;
}
__device__ __forceinline__ void cpasync16(u32 smem_dst, const void* gptr) {
    asm volatile("cp.async.ca.shared.global [%0], [%1], 16;"
                 :: "r"(smem_dst), "l"(gptr));
}
__device__ __forceinline__ void cpcommit() {
    asm volatile("cp.async.commit_group;");
}
__device__ __forceinline__ void cpwait0() {
    asm volatile("cp.async.wait_group 0;");
}
__device__ __forceinline__ void ldsm_x4(u32& r0, u32& r1, u32& r2, u32& r3,
                                        u32 addr) {
    asm volatile("ldmatrix.sync.aligned.m8n8.x4.shared.b16 {%0,%1,%2,%3}, [%4];"
                 : "=r"(r0), "=r"(r1), "=r"(r2), "=r"(r3) : "r"(addr));
}
__device__ __forceinline__ void mma_bf16(float* c, const u32* a, const u32* b) {
    asm volatile(
        "mma.sync.aligned.m16n8k16.row.col.f32.bf16.bf16.f32 "
        "{%0,%1,%2,%3}, {%4,%5,%6,%7}, {%8,%9}, {%0,%1,%2,%3};"
        : "+f"(c[0]), "+f"(c[1]), "+f"(c[2]), "+f"(c[3])
        : "r"(a[0]), "r"(a[1]), "r"(a[2]), "r"(a[3]), "r"(b[0]), "r"(b[1]));
}

// ----------------------------------------------------------------------------
// Device scratch (static; no allocations allowed)
// ----------------------------------------------------------------------------
static __device__ float g_q[BT * CC];
static __device__ float g_k[BT * CC];
static __device__ float g_v[BT * CC];
static __device__ float g_qr[BT * CC];
static __device__ float g_qi[BT * CC];
static __device__ float g_kr[BT * CC];
static __device__ float g_ki[BT * CC];
static __device__ float g_vr[BT * CC];
static __device__ float g_y[BT * CC];
static __device__ float g_inE[BT];
// bf16x3 splits
static __device__ __nv_bfloat16 g_xh[BT * CC];
static __device__ __nv_bfloat16 g_xm[BT * CC];
static __device__ __nv_bfloat16 g_xl[BT * CC];
static __device__ __nv_bfloat16 g_wt[12 * CC * CC];   // 4 weights x {h,m,l}, [N][K]

// ----------------------------------------------------------------------------
// Reductions
// ----------------------------------------------------------------------------
__device__ __forceinline__ float blockReduceSum256(float v) {
    __shared__ float red[8];
    int lane = threadIdx.x & 31;
    int w = threadIdx.x >> 5;
#pragma unroll
    for (int o = 16; o >= 1; o >>= 1)
        v += __shfl_xor_sync(0xffffffffu, v, o);
    if (lane == 0) red[w] = v;
    __syncthreads();
    if (w == 0) {
        v = (lane < 8) ? red[lane] : 0.f;
#pragma unroll
        for (int o = 4; o >= 1; o >>= 1)
            v += __shfl_xor_sync(0xffffffffu, v, o);
    }
    return v;  // valid in thread 0
}

// ----------------------------------------------------------------------------
// Fused: input energy ||x[row,:]|| + bf16x3 split of x (one pass over x)
// ----------------------------------------------------------------------------
__global__ void energy_split_kernel(const float* __restrict__ x,
                                    __nv_bfloat16* __restrict__ H,
                                    __nv_bfloat16* __restrict__ M,
                                    __nv_bfloat16* __restrict__ L) {
    int row = blockIdx.x;
    const float* xr = x + (size_t)row * CC;
    float s = 0.f;
    for (int c = threadIdx.x; c < CC; c += 256) {
        float v = xr[c];
        s += v * v;
        __nv_bfloat16 h = __float2bfloat16(v);
        float r = v - __bfloat162float(h);
        __nv_bfloat16 m = __float2bfloat16(r);
        r -= __bfloat162float(m);
        size_t o = (size_t)row * CC + c;
        H[o] = h; M[o] = m; L[o] = __float2bfloat16(r);
    }
    float tot = blockReduceSum256(s);
    if (threadIdx.x == 0) g_inE[row] = sqrtf(tot);
}

// ----------------------------------------------------------------------------
// Transpose + split W[k][n] -> WT{h,m,l}[n][k] bf16; grid.z selects weight
// ----------------------------------------------------------------------------
__global__ void wsplit4_kernel(const float* __restrict__ W0,
                               const float* __restrict__ W1,
                               const float* __restrict__ W2,
                               const float* __restrict__ W3,
                               __nv_bfloat16* __restrict__ WT) {
    __shared__ float t[32][33];
    const int wsel = blockIdx.z;
    const float* W = (wsel == 0) ? W0 : (wsel == 1) ? W1 : (wsel == 2) ? W2 : W3;
    __nv_bfloat16* H = WT + (size_t)(3 * wsel + 0) * CC * CC;
    __nv_bfloat16* M = WT + (size_t)(3 * wsel + 1) * CC * CC;
    __nv_bfloat16* L = WT + (size_t)(3 * wsel + 2) * CC * CC;
    int n0 = blockIdx.x << 5, k0 = blockIdx.y << 5;
    int tx = threadIdx.x, ty = threadIdx.y;
#pragma unroll
    for (int i = 0; i < 4; i++)
        t[ty + i * 8][tx] = W[(size_t)(k0 + ty + i * 8) * CC + n0 + tx];
    __syncthreads();
#pragma unroll
    for (int i = 0; i < 4; i++) {
        int n = n0 + ty + i * 8;
        float x = t[tx][ty + i * 8];
        __nv_bfloat16 h = __float2bfloat16(x);
        float r = x - __bfloat162float(h);
        __nv_bfloat16 m = __float2bfloat16(r);
        r -= __bfloat162float(m);
        size_t o = (size_t)n * CC + k0 + tx;
        H[o] = h; M[o] = m; L[o] = __float2bfloat16(r);
    }
}

// ----------------------------------------------------------------------------
// Tensor-core GEMM body via mma.sync bf16x3 (emulated fp32):
// Co[4096,1024] = A @ B^T + bias. Block 128x128, BK=32, 8 warps.
// ----------------------------------------------------------------------------
#define ASTRIDE 40
#define SPLITB (2 * 128 * ASTRIDE * 2)   // bytes per split (both buffers)
#define BUFB   (128 * ASTRIDE * 2)       // bytes per buffer

__device__ __forceinline__ void tc_gemm_body(
    const __nv_bfloat16* __restrict__ Ah, const __nv_bfloat16* __restrict__ Am,
    const __nv_bfloat16* __restrict__ Al, const __nv_bfloat16* __restrict__ Bh,
    const __nv_bfloat16* __restrict__ Bm, const __nv_bfloat16* __restrict__ Bl,
    const float* __restrict__ bias, float* __restrict__ Co,
    __nv_bfloat16* smb, int m0, int n0) {
    __nv_bfloat16* sB = smb + 3 * 2 * 128 * ASTRIDE;
    const u32 sAu = smem_u32(smb);
    const u32 sBu = smem_u32(sB);

    const int tid = threadIdx.x;
    const int wid = tid >> 5, lane = tid & 31;
    const int wm = wid >> 2, wn = wid & 3;        // warps 2 (m) x 4 (n)

    const __nv_bfloat16* Asrc[3] = {Ah, Am, Al};
    const __nv_bfloat16* Bsrc[3] = {Bh, Bm, Bl};

    float acc[4][4][4];
#pragma unroll
    for (int i = 0; i < 4; i++)
#pragma unroll
        for (int j = 0; j < 4; j++)
#pragma unroll
            for (int r = 0; r < 4; r++) acc[i][j][r] = 0.f;

    const int ldr0 = tid >> 2, ldk0 = (tid & 3) << 3;
    const int ldr1 = (tid + 256) >> 2, ldk1 = ((tid + 256) & 3) << 3;

    const u32 aRowB = (u32)(((lane & 7) + ((lane >> 3) & 1) * 8) * (ASTRIDE * 2));
    const u32 aKB   = (u32)(((lane >> 4) & 1) * 16);
    const u32 bRowB = (u32)(((lane & 7) + ((lane >> 4) & 1) * 8) * (ASTRIDE * 2));
    const u32 bKB   = (u32)(((lane >> 3) & 1) * 16);

#define ISSUE_CHUNK(c, buf)                                                     \
    do {                                                                        \
        _Pragma("unroll")                                                       \
        for (int t_ = 0; t_ < 3; t_++) {                                        \
            const __nv_bfloat16* ga = Asrc[t_] + (size_t)(m0 + ldr0) * CC +     \
                                      (c) * 32 + ldk0;                          \
            const __nv_bfloat16* ga1 = Asrc[t_] + (size_t)(m0 + ldr1) * CC +    \
                                       (c) * 32 + ldk1;                         \
            const __nv_bfloat16* gb = Bsrc[t_] + (size_t)(n0 + ldr0) * CC +     \
                                      (c) * 32 + ldk0;                          \
            const __nv_bfloat16* gb1 = Bsrc[t_] + (size_t)(n0 + ldr1) * CC +    \
                                       (c) * 32 + ldk1;                         \
            u32 d0 = (u32)(t_ * SPLITB + (buf) * BUFB +                         \
                           (ldr0 * ASTRIDE + ldk0) * 2);                        \
            u32 d1 = (u32)(t_ * SPLITB + (buf) * BUFB +                         \
                           (ldr1 * ASTRIDE + ldk1) * 2);                        \
            cpasync16(sAu + d0, ga);                                            \
            cpasync16(sAu + d1, ga1);                                           \
            cpasync16(sBu + d0, gb);                                            \
            cpasync16(sBu + d1, gb1);                                           \
        }                                                                       \
        cpcommit();                                                             \
    } while (0)

    ISSUE_CHUNK(0, 0);

    for (int c = 0; c < 32; c++) {
        const int buf = c & 1;
        cpwait0();
        __syncthreads();
        if (c + 1 < 32) ISSUE_CHUNK(c + 1, buf ^ 1);

#pragma unroll
        for (int ks = 0; ks < 2; ks++) {
            u32 af[3][4][4];
#pragma unroll
            for (int t = 0; t < 3; t++)
#pragma unroll
                for (int mi = 0; mi < 4; mi++) {
                    u32 addr = sAu + (u32)(t * SPLITB + buf * BUFB) +
                               (u32)((wm * 64 + mi * 16) * (ASTRIDE * 2)) +
                               aRowB + (u32)(ks * 32) + aKB;
                    ldsm_x4(af[t][mi][0], af[t][mi][1], af[t][mi][2],
                            af[t][mi][3], addr);
                }
#pragma unroll
            for (int bt = 0; bt < 3; bt++) {
                u32 bfr[2][4];
#pragma unroll
                for (int np = 0; np < 2; np++) {
                    u32 addr = sBu + (u32)(bt * SPLITB + buf * BUFB) +
                               (u32)((wn * 32 + np * 16) * (ASTRIDE * 2)) +
                               bRowB + (u32)(ks * 32) + bKB;
                    ldsm_x4(bfr[np][0], bfr[np][1], bfr[np][2], bfr[np][3],
                            addr);
                }
                const int nA = (bt == 0) ? 3 : (bt == 1) ? 2 : 1;
#pragma unroll
                for (int ia = 0; ia < 3; ia++) {
                    if (ia >= nA) break;
#pragma unroll
                    for (int mi = 0; mi < 4; mi++)
#pragma unroll
                        for (int ni = 0; ni < 4; ni++)
                            mma_bf16(acc[mi][ni], af[ia][mi],
                                     &bfr[ni >> 1][(ni & 1) * 2]);
                }
            }
        }
        __syncthreads();
    }

    const int grp = lane >> 2, qd = lane & 3;
#pragma unroll
    for (int mi = 0; mi < 4; mi++) {
#pragma unroll
        for (int ni = 0; ni < 4; ni++) {
            int row = m0 + wm * 64 + mi * 16 + grp;
            int col = n0 + wn * 32 + ni * 8 + qd * 2;
            float b0 = bias[col], b1 = bias[col + 1];
            float2 o0 = make_float2(acc[mi][ni][0] + b0, acc[mi][ni][1] + b1);
            float2 o1 = make_float2(acc[mi][ni][2] + b0, acc[mi][ni][3] + b1);
            *(float2*)&Co[(size_t)row * CC + col] = o0;
            *(float2*)&Co[(size_t)(row + 8) * CC + col] = o1;
        }
    }
}

// single-output GEMM (wo projection)
__global__ void __launch_bounds__(256, 1)
tc_gemm_kernel(const __nv_bfloat16* __restrict__ Ah,
               const __nv_bfloat16* __restrict__ Am,
               const __nv_bfloat16* __restrict__ Al,
               const __nv_bfloat16* __restrict__ Bh,
               const __nv_bfloat16* __restrict__ Bm,
               const __nv_bfloat16* __restrict__ Bl,
               const float* __restrict__ bias, float* __restrict__ Co) {
    extern __shared__ __align__(16) __nv_bfloat16 smb[];
    tc_gemm_body(Ah, Am, Al, Bh, Bm, Bl, bias, Co, smb,
                 blockIdx.y << 7, blockIdx.x << 7);
}

// batched QKV GEMM: grid.z = 0/1/2 -> (wq->q), (wk->k), (wv->v)
__global__ void __launch_bounds__(256, 1)
tc_gemm3_kernel(const __nv_bfloat16* __restrict__ Ah,
                const __nv_bfloat16* __restrict__ Am,
                const __nv_bfloat16* __restrict__ Al,
                const __nv_bfloat16* __restrict__ WT,
                const float* __restrict__ bq, const float* __restrict__ bk,
                const float* __restrict__ bv,
                float* __restrict__ Q, float* __restrict__ K,
                float* __restrict__ V) {
    extern __shared__ __align__(16) __nv_bfloat16 smb[];
    const int z = blockIdx.z;
    const __nv_bfloat16* B = WT + (size_t)(3 * z) * CC * CC;
    const float* bias = (z == 0) ? bq : (z == 1) ? bk : bv;
    float* Co = (z == 0) ? Q : (z == 1) ? K : V;
    tc_gemm_body(Ah, Am, Al, B, B + (size_t)CC * CC, B + (size_t)2 * CC * CC,
                 bias, Co, smb, blockIdx.y << 7, blockIdx.x << 7);
}

// ----------------------------------------------------------------------------
// Batched FFT with real-pair packing: one block per (tensor, b, h, 16-dim
// group). Two real columns packed as one complex sequence -> half the
// butterfly work; unpacked in the filter epilogue via
//   X_k = (Z_k + conj(Z_{N-k}))/2,  Y_k = (Z_k - conj(Z_{N-k}))/(2i).
// ----------------------------------------------------------------------------
#define FSTR 9
__global__ void __launch_bounds__(256, 1)
fft_filter_kernel(const float* __restrict__ inQ, const float* __restrict__ inK,
                  const float* __restrict__ inV,
                  float* __restrict__ oQr, float* __restrict__ oQi,
                  float* __restrict__ oKr, float* __restrict__ oKi,
                  float* __restrict__ oVr,
                  const float* __restrict__ fd,
                  const float* __restrict__ alpha,
                  const float* __restrict__ fas) {
    extern __shared__ __align__(16) float2 sh[];   // sh[t*FSTR + c], c<8
    const int dg = blockIdx.x;          // 16-dim group 0..3
    const int which = blockIdx.y >> 4;  // 0=Q 1=K 2=V
    const int h = blockIdx.y & 15;
    const int b = blockIdx.z;
    const float* in = (which == 0) ? inQ : (which == 1) ? inK : inV;
    float* outRe = (which == 0) ? oQr : (which == 1) ? oKr : oVr;
    float* outIm = (which == 0) ? oQi : (which == 1) ? oKi : (float*)0;

    const int col0 = h * HDIM + dg * 16;
    const float* src = in + (size_t)b * TT * CC + col0;
    const int tid = threadIdx.x;

    // load: complex column c packs real cols (2c, 2c+1); float2 loads are the
    // packed pair directly.
#pragma unroll
    for (int i = 0; i < 32; i++) {
        int e = tid + i * 256;
        int t = e >> 2, pr = e & 3;     // pr: 2 complex columns per float4
        float4 v = *(const float4*)&src[(size_t)t * CC + pr * 4];
        unsigned r = __brev((unsigned)t) >> (32 - LOG2T);
        sh[r * FSTR + pr * 2]     = make_float2(v.x, v.y);
        sh[r * FSTR + pr * 2 + 1] = make_float2(v.z, v.w);
    }
    __syncthreads();

    for (int st = 1; st <= LOG2T; st++) {
        const int half = 1 << (st - 1);
        const float wstep = -6.283185307179586f / (float)(half * 2);
#pragma unroll
        for (int w = 0; w < 4; w++) {
            int idx = tid + w * 256;
            int pos = idx & (half - 1);
            int grp = idx >> (st - 1);
            int i0 = (grp << st) + pos;
            int i1 = i0 + half;
            float sn, cs;
            __sincosf(wstep * (float)pos, &sn, &cs);
            float2* p0 = &sh[i0 * FSTR];
            float2* p1 = &sh[i1 * FSTR];
#pragma unroll
            for (int c = 0; c < 8; c++) {
                float2 u = p0[c], v = p1[c];
                float tr = cs * v.x - sn * v.y;
                float ti = cs * v.y + sn * v.x;
                p0[c] = make_float2(u.x + tr, u.y + ti);
                p1[c] = make_float2(u.x - tr, u.y - ti);
            }
        }
        __syncthreads();
    }

    // unpack + spectral filter + store (phase shared across all 16 columns)
    const float aal = alpha[0] + fas[0] * (fd[0] - 1.5f);
    const size_t obase = ((size_t)(b * HH + h)) * TT * HDIM + dg * 16;
#pragma unroll
    for (int i = 0; i < 8; i++) {
        int t = tid + i * 256;
        int tm = (TT - t) & (TT - 1);
        float fr = (float)(t < TT / 2 ? t : t - TT) * (1.0f / (float)TT);
        float phase = aal * atanf(logf(fabsf(fr) + 1e-10f));
        float sp, cp;
        sincosf(phase, &sp, &cp);
        const float2* pz = &sh[t * FSTR];
        const float2* pw = &sh[tm * FSTR];
        float re[16], im[16];
#pragma unroll
        for (int c = 0; c < 8; c++) {
            float2 Z = pz[c], W = pw[c];
            float Xr = 0.5f * (Z.x + W.x);
            float Xi = 0.5f * (Z.y - W.y);
            float Yr = 0.5f * (Z.y + W.y);
            float Yi = 0.5f * (W.x - Z.x);
            re[2 * c]     = Xr * cp - Xi * sp;
            im[2 * c]     = Xr * sp + Xi * cp;
            re[2 * c + 1] = Yr * cp - Yi * sp;
            im[2 * c + 1] = Yr * sp + Yi * cp;
        }
        size_t o = obase + (size_t)t * HDIM;
#pragma unroll
        for (int q4 = 0; q4 < 4; q4++)
            *(float4*)&outRe[o + q4 * 4] =
                make_float4(re[q4 * 4], re[q4 * 4 + 1], re[q4 * 4 + 2],
                            re[q4 * 4 + 3]);
        if (outIm) {
#pragma unroll
            for (int q4 = 0; q4 < 4; q4++)
                *(float4*)&outIm[o + q4 * 4] =
                    make_float4(im[q4 * 4], im[q4 * 4 + 1], im[q4 * 4 + 2],
                                im[q4 * 4 + 3]);
        }
    }
}

// ----------------------------------------------------------------------------
// Flash attention per (b,h). 128x128 tiles, 512 threads, column-packed f32x2.
// (Measured-best configuration.) Epilogue writes the bf16x3 split of O.
// ----------------------------------------------------------------------------
__global__ void __launch_bounds__(512, 1)
attn_kernel(const float* __restrict__ Qr, const float* __restrict__ Qi,
            const float* __restrict__ Kr, const float* __restrict__ Ki,
            const float* __restrict__ Vr,
            __nv_bfloat16* __restrict__ Oh, __nv_bfloat16* __restrict__ Om,
            __nv_bfloat16* __restrict__ Ol) {
    extern __shared__ __align__(16) float smbuf[];
    float* sQr = smbuf;                 // [d=64][132]
    float* sQi = sQr + 64 * 132;
    float* sKr = sQi + 64 * 132;        // [d=64][132]
    float* sKi = sKr + 64 * 132;        // holds -Ki
    float* sV  = sKi + 64 * 132;        // [s=128][68]
    float* sP  = sKr;                   // [t=128][132], aliases Kr+Ki

    const int tid = threadIdx.x;
    const int ty = tid >> 4, tx = tid & 15;   // ty 0..31, tx 0..15
    const int t0 = blockIdx.x << 7;
    const int h = blockIdx.y, b = blockIdx.z;
    const size_t base = ((size_t)(b * HH + h)) * TT * HDIM;
    const int r0 = ty << 2;                   // 4 rows per thread
    const int c0 = tx << 2;                   // 4+4 cols per thread

    // load Q tile (transposed into [d][t])
#pragma unroll
    for (int i = 0; i < 4; i++) {
        int e = tid + i * 512;          // 0..2047
        int r = e >> 4, c4 = (e & 15) << 2;
        size_t g = base + (size_t)(t0 + r) * HDIM + c4;
        float4 qr = *(const float4*)&Qr[g];
        float4 qi = *(const float4*)&Qi[g];
        sQr[(c4 + 0) * 132 + r] = qr.x;
        sQr[(c4 + 1) * 132 + r] = qr.y;
        sQr[(c4 + 2) * 132 + r] = qr.z;
        sQr[(c4 + 3) * 132 + r] = qr.w;
        sQi[(c4 + 0) * 132 + r] = qi.x;
        sQi[(c4 + 1) * 132 + r] = qi.y;
        sQi[(c4 + 2) * 132 + r] = qi.z;
        sQi[(c4 + 3) * 132 + r] = qi.w;
    }

    float m[4], l[4];
    u64 acc2[4][2];                     // [row][col-pair]
#pragma unroll
    for (int i = 0; i < 4; i++) { m[i] = -INFINITY; l[i] = 0.f; }
#pragma unroll
    for (int i = 0; i < 4; i++) { acc2[i][0] = 0ull; acc2[i][1] = 0ull; }

    for (int s0 = 0; s0 < TT; s0 += 128) {
        __syncthreads();  // P/V consumed (and Q visible on first iter)
#pragma unroll
        for (int i = 0; i < 4; i++) {
            int e = tid + i * 512;
            int r = e >> 4, c4 = (e & 15) << 2;
            size_t g = base + (size_t)(s0 + r) * HDIM + c4;
            float4 kr = *(const float4*)&Kr[g];
            float4 ki = *(const float4*)&Ki[g];
            sKr[(c4 + 0) * 132 + r] = kr.x;
            sKr[(c4 + 1) * 132 + r] = kr.y;
            sKr[(c4 + 2) * 132 + r] = kr.z;
            sKr[(c4 + 3) * 132 + r] = kr.w;
            sKi[(c4 + 0) * 132 + r] = -ki.x;
            sKi[(c4 + 1) * 132 + r] = -ki.y;
            sKi[(c4 + 2) * 132 + r] = -ki.z;
            sKi[(c4 + 3) * 132 + r] = -ki.w;
            *(float4*)&sV[r * 68 + c4] = *(const float4*)&Vr[g];
        }
        __syncthreads();

        // ---- S tile: [4 rows][4 col-pairs]; K pairs direct from smem ----
        u64 S2[4][4];
#pragma unroll
        for (int i = 0; i < 4; i++)
#pragma unroll
            for (int j = 0; j < 4; j++) S2[i][j] = 0ull;

#pragma unroll 8
        for (int d = 0; d < 64; d++) {
            float4 q4 = *(const float4*)&sQr[d * 132 + r0];
            float4 p4 = *(const float4*)&sQi[d * 132 + r0];
            ulonglong2 K0 = *(const ulonglong2*)&sKr[d * 132 + c0];
            ulonglong2 K1 = *(const ulonglong2*)&sKr[d * 132 + 64 + c0];
            ulonglong2 J0 = *(const ulonglong2*)&sKi[d * 132 + c0];
            ulonglong2 J1 = *(const ulonglong2*)&sKi[d * 132 + 64 + c0];
            u64 kp[4] = {K0.x, K0.y, K1.x, K1.y};
            u64 jp[4] = {J0.x, J0.y, J1.x, J1.y};
            float qv[4] = {q4.x, q4.y, q4.z, q4.w};
            float pv_[4] = {p4.x, p4.y, p4.z, p4.w};
#pragma unroll
            for (int i = 0; i < 4; i++) {
                u64 qd = dup2(qv[i]);
                u64 pd = dup2(pv_[i]);
#pragma unroll
                for (int cp = 0; cp < 4; cp++) {
                    fma2(S2[i][cp], qd, kp[cp]);
                    fma2(S2[i][cp], pd, jp[cp]);
                }
            }
        }
        __syncthreads();  // all K reads done before P overwrites that smem

        float S[4][8];
#pragma unroll
        for (int i = 0; i < 4; i++)
#pragma unroll
            for (int cp = 0; cp < 4; cp++)
                upk2(S[i][2 * cp], S[i][2 * cp + 1], S2[i][cp]);

        // ---- online softmax; write P into aliased smem ----
        float corr[4];
#pragma unroll
        for (int i = 0; i < 4; i++) {
            float mx = S[i][0];
#pragma unroll
            for (int j = 1; j < 8; j++) mx = fmaxf(mx, S[i][j]);
            mx *= 0.125f;
#pragma unroll
            for (int o = 8; o >= 1; o >>= 1)
                mx = fmaxf(mx, __shfl_xor_sync(0xffffffffu, mx, o));
            float mn = fmaxf(m[i], mx);
            corr[i] = __expf(m[i] - mn);
            float ps = 0.f;
            float pv[8];
#pragma unroll
            for (int j = 0; j < 8; j++) {
                float p = __expf(S[i][j] * 0.125f - mn);
                pv[j] = p;
                ps += p;
            }
            *(float4*)&sP[(r0 + i) * 132 + c0] =
                make_float4(pv[0], pv[1], pv[2], pv[3]);
            *(float4*)&sP[(r0 + i) * 132 + 64 + c0] =
                make_float4(pv[4], pv[5], pv[6], pv[7]);
#pragma unroll
            for (int o = 8; o >= 1; o >>= 1)
                ps += __shfl_xor_sync(0xffffffffu, ps, o);
            l[i] = l[i] * corr[i] + ps;
            m[i] = mn;
        }
#pragma unroll
        for (int i = 0; i < 4; i++) {
            u64 cd = dup2(corr[i]);
            u64 t0r, t1r;
            mul2(t0r, acc2[i][0], cd);
            mul2(t1r, acc2[i][1], cd);
            acc2[i][0] = t0r;
            acc2[i][1] = t1r;
        }
        __syncthreads();

        // ---- O += P @ V: V pairs direct from smem, P scalars dup'd ----
#pragma unroll 8
        for (int s = 0; s < 128; s += 2) {
            ulonglong2 V0 = *(const ulonglong2*)&sV[s * 68 + c0];
            ulonglong2 V1 = *(const ulonglong2*)&sV[(s + 1) * 68 + c0];
#pragma unroll
            for (int i = 0; i < 4; i++) {
                float2 pp = *(const float2*)&sP[(r0 + i) * 132 + s];
                u64 pd0 = dup2(pp.x);
                u64 pd1 = dup2(pp.y);
                fma2(acc2[i][0], pd0, V0.x);
                fma2(acc2[i][1], pd0, V0.y);
                fma2(acc2[i][0], pd1, V1.x);
                fma2(acc2[i][1], pd1, V1.y);
            }
        }
    }

    // epilogue: normalize and write bf16x3 splits at [b, t, h*64+d]
#pragma unroll
    for (int i = 0; i < 4; i++) {
        float a[4];
        upk2(a[0], a[1], acc2[i][0]);
        upk2(a[2], a[3], acc2[i][1]);
        float inv = 1.f / l[i];
        size_t off = ((size_t)(b * TT + t0 + r0 + i)) * CC + h * HDIM + c0;
        __nv_bfloat162 h2[2], m2[2], l2[2];
#pragma unroll
        for (int c = 0; c < 4; c++) {
            float v = a[c] * inv;
            __nv_bfloat16 hb = __float2bfloat16(v);
            float r = v - __bfloat162float(hb);
            __nv_bfloat16 mb = __float2bfloat16(r);
            r -= __bfloat162float(mb);
            __nv_bfloat16 lb = __float2bfloat16(r);
            if (c & 1) {
                h2[c >> 1].y = hb; m2[c >> 1].y = mb; l2[c >> 1].y = lb;
            } else {
                h2[c >> 1].x = hb; m2[c >> 1].x = mb; l2[c >> 1].x = lb;
            }
        }
        *(__nv_bfloat162*)&Oh[off]     = h2[0];
        *(__nv_bfloat162*)&Oh[off + 2] = h2[1];
        *(__nv_bfloat162*)&Om[off]     = m2[0];
        *(__nv_bfloat162*)&Om[off + 2] = m2[1];
        *(__nv_bfloat162*)&Ol[off]     = l2[0];
        *(__nv_bfloat162*)&Ol[off + 2] = l2[1];
    }
}

// ----------------------------------------------------------------------------
// Final energy ratio: out = Y * (inE / (||Y row|| + 1e-8)) * energy_normalizer
// ----------------------------------------------------------------------------
__global__ void finalize_kernel(const float* __restrict__ Y,
                                const float* __restrict__ enorm,
                                float* __restrict__ out) {
    int row = blockIdx.x;
    const float* yr = Y + (size_t)row * CC;
    float s = 0.f;
    for (int c = threadIdx.x; c < CC; c += 256) {
        float v = yr[c];
        s += v * v;
    }
    float tot = blockReduceSum256(s);
    __shared__ float ratio;
    if (threadIdx.x == 0)
        ratio = g_inE[row] / (sqrtf(tot) + 1e-8f) * enorm[0];
    __syncthreads();
    for (int c = threadIdx.x; c < CC; c += 256)
        out[(size_t)row * CC + c] = yr[c] * ratio;
}

// ----------------------------------------------------------------------------
// Launch
// ----------------------------------------------------------------------------
extern "C" void kernel_launch(void* const* d_in, const int* in_sizes, int n_in,
                              void* d_out, int out_size) {
    const float* x      = (const float*)d_in[0];
    const float* fd     = (const float*)d_in[1];
    const float* wq     = (const float*)d_in[2];
    const float* bq     = (const float*)d_in[3];
    const float* wk     = (const float*)d_in[4];
    const float* bk     = (const float*)d_in[5];
    const float* wv     = (const float*)d_in[6];
    const float* bv     = (const float*)d_in[7];
    const float* wo     = (const float*)d_in[8];
    const float* bo     = (const float*)d_in[9];
    const float* alpha  = (const float*)d_in[10];
    const float* fas    = (const float*)d_in[11];
    const float* enorm  = (const float*)d_in[12];
    float* out = (float*)d_out;

    float *q, *k, *v, *qr, *qi, *kr, *ki, *vr, *y;
    __nv_bfloat16 *xh, *xm, *xl, *wt;
    cudaGetSymbolAddress((void**)&q,  g_q);
    cudaGetSymbolAddress((void**)&k,  g_k);
    cudaGetSymbolAddress((void**)&v,  g_v);
    cudaGetSymbolAddress((void**)&qr, g_qr);
    cudaGetSymbolAddress((void**)&qi, g_qi);
    cudaGetSymbolAddress((void**)&kr, g_kr);
    cudaGetSymbolAddress((void**)&ki, g_ki);
    cudaGetSymbolAddress((void**)&vr, g_vr);
    cudaGetSymbolAddress((void**)&y,  g_y);
    cudaGetSymbolAddress((void**)&xh, g_xh);
    cudaGetSymbolAddress((void**)&xm, g_xm);
    cudaGetSymbolAddress((void**)&xl, g_xl);
    cudaGetSymbolAddress((void**)&wt, g_wt);
    const size_t WSZ = (size_t)CC * CC;

    // fused: input energies + x split
    energy_split_kernel<<<BT, 256>>>(x, xh, xm, xl);

    // weight transpose+split (all 4 weights, one launch)
    dim3 wg(32, 32, 4), wb(32, 8);
    wsplit4_kernel<<<wg, wb>>>(wq, wk, wv, wo, wt);

    // QKV projections on tensor cores (one batched launch, grid.z = tensor)
    static const int kTcSmem = 2 * 3 * 2 * 128 * ASTRIDE * (int)sizeof(__nv_bfloat16);
    cudaFuncSetAttribute(tc_gemm3_kernel,
                         cudaFuncAttributeMaxDynamicSharedMemorySize, kTcSmem);
    cudaFuncSetAttribute(tc_gemm_kernel,
                         cudaFuncAttributeMaxDynamicSharedMemorySize, kTcSmem);
    dim3 gg3(CC / 128, BT / 128, 3);
    tc_gemm3_kernel<<<gg3, 256, kTcSmem>>>(xh, xm, xl, wt, bq, bk, bv, q, k, v);

    // FFT + spectral filter (real-pair packed: 16 dims per block)
    static const int kFftSmem = TT * FSTR * (int)sizeof(float2);  // 147456
    cudaFuncSetAttribute(fft_filter_kernel,
                         cudaFuncAttributeMaxDynamicSharedMemorySize, kFftSmem);
    dim3 gf(HDIM / 16, HH * 3, BB);
    fft_filter_kernel<<<gf, 256, kFftSmem>>>(q, k, v, qr, qi, kr, ki, vr,
                                             fd, alpha, fas);

    // attention (writes O splits directly into xh/xm/xl)
    static const int kAttnSmem = (4 * 64 * 132 + 128 * 68) * (int)sizeof(float);
    cudaFuncSetAttribute(attn_kernel, cudaFuncAttributeMaxDynamicSharedMemorySize,
                         kAttnSmem);
    dim3 ga(TT / 128, HH, BB);
    attn_kernel<<<ga, 512, kAttnSmem>>>(qr, qi, kr, ki, vr, xh, xm, xl);

    // output projection
    dim3 gg(CC / 128, BT / 128);
    tc_gemm_kernel<<<gg, 256, kTcSmem>>>(xh, xm, xl,
                                         wt + 9 * WSZ, wt + 10 * WSZ, wt + 11 * WSZ,
                                         bo, y);

    // energy-ratio epilogue
    finalize_kernel<<<BT, 256>>>(y, enorm, out);
}

// round 14
// speedup vs baseline: 1.7117x; 1.2389x over previous
#include <cuda_runtime.h>
#include <cuda_bf16.h>
#include <math.h>
#include <cstdint>

// Problem constants
#define BB 2
#define TT 2048
#define CC 1024
#define HH 16
#define HDIM 64
#define BT (BB * TT)      // 4096 rows
#define LOG2T 11

typedef unsigned long long u64;
typedef unsigned int u32;

// ---------------------------------------------------------------------------
// Packed f32x2 helpers (Blackwell sm_103a)
// ---------------------------------------------------------------------------
__device__ __forceinline__ u64 pk2(float lo, float hi) {
    u64 r;
    asm("mov.b64 %0, {%1, %2};" : "=l"(r) : "f"(lo), "f"(hi));
    return r;
}
__device__ __forceinline__ u64 dup2(float v) { return pk2(v, v); }
__device__ __forceinline__ void upk2(float& lo, float& hi, u64 v) {
    asm("mov.b64 {%0, %1}, %2;" : "=f"(lo), "=f"(hi) : "l"(v));
}
__device__ __forceinline__ void fma2(u64& d, u64 a, u64 b) {
    asm("fma.rn.f32x2 %0, %1, %2, %0;" : "+l"(d) : "l"(a), "l"(b));
}
__device__ __forceinline__ void mul2(u64& d, u64 a, u64 b) {
    asm("mul.rn.f32x2 %0, %1, %2;" : "=l"(d) : "l"(a), "l"(b));
}

// ---------------------------------------------------------------------------
// mma.sync / ldmatrix / cp.async helpers (compute_103-legal PTX)
// ---------------------------------------------------------------------------
__device__ __forceinline__ u32 smem_u32(const void* p) {
    u32 a;
    asm("{ .reg .u64 t; cvta.to.shared.u64 t, %1; cvt.u32.u64 %0, t; }"
        : "=r"(a) : "l"(p));
    return a;
}
__device__ __forceinline__ void cpasync16(u32 smem_dst, const void* gptr) {
    asm volatile("cp.async.ca.shared.global [%0], [%1], 16;"
                 :: "r"(smem_dst), "l"(gptr));
}
__device__ __forceinline__ void cpcommit() {
    asm volatile("cp.async.commit_group;");
}
__device__ __forceinline__ void cpwait0() {
    asm volatile("cp.async.wait_group 0;");
}
__device__ __forceinline__ void ldsm_x4(u32& r0, u32& r1, u32& r2, u32& r3,
                                        u32 addr) {
    asm volatile("ldmatrix.sync.aligned.m8n8.x4.shared.b16 {%0,%1,%2,%3}, [%4];"
                 : "=r"(r0), "=r"(r1), "=r"(r2), "=r"(r3) : "r"(addr));
}
__device__ __forceinline__ void mma_bf16(float* c, const u32* a, const u32* b) {
    asm volatile(
        "mma.sync.aligned.m16n8k16.row.col.f32.bf16.bf16.f32 "
        "{%0,%1,%2,%3}, {%4,%5,%6,%7}, {%8,%9}, {%0,%1,%2,%3};"
        : "+f"(c[0]), "+f"(c[1]), "+f"(c[2]), "+f"(c[3])
        : "r"(a[0]), "r"(a[1]), "r"(a[2]), "r"(a[3]), "r"(b[0]), "r"(b[1]));
}

// ----------------------------------------------------------------------------
// Device scratch (static; no allocations allowed)
// ----------------------------------------------------------------------------
static __device__ float g_q[BT * CC];
static __device__ float g_k[BT * CC];
static __device__ float g_v[BT * CC];
static __device__ float g_qr[BT * CC];
static __device__ float g_qi[BT * CC];
static __device__ float g_kr[BT * CC];
static __device__ float g_ki[BT * CC];
static __device__ float g_vr[BT * CC];
static __device__ float g_y[BT * CC];
static __device__ float g_inE[BT];
// bf16x3 splits
static __device__ __nv_bfloat16 g_xh[BT * CC];
static __device__ __nv_bfloat16 g_xm[BT * CC];
static __device__ __nv_bfloat16 g_xl[BT * CC];
static __device__ __nv_bfloat16 g_wt[12 * CC * CC];   // 4 weights x {h,m,l}, [N][K]

// ----------------------------------------------------------------------------
// Reductions
// ----------------------------------------------------------------------------
__device__ __forceinline__ float blockReduceSum256(float v) {
    __shared__ float red[8];
    int lane = threadIdx.x & 31;
    int w = threadIdx.x >> 5;
#pragma unroll
    for (int o = 16; o >= 1; o >>= 1)
        v += __shfl_xor_sync(0xffffffffu, v, o);
    if (lane == 0) red[w] = v;
    __syncthreads();
    if (w == 0) {
        v = (lane < 8) ? red[lane] : 0.f;
#pragma unroll
        for (int o = 4; o >= 1; o >>= 1)
            v += __shfl_xor_sync(0xffffffffu, v, o);
    }
    return v;  // valid in thread 0
}

// ----------------------------------------------------------------------------
// Fused: input energy ||x[row,:]|| + bf16x3 split of x (one pass over x)
// ----------------------------------------------------------------------------
__global__ void energy_split_kernel(const float* __restrict__ x,
                                    __nv_bfloat16* __restrict__ H,
                                    __nv_bfloat16* __restrict__ M,
                                    __nv_bfloat16* __restrict__ L) {
    int row = blockIdx.x;
    const float* xr = x + (size_t)row * CC;
    float s = 0.f;
    for (int c = threadIdx.x; c < CC; c += 256) {
        float v = xr[c];
        s += v * v;
        __nv_bfloat16 h = __float2bfloat16(v);
        float r = v - __bfloat162float(h);
        __nv_bfloat16 m = __float2bfloat16(r);
        r -= __bfloat162float(m);
        size_t o = (size_t)row * CC + c;
        H[o] = h; M[o] = m; L[o] = __float2bfloat16(r);
    }
    float tot = blockReduceSum256(s);
    if (threadIdx.x == 0) g_inE[row] = sqrtf(tot);
}

// ----------------------------------------------------------------------------
// Transpose + split W[k][n] -> WT{h,m,l}[n][k] bf16; grid.z selects weight
// ----------------------------------------------------------------------------
__global__ void wsplit4_kernel(const float* __restrict__ W0,
                               const float* __restrict__ W1,
                               const float* __restrict__ W2,
                               const float* __restrict__ W3,
                               __nv_bfloat16* __restrict__ WT) {
    __shared__ float t[32][33];
    const int wsel = blockIdx.z;
    const float* W = (wsel == 0) ? W0 : (wsel == 1) ? W1 : (wsel == 2) ? W2 : W3;
    __nv_bfloat16* H = WT + (size_t)(3 * wsel + 0) * CC * CC;
    __nv_bfloat16* M = WT + (size_t)(3 * wsel + 1) * CC * CC;
    __nv_bfloat16* L = WT + (size_t)(3 * wsel + 2) * CC * CC;
    int n0 = blockIdx.x << 5, k0 = blockIdx.y << 5;
    int tx = threadIdx.x, ty = threadIdx.y;
#pragma unroll
    for (int i = 0; i < 4; i++)
        t[ty + i * 8][tx] = W[(size_t)(k0 + ty + i * 8) * CC + n0 + tx];
    __syncthreads();
#pragma unroll
    for (int i = 0; i < 4; i++) {
        int n = n0 + ty + i * 8;
        float x = t[tx][ty + i * 8];
        __nv_bfloat16 h = __float2bfloat16(x);
        float r = x - __bfloat162float(h);
        __nv_bfloat16 m = __float2bfloat16(r);
        r -= __bfloat162float(m);
        size_t o = (size_t)n * CC + k0 + tx;
        H[o] = h; M[o] = m; L[o] = __float2bfloat16(r);
    }
}

// ----------------------------------------------------------------------------
// Tensor-core GEMM body via mma.sync bf16x3 (emulated fp32)
// ----------------------------------------------------------------------------
#define ASTRIDE 40
#define SPLITB (2 * 128 * ASTRIDE * 2)   // bytes per split (both buffers)
#define BUFB   (128 * ASTRIDE * 2)       // bytes per buffer

__device__ __forceinline__ void tc_gemm_body(
    const __nv_bfloat16* __restrict__ Ah, const __nv_bfloat16* __restrict__ Am,
    const __nv_bfloat16* __restrict__ Al, const __nv_bfloat16* __restrict__ Bh,
    const __nv_bfloat16* __restrict__ Bm, const __nv_bfloat16* __restrict__ Bl,
    const float* __restrict__ bias, float* __restrict__ Co,
    __nv_bfloat16* smb, int m0, int n0) {
    __nv_bfloat16* sB = smb + 3 * 2 * 128 * ASTRIDE;
    const u32 sAu = smem_u32(smb);
    const u32 sBu = smem_u32(sB);

    const int tid = threadIdx.x;
    const int wid = tid >> 5, lane = tid & 31;
    const int wm = wid >> 2, wn = wid & 3;        // warps 2 (m) x 4 (n)

    const __nv_bfloat16* Asrc[3] = {Ah, Am, Al};
    const __nv_bfloat16* Bsrc[3] = {Bh, Bm, Bl};

    float acc[4][4][4];
#pragma unroll
    for (int i = 0; i < 4; i++)
#pragma unroll
        for (int j = 0; j < 4; j++)
#pragma unroll
            for (int r = 0; r < 4; r++) acc[i][j][r] = 0.f;

    const int ldr0 = tid >> 2, ldk0 = (tid & 3) << 3;
    const int ldr1 = (tid + 256) >> 2, ldk1 = ((tid + 256) & 3) << 3;

    const u32 aRowB = (u32)(((lane & 7) + ((lane >> 3) & 1) * 8) * (ASTRIDE * 2));
    const u32 aKB   = (u32)(((lane >> 4) & 1) * 16);
    const u32 bRowB = (u32)(((lane & 7) + ((lane >> 4) & 1) * 8) * (ASTRIDE * 2));
    const u32 bKB   = (u32)(((lane >> 3) & 1) * 16);

#define ISSUE_CHUNK(c, buf)                                                     \
    do {                                                                        \
        _Pragma("unroll")                                                       \
        for (int t_ = 0; t_ < 3; t_++) {                                        \
            const __nv_bfloat16* ga = Asrc[t_] + (size_t)(m0 + ldr0) * CC +     \
                                      (c) * 32 + ldk0;                          \
            const __nv_bfloat16* ga1 = Asrc[t_] + (size_t)(m0 + ldr1) * CC +    \
                                       (c) * 32 + ldk1;                         \
            const __nv_bfloat16* gb = Bsrc[t_] + (size_t)(n0 + ldr0) * CC +     \
                                      (c) * 32 + ldk0;                          \
            const __nv_bfloat16* gb1 = Bsrc[t_] + (size_t)(n0 + ldr1) * CC +    \
                                       (c) * 32 + ldk1;                         \
            u32 d0 = (u32)(t_ * SPLITB + (buf) * BUFB +                         \
                           (ldr0 * ASTRIDE + ldk0) * 2);                        \
            u32 d1 = (u32)(t_ * SPLITB + (buf) * BUFB +                         \
                           (ldr1 * ASTRIDE + ldk1) * 2);                        \
            cpasync16(sAu + d0, ga);                                            \
            cpasync16(sAu + d1, ga1);                                           \
            cpasync16(sBu + d0, gb);                                            \
            cpasync16(sBu + d1, gb1);                                           \
        }                                                                       \
        cpcommit();                                                             \
    } while (0)

    ISSUE_CHUNK(0, 0);

    for (int c = 0; c < 32; c++) {
        const int buf = c & 1;
        cpwait0();
        __syncthreads();
        if (c + 1 < 32) ISSUE_CHUNK(c + 1, buf ^ 1);

#pragma unroll
        for (int ks = 0; ks < 2; ks++) {
            u32 af[3][4][4];
#pragma unroll
            for (int t = 0; t < 3; t++)
#pragma unroll
                for (int mi = 0; mi < 4; mi++) {
                    u32 addr = sAu + (u32)(t * SPLITB + buf * BUFB) +
                               (u32)((wm * 64 + mi * 16) * (ASTRIDE * 2)) +
                               aRowB + (u32)(ks * 32) + aKB;
                    ldsm_x4(af[t][mi][0], af[t][mi][1], af[t][mi][2],
                            af[t][mi][3], addr);
                }
#pragma unroll
            for (int bt = 0; bt < 3; bt++) {
                u32 bfr[2][4];
#pragma unroll
                for (int np = 0; np < 2; np++) {
                    u32 addr = sBu + (u32)(bt * SPLITB + buf * BUFB) +
                               (u32)((wn * 32 + np * 16) * (ASTRIDE * 2)) +
                               bRowB + (u32)(ks * 32) + bKB;
                    ldsm_x4(bfr[np][0], bfr[np][1], bfr[np][2], bfr[np][3],
                            addr);
                }
                const int nA = (bt == 0) ? 3 : (bt == 1) ? 2 : 1;
#pragma unroll
                for (int ia = 0; ia < 3; ia++) {
                    if (ia >= nA) break;
#pragma unroll
                    for (int mi = 0; mi < 4; mi++)
#pragma unroll
                        for (int ni = 0; ni < 4; ni++)
                            mma_bf16(acc[mi][ni], af[ia][mi],
                                     &bfr[ni >> 1][(ni & 1) * 2]);
                }
            }
        }
        __syncthreads();
    }

    const int grp = lane >> 2, qd = lane & 3;
#pragma unroll
    for (int mi = 0; mi < 4; mi++) {
#pragma unroll
        for (int ni = 0; ni < 4; ni++) {
            int row = m0 + wm * 64 + mi * 16 + grp;
            int col = n0 + wn * 32 + ni * 8 + qd * 2;
            float b0 = bias[col], b1 = bias[col + 1];
            float2 o0 = make_float2(acc[mi][ni][0] + b0, acc[mi][ni][1] + b1);
            float2 o1 = make_float2(acc[mi][ni][2] + b0, acc[mi][ni][3] + b1);
            *(float2*)&Co[(size_t)row * CC + col] = o0;
            *(float2*)&Co[(size_t)(row + 8) * CC + col] = o1;
        }
    }
}

// single-output GEMM (wo projection)
__global__ void __launch_bounds__(256, 1)
tc_gemm_kernel(const __nv_bfloat16* __restrict__ Ah,
               const __nv_bfloat16* __restrict__ Am,
               const __nv_bfloat16* __restrict__ Al,
               const __nv_bfloat16* __restrict__ Bh,
               const __nv_bfloat16* __restrict__ Bm,
               const __nv_bfloat16* __restrict__ Bl,
               const float* __restrict__ bias, float* __restrict__ Co) {
    extern __shared__ __align__(16) __nv_bfloat16 smb[];
    tc_gemm_body(Ah, Am, Al, Bh, Bm, Bl, bias, Co, smb,
                 blockIdx.y << 7, blockIdx.x << 7);
}

// batched QKV GEMM: grid.z = 0/1/2 -> (wq->q), (wk->k), (wv->v)
__global__ void __launch_bounds__(256, 1)
tc_gemm3_kernel(const __nv_bfloat16* __restrict__ Ah,
                const __nv_bfloat16* __restrict__ Am,
                const __nv_bfloat16* __restrict__ Al,
                const __nv_bfloat16* __restrict__ WT,
                const float* __restrict__ bq, const float* __restrict__ bk,
                const float* __restrict__ bv,
                float* __restrict__ Q, float* __restrict__ K,
                float* __restrict__ V) {
    extern __shared__ __align__(16) __nv_bfloat16 smb[];
    const int z = blockIdx.z;
    const __nv_bfloat16* B = WT + (size_t)(3 * z) * CC * CC;
    const float* bias = (z == 0) ? bq : (z == 1) ? bk : bv;
    float* Co = (z == 0) ? Q : (z == 1) ? K : V;
    tc_gemm_body(Ah, Am, Al, B, B + (size_t)CC * CC, B + (size_t)2 * CC * CC,
                 bias, Co, smb, blockIdx.y << 7, blockIdx.x << 7);
}

// ----------------------------------------------------------------------------
// Batched FFT with real-pair packing (round-13, unchanged)
// ----------------------------------------------------------------------------
#define FSTR 9
__global__ void __launch_bounds__(256, 1)
fft_filter_kernel(const float* __restrict__ inQ, const float* __restrict__ inK,
                  const float* __restrict__ inV,
                  float* __restrict__ oQr, float* __restrict__ oQi,
                  float* __restrict__ oKr, float* __restrict__ oKi,
                  float* __restrict__ oVr,
                  const float* __restrict__ fd,
                  const float* __restrict__ alpha,
                  const float* __restrict__ fas) {
    extern __shared__ __align__(16) float2 sh[];   // sh[t*FSTR + c], c<8
    const int dg = blockIdx.x;          // 16-dim group 0..3
    const int which = blockIdx.y >> 4;  // 0=Q 1=K 2=V
    const int h = blockIdx.y & 15;
    const int b = blockIdx.z;
    const float* in = (which == 0) ? inQ : (which == 1) ? inK : inV;
    float* outRe = (which == 0) ? oQr : (which == 1) ? oKr : oVr;
    float* outIm = (which == 0) ? oQi : (which == 1) ? oKi : (float*)0;

    const int col0 = h * HDIM + dg * 16;
    const float* src = in + (size_t)b * TT * CC + col0;
    const int tid = threadIdx.x;

#pragma unroll
    for (int i = 0; i < 32; i++) {
        int e = tid + i * 256;
        int t = e >> 2, pr = e & 3;
        float4 v = *(const float4*)&src[(size_t)t * CC + pr * 4];
        unsigned r = __brev((unsigned)t) >> (32 - LOG2T);
        sh[r * FSTR + pr * 2]     = make_float2(v.x, v.y);
        sh[r * FSTR + pr * 2 + 1] = make_float2(v.z, v.w);
    }
    __syncthreads();

    for (int st = 1; st <= LOG2T; st++) {
        const int half = 1 << (st - 1);
        const float wstep = -6.283185307179586f / (float)(half * 2);
#pragma unroll
        for (int w = 0; w < 4; w++) {
            int idx = tid + w * 256;
            int pos = idx & (half - 1);
            int grp = idx >> (st - 1);
            int i0 = (grp << st) + pos;
            int i1 = i0 + half;
            float sn, cs;
            __sincosf(wstep * (float)pos, &sn, &cs);
            float2* p0 = &sh[i0 * FSTR];
            float2* p1 = &sh[i1 * FSTR];
#pragma unroll
            for (int c = 0; c < 8; c++) {
                float2 u = p0[c], v = p1[c];
                float tr = cs * v.x - sn * v.y;
                float ti = cs * v.y + sn * v.x;
                p0[c] = make_float2(u.x + tr, u.y + ti);
                p1[c] = make_float2(u.x - tr, u.y - ti);
            }
        }
        __syncthreads();
    }

    const float aal = alpha[0] + fas[0] * (fd[0] - 1.5f);
    const size_t obase = ((size_t)(b * HH + h)) * TT * HDIM + dg * 16;
#pragma unroll
    for (int i = 0; i < 8; i++) {
        int t = tid + i * 256;
        int tm = (TT - t) & (TT - 1);
        float fr = (float)(t < TT / 2 ? t : t - TT) * (1.0f / (float)TT);
        float phase = aal * atanf(logf(fabsf(fr) + 1e-10f));
        float sp, cp;
        sincosf(phase, &sp, &cp);
        const float2* pz = &sh[t * FSTR];
        const float2* pw = &sh[tm * FSTR];
        float re[16], im[16];
#pragma unroll
        for (int c = 0; c < 8; c++) {
            float2 Z = pz[c], W = pw[c];
            float Xr = 0.5f * (Z.x + W.x);
            float Xi = 0.5f * (Z.y - W.y);
            float Yr = 0.5f * (Z.y + W.y);
            float Yi = 0.5f * (W.x - Z.x);
            re[2 * c]     = Xr * cp - Xi * sp;
            im[2 * c]     = Xr * sp + Xi * cp;
            re[2 * c + 1] = Yr * cp - Yi * sp;
            im[2 * c + 1] = Yr * sp + Yi * cp;
        }
        size_t o = obase + (size_t)t * HDIM;
#pragma unroll
        for (int q4 = 0; q4 < 4; q4++)
            *(float4*)&outRe[o + q4 * 4] =
                make_float4(re[q4 * 4], re[q4 * 4 + 1], re[q4 * 4 + 2],
                            re[q4 * 4 + 3]);
        if (outIm) {
#pragma unroll
            for (int q4 = 0; q4 < 4; q4++)
                *(float4*)&outIm[o + q4 * 4] =
                    make_float4(im[q4 * 4], im[q4 * 4 + 1], im[q4 * 4 + 2],
                                im[q4 * 4 + 3]);
        }
    }
}

// ----------------------------------------------------------------------------
// Tensor-core flash attention per (b,h).
// t-tile 128, s-tile 64, 256 threads (8 warps; warp w owns rows w*16..w*16+15,
// all 64 s columns -> row softmax stays inside one lane-quad).
// S: 12 accumulate-chained bf16 mma passes (Qr{h,m,l} x Kr{h,m,l} 6-product set
// + Qi x (-Ki)), split error ~2^-24. PV: bf16x2 x bf16x2, 3 passes.
// Q prescaled by 1/8 at conversion. Epilogue emits bf16x3 O-splits.
// ----------------------------------------------------------------------------
#define KSTR 72                 // smem row stride in bf16 elems (144 B)
#define OQRH 0
#define OQRM 9216
#define OQRL 18432
#define OQIH 27648
#define OQIM 36864
#define OQIL 46080
#define OKRH 55296
#define OKRM 59904
#define OKRL 64512
#define OKIH 69120
#define OKIM 73728
#define OKIL 78336
#define OVH  82944
#define OVM  87552
#define OPH  92160
#define OPM  101376
#define ATTN_SMEM_BYTES (110592 * 2)   // 221184

__device__ __forceinline__ void st2h(__nv_bfloat16* p, __nv_bfloat16 a,
                                     __nv_bfloat16 b) {
    __nv_bfloat162 t;
    t.x = a; t.y = b;
    *(__nv_bfloat162*)p = t;
}

__global__ void __launch_bounds__(256, 1)
attn_kernel(const float* __restrict__ Qr, const float* __restrict__ Qi,
            const float* __restrict__ Kr, const float* __restrict__ Ki,
            const float* __restrict__ Vr,
            __nv_bfloat16* __restrict__ Oh, __nv_bfloat16* __restrict__ Om,
            __nv_bfloat16* __restrict__ Ol) {
    extern __shared__ __align__(16) __nv_bfloat16 sm[];
    const u32 smU = smem_u32(sm);
    const int tid = threadIdx.x;
    const int wid = tid >> 5, lane = tid & 31;
    const int grp = lane >> 2, qd = lane & 3;
    const int t0 = blockIdx.x << 7;
    const int h = blockIdx.y, b = blockIdx.z;
    const size_t base = ((size_t)(b * HH + h)) * TT * HDIM;

    // ldmatrix lane-offset patterns (validated in tc_gemm)
    const u32 aOff = (u32)(((lane & 7) + ((lane >> 3) & 1) * 8) * (KSTR * 2) +
                           ((lane >> 4) & 1) * 16);
    const u32 bOff = (u32)(((lane & 7) + ((lane >> 4) & 1) * 8) * (KSTR * 2) +
                           ((lane >> 3) & 1) * 16);
    const u32 aWarp = (u32)(wid * 16 * (KSTR * 2));

    // ---- convert Q tile (128 x 64, scaled by 1/8) to bf16x3 (r and i) ----
#pragma unroll
    for (int i = 0; i < 8; i++) {
        int e = tid + i * 256;          // 0..2047
        int r = e >> 4, c4 = (e & 15) << 2;
        size_t g = base + (size_t)(t0 + r) * HDIM + c4;
        float4 xr = *(const float4*)&Qr[g];
        float4 xi = *(const float4*)&Qi[g];
        float vr_[4] = {xr.x, xr.y, xr.z, xr.w};
        float vi_[4] = {xi.x, xi.y, xi.z, xi.w};
        int off = r * KSTR + c4;
        __nv_bfloat16 hv[4], mv[4], lv[4];
#pragma unroll
        for (int j = 0; j < 4; j++) {
            float v = vr_[j] * 0.125f;
            hv[j] = __float2bfloat16(v);
            float rr = v - __bfloat162float(hv[j]);
            mv[j] = __float2bfloat16(rr);
            lv[j] = __float2bfloat16(rr - __bfloat162float(mv[j]));
        }
        st2h(sm + OQRH + off, hv[0], hv[1]); st2h(sm + OQRH + off + 2, hv[2], hv[3]);
        st2h(sm + OQRM + off, mv[0], mv[1]); st2h(sm + OQRM + off + 2, mv[2], mv[3]);
        st2h(sm + OQRL + off, lv[0], lv[1]); st2h(sm + OQRL + off + 2, lv[2], lv[3]);
#pragma unroll
        for (int j = 0; j < 4; j++) {
            float v = vi_[j] * 0.125f;
            hv[j] = __float2bfloat16(v);
            float rr = v - __bfloat162float(hv[j]);
            mv[j] = __float2bfloat16(rr);
            lv[j] = __float2bfloat16(rr - __bfloat162float(mv[j]));
        }
        st2h(sm + OQIH + off, hv[0], hv[1]); st2h(sm + OQIH + off + 2, hv[2], hv[3]);
        st2h(sm + OQIM + off, mv[0], mv[1]); st2h(sm + OQIM + off + 2, mv[2], mv[3]);
        st2h(sm + OQIL + off, lv[0], lv[1]); st2h(sm + OQIL + off + 2, lv[2], lv[3]);
    }

    float m0 = -INFINITY, m1 = -INFINITY, l0 = 0.f, l1 = 0.f;
    float Oacc[8][4];
#pragma unroll
    for (int ni = 0; ni < 8; ni++)
#pragma unroll
        for (int j = 0; j < 4; j++) Oacc[ni][j] = 0.f;

    for (int s0 = 0; s0 < TT; s0 += 64) {
        __syncthreads();   // previous tile fully consumed
        // ---- convert K (r, -i) bf16x3 + V bf16x2 transposed ----
#pragma unroll
        for (int i = 0; i < 4; i++) {
            int e = tid + i * 256;      // 0..1023
            int r = e >> 4, c4 = (e & 15) << 2;
            size_t g = base + (size_t)(s0 + r) * HDIM + c4;
            float4 kr = *(const float4*)&Kr[g];
            float4 ki = *(const float4*)&Ki[g];
            float4 vv = *(const float4*)&Vr[g];
            float kv[4] = {kr.x, kr.y, kr.z, kr.w};
            float jv[4] = {-ki.x, -ki.y, -ki.z, -ki.w};
            float va[4] = {vv.x, vv.y, vv.z, vv.w};
            int off = r * KSTR + c4;
            __nv_bfloat16 hv[4], mv[4], lv[4];
#pragma unroll
            for (int j = 0; j < 4; j++) {
                hv[j] = __float2bfloat16(kv[j]);
                float rr = kv[j] - __bfloat162float(hv[j]);
                mv[j] = __float2bfloat16(rr);
                lv[j] = __float2bfloat16(rr - __bfloat162float(mv[j]));
            }
            st2h(sm + OKRH + off, hv[0], hv[1]); st2h(sm + OKRH + off + 2, hv[2], hv[3]);
            st2h(sm + OKRM + off, mv[0], mv[1]); st2h(sm + OKRM + off + 2, mv[2], mv[3]);
            st2h(sm + OKRL + off, lv[0], lv[1]); st2h(sm + OKRL + off + 2, lv[2], lv[3]);
#pragma unroll
            for (int j = 0; j < 4; j++) {
                hv[j] = __float2bfloat16(jv[j]);
                float rr = jv[j] - __bfloat162float(hv[j]);
                mv[j] = __float2bfloat16(rr);
                lv[j] = __float2bfloat16(rr - __bfloat162float(mv[j]));
            }
            st2h(sm + OKIH + off, hv[0], hv[1]); st2h(sm + OKIH + off + 2, hv[2], hv[3]);
            st2h(sm + OKIM + off, mv[0], mv[1]); st2h(sm + OKIM + off + 2, mv[2], mv[3]);
            st2h(sm + OKIL + off, lv[0], lv[1]); st2h(sm + OKIL + off + 2, lv[2], lv[3]);
            // V transposed: Vt[d][s]
#pragma unroll
            for (int j = 0; j < 4; j++) {
                __nv_bfloat16 vh = __float2bfloat16(va[j]);
                __nv_bfloat16 vm = __float2bfloat16(va[j] - __bfloat162float(vh));
                sm[OVH + (c4 + j) * KSTR + r] = vh;
                sm[OVM + (c4 + j) * KSTR + r] = vm;
            }
        }
        __syncthreads();

        // ---- S phase: 12 accumulate-chained bf16 mma passes ----
        float Sacc[8][4];
#pragma unroll
        for (int ni = 0; ni < 8; ni++)
#pragma unroll
            for (int j = 0; j < 4; j++) Sacc[ni][j] = 0.f;

        const int QO[6] = {OQRH, OQRM, OQRL, OQIH, OQIM, OQIL};
        const int KO[6] = {OKRH, OKRM, OKRL, OKIH, OKIM, OKIL};
#pragma unroll
        for (int part = 0; part < 2; part++) {
#pragma unroll
            for (int bk = 0; bk < 3; bk++) {
                const int nA = 3 - bk;
                const u32 kb = smU + (u32)(KO[part * 3 + bk] * 2);
#pragma unroll
                for (int ks = 0; ks < 4; ks++) {
                    u32 bfr[4][4];
#pragma unroll
                    for (int np = 0; np < 4; np++)
                        ldsm_x4(bfr[np][0], bfr[np][1], bfr[np][2], bfr[np][3],
                                kb + (u32)(np * 16 * (KSTR * 2)) + bOff +
                                    (u32)(ks * 32));
#pragma unroll
                    for (int ia = 0; ia < 3; ia++) {
                        if (ia >= nA) break;
                        u32 af[4];
                        ldsm_x4(af[0], af[1], af[2], af[3],
                                smU + (u32)(QO[part * 3 + ia] * 2) + aWarp +
                                    aOff + (u32)(ks * 32));
#pragma unroll
                        for (int ni = 0; ni < 8; ni++)
                            mma_bf16(Sacc[ni], af, &bfr[ni >> 1][(ni & 1) * 2]);
                    }
                }
            }
        }

        // ---- online softmax on fragments; P -> bf16x2 smem ----
        float mx0 = Sacc[0][0], mx1 = Sacc[0][2];
#pragma unroll
        for (int ni = 0; ni < 8; ni++) {
            mx0 = fmaxf(mx0, fmaxf(Sacc[ni][0], Sacc[ni][1]));
            mx1 = fmaxf(mx1, fmaxf(Sacc[ni][2], Sacc[ni][3]));
        }
        mx0 = fmaxf(mx0, __shfl_xor_sync(0xffffffffu, mx0, 1));
        mx0 = fmaxf(mx0, __shfl_xor_sync(0xffffffffu, mx0, 2));
        mx1 = fmaxf(mx1, __shfl_xor_sync(0xffffffffu, mx1, 1));
        mx1 = fmaxf(mx1, __shfl_xor_sync(0xffffffffu, mx1, 2));
        float mn0 = fmaxf(m0, mx0), mn1 = fmaxf(m1, mx1);
        float c0 = __expf(m0 - mn0), c1 = __expf(m1 - mn1);
        m0 = mn0; m1 = mn1;
        float ps0 = 0.f, ps1 = 0.f;
        const int r0 = wid * 16 + grp;
#pragma unroll
        for (int ni = 0; ni < 8; ni++) {
            float p00 = __expf(Sacc[ni][0] - mn0);
            float p01 = __expf(Sacc[ni][1] - mn0);
            float p10 = __expf(Sacc[ni][2] - mn1);
            float p11 = __expf(Sacc[ni][3] - mn1);
            ps0 += p00 + p01;
            ps1 += p10 + p11;
            int col = ni * 8 + qd * 2;
            __nv_bfloat16 h00 = __float2bfloat16(p00);
            __nv_bfloat16 h01 = __float2bfloat16(p01);
            __nv_bfloat16 h10 = __float2bfloat16(p10);
            __nv_bfloat16 h11 = __float2bfloat16(p11);
            st2h(sm + OPH + r0 * KSTR + col, h00, h01);
            st2h(sm + OPH + (r0 + 8) * KSTR + col, h10, h11);
            st2h(sm + OPM + r0 * KSTR + col,
                 __float2bfloat16(p00 - __bfloat162float(h00)),
                 __float2bfloat16(p01 - __bfloat162float(h01)));
            st2h(sm + OPM + (r0 + 8) * KSTR + col,
                 __float2bfloat16(p10 - __bfloat162float(h10)),
                 __float2bfloat16(p11 - __bfloat162float(h11)));
        }
        ps0 += __shfl_xor_sync(0xffffffffu, ps0, 1);
        ps0 += __shfl_xor_sync(0xffffffffu, ps0, 2);
        ps1 += __shfl_xor_sync(0xffffffffu, ps1, 1);
        ps1 += __shfl_xor_sync(0xffffffffu, ps1, 2);
        l0 = l0 * c0 + ps0;
        l1 = l1 * c1 + ps1;
#pragma unroll
        for (int ni = 0; ni < 8; ni++) {
            Oacc[ni][0] *= c0; Oacc[ni][1] *= c0;
            Oacc[ni][2] *= c1; Oacc[ni][3] *= c1;
        }
        __syncwarp();   // P stores visible to this warp's ldmatrix

        // ---- PV: O += P @ V (bf16x2 x bf16x2: hh, hm, mh) ----
#pragma unroll
        for (int vp = 0; vp < 3; vp++) {
            const u32 pb = smU + (u32)(((vp == 2) ? OPM : OPH) * 2) + aWarp;
            const u32 vb = smU + (u32)(((vp == 1) ? OVM : OVH) * 2);
#pragma unroll
            for (int ks = 0; ks < 4; ks++) {
                u32 bfr[4][4];
#pragma unroll
                for (int np = 0; np < 4; np++)
                    ldsm_x4(bfr[np][0], bfr[np][1], bfr[np][2], bfr[np][3],
                            vb + (u32)(np * 16 * (KSTR * 2)) + bOff +
                                (u32)(ks * 32));
                u32 af[4];
                ldsm_x4(af[0], af[1], af[2], af[3], pb + aOff + (u32)(ks * 32));
#pragma unroll
                for (int ni = 0; ni < 8; ni++)
                    mma_bf16(Oacc[ni], af, &bfr[ni >> 1][(ni & 1) * 2]);
            }
        }
    }

    // ---- epilogue: normalize, split bf16x3, write [b, t, h*64+d] ----
    float il0 = 1.f / l0, il1 = 1.f / l1;
    const int r0e = wid * 16 + grp;
#pragma unroll
    for (int ni = 0; ni < 8; ni++) {
        int col = h * HDIM + ni * 8 + qd * 2;
#pragma unroll
        for (int rr = 0; rr < 2; rr++) {
            int row = r0e + rr * 8;
            float sc = rr ? il1 : il0;
            float v0 = Oacc[ni][rr * 2 + 0] * sc;
            float v1 = Oacc[ni][rr * 2 + 1] * sc;
            size_t off = ((size_t)(b * TT + t0 + row)) * CC + col;
            __nv_bfloat16 h0 = __float2bfloat16(v0);
            __nv_bfloat16 h1 = __float2bfloat16(v1);
            float r0f = v0 - __bfloat162float(h0);
            float r1f = v1 - __bfloat162float(h1);
            __nv_bfloat16 mm0 = __float2bfloat16(r0f);
            __nv_bfloat16 mm1 = __float2bfloat16(r1f);
            st2h(&Oh[off], h0, h1);
            st2h(&Om[off], mm0, mm1);
            st2h(&Ol[off], __float2bfloat16(r0f - __bfloat162float(mm0)),
                 __float2bfloat16(r1f - __bfloat162float(mm1)));
        }
    }
}

// ----------------------------------------------------------------------------
// Final energy ratio: out = Y * (inE / (||Y row|| + 1e-8)) * energy_normalizer
// ----------------------------------------------------------------------------
__global__ void finalize_kernel(const float* __restrict__ Y,
                                const float* __restrict__ enorm,
                                float* __restrict__ out) {
    int row = blockIdx.x;
    const float* yr = Y + (size_t)row * CC;
    float s = 0.f;
    for (int c = threadIdx.x; c < CC; c += 256) {
        float v = yr[c];
        s += v * v;
    }
    float tot = blockReduceSum256(s);
    __shared__ float ratio;
    if (threadIdx.x == 0)
        ratio = g_inE[row] / (sqrtf(tot) + 1e-8f) * enorm[0];
    __syncthreads();
    for (int c = threadIdx.x; c < CC; c += 256)
        out[(size_t)row * CC + c] = yr[c] * ratio;
}

// ----------------------------------------------------------------------------
// Launch
// ----------------------------------------------------------------------------
extern "C" void kernel_launch(void* const* d_in, const int* in_sizes, int n_in,
                              void* d_out, int out_size) {
    const float* x      = (const float*)d_in[0];
    const float* fd     = (const float*)d_in[1];
    const float* wq     = (const float*)d_in[2];
    const float* bq     = (const float*)d_in[3];
    const float* wk     = (const float*)d_in[4];
    const float* bk     = (const float*)d_in[5];
    const float* wv     = (const float*)d_in[6];
    const float* bv     = (const float*)d_in[7];
    const float* wo     = (const float*)d_in[8];
    const float* bo     = (const float*)d_in[9];
    const float* alpha  = (const float*)d_in[10];
    const float* fas    = (const float*)d_in[11];
    const float* enorm  = (const float*)d_in[12];
    float* out = (float*)d_out;

    float *q, *k, *v, *qr, *qi, *kr, *ki, *vr, *y;
    __nv_bfloat16 *xh, *xm, *xl, *wt;
    cudaGetSymbolAddress((void**)&q,  g_q);
    cudaGetSymbolAddress((void**)&k,  g_k);
    cudaGetSymbolAddress((void**)&v,  g_v);
    cudaGetSymbolAddress((void**)&qr, g_qr);
    cudaGetSymbolAddress((void**)&qi, g_qi);
    cudaGetSymbolAddress((void**)&kr, g_kr);
    cudaGetSymbolAddress((void**)&ki, g_ki);
    cudaGetSymbolAddress((void**)&vr, g_vr);
    cudaGetSymbolAddress((void**)&y,  g_y);
    cudaGetSymbolAddress((void**)&xh, g_xh);
    cudaGetSymbolAddress((void**)&xm, g_xm);
    cudaGetSymbolAddress((void**)&xl, g_xl);
    cudaGetSymbolAddress((void**)&wt, g_wt);
    const size_t WSZ = (size_t)CC * CC;

    // fused: input energies + x split
    energy_split_kernel<<<BT, 256>>>(x, xh, xm, xl);

    // weight transpose+split (all 4 weights, one launch)
    dim3 wg(32, 32, 4), wb(32, 8);
    wsplit4_kernel<<<wg, wb>>>(wq, wk, wv, wo, wt);

    // QKV projections on tensor cores (one batched launch)
    static const int kTcSmem = 2 * 3 * 2 * 128 * ASTRIDE * (int)sizeof(__nv_bfloat16);
    cudaFuncSetAttribute(tc_gemm3_kernel,
                         cudaFuncAttributeMaxDynamicSharedMemorySize, kTcSmem);
    cudaFuncSetAttribute(tc_gemm_kernel,
                         cudaFuncAttributeMaxDynamicSharedMemorySize, kTcSmem);
    dim3 gg3(CC / 128, BT / 128, 3);
    tc_gemm3_kernel<<<gg3, 256, kTcSmem>>>(xh, xm, xl, wt, bq, bk, bv, q, k, v);

    // FFT + spectral filter (real-pair packed)
    static const int kFftSmem = TT * FSTR * (int)sizeof(float2);  // 147456
    cudaFuncSetAttribute(fft_filter_kernel,
                         cudaFuncAttributeMaxDynamicSharedMemorySize, kFftSmem);
    dim3 gf(HDIM / 16, HH * 3, BB);
    fft_filter_kernel<<<gf, 256, kFftSmem>>>(q, k, v, qr, qi, kr, ki, vr,
                                             fd, alpha, fas);

    // tensor-core attention (writes O splits directly into xh/xm/xl)
    cudaFuncSetAttribute(attn_kernel, cudaFuncAttributeMaxDynamicSharedMemorySize,
                         ATTN_SMEM_BYTES);
    dim3 ga(TT / 128, HH, BB);
    attn_kernel<<<ga, 256, ATTN_SMEM_BYTES>>>(qr, qi, kr, ki, vr, xh, xm, xl);

    // output projection
    dim3 gg(CC / 128, BT / 128);
    tc_gemm_kernel<<<gg, 256, kTcSmem>>>(xh, xm, xl,
                                         wt + 9 * WSZ, wt + 10 * WSZ, wt + 11 * WSZ,
                                         bo, y);

    // energy-ratio epilogue
    finalize_kernel<<<BT, 256>>>(y, enorm, out);
}

// round 15
// speedup vs baseline: 1.7214x; 1.0057x over previous
#include <cuda_runtime.h>
#include <cuda_bf16.h>
#include <math.h>
#include <cstdint>

// Problem constants
#define BB 2
#define TT 2048
#define CC 1024
#define HH 16
#define HDIM 64
#define BT (BB * TT)      // 4096 rows
#define LOG2T 11

typedef unsigned long long u64;
typedef unsigned int u32;

// ---------------------------------------------------------------------------
// helpers
// ---------------------------------------------------------------------------
__device__ __forceinline__ u32 smem_u32(const void* p) {
    u32 a;
    asm("{ .reg .u64 t; cvta.to.shared.u64 t, %1; cvt.u32.u64 %0, t; }"
        : "=r"(a) : "l"(p));
    return a;
}
__device__ __forceinline__ void cpasync16(u32 smem_dst, const void* gptr) {
    asm volatile("cp.async.ca.shared.global [%0], [%1], 16;"
                 :: "r"(smem_dst), "l"(gptr));
}
__device__ __forceinline__ void cpcommit() {
    asm volatile("cp.async.commit_group;");
}
__device__ __forceinline__ void cpwait0() {
    asm volatile("cp.async.wait_group 0;");
}
__device__ __forceinline__ void ldsm_x4(u32& r0, u32& r1, u32& r2, u32& r3,
                                        u32 addr) {
    asm volatile("ldmatrix.sync.aligned.m8n8.x4.shared.b16 {%0,%1,%2,%3}, [%4];"
                 : "=r"(r0), "=r"(r1), "=r"(r2), "=r"(r3) : "r"(addr));
}
__device__ __forceinline__ void mma_bf16(float* c, const u32* a, const u32* b) {
    asm volatile(
        "mma.sync.aligned.m16n8k16.row.col.f32.bf16.bf16.f32 "
        "{%0,%1,%2,%3}, {%4,%5,%6,%7}, {%8,%9}, {%0,%1,%2,%3};"
        : "+f"(c[0]), "+f"(c[1]), "+f"(c[2]), "+f"(c[3])
        : "r"(a[0]), "r"(a[1]), "r"(a[2]), "r"(a[3]), "r"(b[0]), "r"(b[1]));
}
__device__ __forceinline__ void st2h(__nv_bfloat16* p, __nv_bfloat16 a,
                                     __nv_bfloat16 b) {
    __nv_bfloat162 t;
    t.x = a; t.y = b;
    *(__nv_bfloat162*)p = t;
}
__device__ __forceinline__ u32 bpack(__nv_bfloat16 a, __nv_bfloat16 b) {
    __nv_bfloat162 t;
    t.x = a; t.y = b;
    return *(u32*)&t;
}

// ----------------------------------------------------------------------------
// Device scratch (static; no allocations allowed)
// ----------------------------------------------------------------------------
static __device__ float g_q[BT * CC];
static __device__ float g_k[BT * CC];
static __device__ float g_v[BT * CC];
static __device__ float g_y[BT * CC];
static __device__ float g_inE[BT];
// bf16x3 splits of x / attention output
static __device__ __nv_bfloat16 g_xh[BT * CC];
static __device__ __nv_bfloat16 g_xm[BT * CC];
static __device__ __nv_bfloat16 g_xl[BT * CC];
static __device__ __nv_bfloat16 g_wt[12 * CC * CC];   // 4 weights x {h,m,l}, [N][K]
// FFT-produced attention operand splits: Q(6: r h/m/l, i h/m/l, pre-scaled 1/8),
// K(6: r h/m/l, -i h/m/l), V(2: h/m). Layout [b,h,t,d].
static __device__ __nv_bfloat16 g_qs[6 * BT * CC];
static __device__ __nv_bfloat16 g_ks[6 * BT * CC];
static __device__ __nv_bfloat16 g_vs[2 * BT * CC];
#define QSZ ((size_t)BT * CC)

// ----------------------------------------------------------------------------
// Reductions
// ----------------------------------------------------------------------------
__device__ __forceinline__ float blockReduceSum256(float v) {
    __shared__ float red[8];
    int lane = threadIdx.x & 31;
    int w = threadIdx.x >> 5;
#pragma unroll
    for (int o = 16; o >= 1; o >>= 1)
        v += __shfl_xor_sync(0xffffffffu, v, o);
    if (lane == 0) red[w] = v;
    __syncthreads();
    if (w == 0) {
        v = (lane < 8) ? red[lane] : 0.f;
#pragma unroll
        for (int o = 4; o >= 1; o >>= 1)
            v += __shfl_xor_sync(0xffffffffu, v, o);
    }
    return v;  // valid in thread 0
}

// ----------------------------------------------------------------------------
// Fused: input energy ||x[row,:]|| + bf16x3 split of x
// ----------------------------------------------------------------------------
__global__ void energy_split_kernel(const float* __restrict__ x,
                                    __nv_bfloat16* __restrict__ H,
                                    __nv_bfloat16* __restrict__ M,
                                    __nv_bfloat16* __restrict__ L) {
    int row = blockIdx.x;
    const float* xr = x + (size_t)row * CC;
    float s = 0.f;
    for (int c = threadIdx.x; c < CC; c += 256) {
        float v = xr[c];
        s += v * v;
        __nv_bfloat16 h = __float2bfloat16(v);
        float r = v - __bfloat162float(h);
        __nv_bfloat16 m = __float2bfloat16(r);
        r -= __bfloat162float(m);
        size_t o = (size_t)row * CC + c;
        H[o] = h; M[o] = m; L[o] = __float2bfloat16(r);
    }
    float tot = blockReduceSum256(s);
    if (threadIdx.x == 0) g_inE[row] = sqrtf(tot);
}

// ----------------------------------------------------------------------------
// Transpose + split W[k][n] -> WT{h,m,l}[n][k] bf16; grid.z selects weight
// ----------------------------------------------------------------------------
__global__ void wsplit4_kernel(const float* __restrict__ W0,
                               const float* __restrict__ W1,
                               const float* __restrict__ W2,
                               const float* __restrict__ W3,
                               __nv_bfloat16* __restrict__ WT) {
    __shared__ float t[32][33];
    const int wsel = blockIdx.z;
    const float* W = (wsel == 0) ? W0 : (wsel == 1) ? W1 : (wsel == 2) ? W2 : W3;
    __nv_bfloat16* H = WT + (size_t)(3 * wsel + 0) * CC * CC;
    __nv_bfloat16* M = WT + (size_t)(3 * wsel + 1) * CC * CC;
    __nv_bfloat16* L = WT + (size_t)(3 * wsel + 2) * CC * CC;
    int n0 = blockIdx.x << 5, k0 = blockIdx.y << 5;
    int tx = threadIdx.x, ty = threadIdx.y;
#pragma unroll
    for (int i = 0; i < 4; i++)
        t[ty + i * 8][tx] = W[(size_t)(k0 + ty + i * 8) * CC + n0 + tx];
    __syncthreads();
#pragma unroll
    for (int i = 0; i < 4; i++) {
        int n = n0 + ty + i * 8;
        float x = t[tx][ty + i * 8];
        __nv_bfloat16 h = __float2bfloat16(x);
        float r = x - __bfloat162float(h);
        __nv_bfloat16 m = __float2bfloat16(r);
        r -= __bfloat162float(m);
        size_t o = (size_t)n * CC + k0 + tx;
        H[o] = h; M[o] = m; L[o] = __float2bfloat16(r);
    }
}

// ----------------------------------------------------------------------------
// Tensor-core GEMM body via mma.sync bf16x3 (emulated fp32)
// ----------------------------------------------------------------------------
#define ASTRIDE 40
#define SPLITB (2 * 128 * ASTRIDE * 2)   // bytes per split (both buffers)
#define BUFB   (128 * ASTRIDE * 2)       // bytes per buffer

__device__ __forceinline__ void tc_gemm_body(
    const __nv_bfloat16* __restrict__ Ah, const __nv_bfloat16* __restrict__ Am,
    const __nv_bfloat16* __restrict__ Al, const __nv_bfloat16* __restrict__ Bh,
    const __nv_bfloat16* __restrict__ Bm, const __nv_bfloat16* __restrict__ Bl,
    const float* __restrict__ bias, float* __restrict__ Co,
    __nv_bfloat16* smb, int m0, int n0) {
    __nv_bfloat16* sB = smb + 3 * 2 * 128 * ASTRIDE;
    const u32 sAu = smem_u32(smb);
    const u32 sBu = smem_u32(sB);

    const int tid = threadIdx.x;
    const int wid = tid >> 5, lane = tid & 31;
    const int wm = wid >> 2, wn = wid & 3;        // warps 2 (m) x 4 (n)

    const __nv_bfloat16* Asrc[3] = {Ah, Am, Al};
    const __nv_bfloat16* Bsrc[3] = {Bh, Bm, Bl};

    float acc[4][4][4];
#pragma unroll
    for (int i = 0; i < 4; i++)
#pragma unroll
        for (int j = 0; j < 4; j++)
#pragma unroll
            for (int r = 0; r < 4; r++) acc[i][j][r] = 0.f;

    const int ldr0 = tid >> 2, ldk0 = (tid & 3) << 3;
    const int ldr1 = (tid + 256) >> 2, ldk1 = ((tid + 256) & 3) << 3;

    const u32 aRowB = (u32)(((lane & 7) + ((lane >> 3) & 1) * 8) * (ASTRIDE * 2));
    const u32 aKB   = (u32)(((lane >> 4) & 1) * 16);
    const u32 bRowB = (u32)(((lane & 7) + ((lane >> 4) & 1) * 8) * (ASTRIDE * 2));
    const u32 bKB   = (u32)(((lane >> 3) & 1) * 16);

#define ISSUE_CHUNK(c, buf)                                                     \
    do {                                                                        \
        _Pragma("unroll")                                                       \
        for (int t_ = 0; t_ < 3; t_++) {                                        \
            const __nv_bfloat16* ga = Asrc[t_] + (size_t)(m0 + ldr0) * CC +     \
                                      (c) * 32 + ldk0;                          \
            const __nv_bfloat16* ga1 = Asrc[t_] + (size_t)(m0 + ldr1) * CC +    \
                                       (c) * 32 + ldk1;                         \
            const __nv_bfloat16* gb = Bsrc[t_] + (size_t)(n0 + ldr0) * CC +     \
                                      (c) * 32 + ldk0;                          \
            const __nv_bfloat16* gb1 = Bsrc[t_] + (size_t)(n0 + ldr1) * CC +    \
                                       (c) * 32 + ldk1;                         \
            u32 d0 = (u32)(t_ * SPLITB + (buf) * BUFB +                         \
                           (ldr0 * ASTRIDE + ldk0) * 2);                        \
            u32 d1 = (u32)(t_ * SPLITB + (buf) * BUFB +                         \
                           (ldr1 * ASTRIDE + ldk1) * 2);                        \
            cpasync16(sAu + d0, ga);                                            \
            cpasync16(sAu + d1, ga1);                                           \
            cpasync16(sBu + d0, gb);                                            \
            cpasync16(sBu + d1, gb1);                                           \
        }                                                                       \
        cpcommit();                                                             \
    } while (0)

    ISSUE_CHUNK(0, 0);

    for (int c = 0; c < 32; c++) {
        const int buf = c & 1;
        cpwait0();
        __syncthreads();
        if (c + 1 < 32) ISSUE_CHUNK(c + 1, buf ^ 1);

#pragma unroll
        for (int ks = 0; ks < 2; ks++) {
            u32 af[3][4][4];
#pragma unroll
            for (int t = 0; t < 3; t++)
#pragma unroll
                for (int mi = 0; mi < 4; mi++) {
                    u32 addr = sAu + (u32)(t * SPLITB + buf * BUFB) +
                               (u32)((wm * 64 + mi * 16) * (ASTRIDE * 2)) +
                               aRowB + (u32)(ks * 32) + aKB;
                    ldsm_x4(af[t][mi][0], af[t][mi][1], af[t][mi][2],
                            af[t][mi][3], addr);
                }
#pragma unroll
            for (int bt = 0; bt < 3; bt++) {
                u32 bfr[2][4];
#pragma unroll
                for (int np = 0; np < 2; np++) {
                    u32 addr = sBu + (u32)(bt * SPLITB + buf * BUFB) +
                               (u32)((wn * 32 + np * 16) * (ASTRIDE * 2)) +
                               bRowB + (u32)(ks * 32) + bKB;
                    ldsm_x4(bfr[np][0], bfr[np][1], bfr[np][2], bfr[np][3],
                            addr);
                }
                const int nA = (bt == 0) ? 3 : (bt == 1) ? 2 : 1;
#pragma unroll
                for (int ia = 0; ia < 3; ia++) {
                    if (ia >= nA) break;
#pragma unroll
                    for (int mi = 0; mi < 4; mi++)
#pragma unroll
                        for (int ni = 0; ni < 4; ni++)
                            mma_bf16(acc[mi][ni], af[ia][mi],
                                     &bfr[ni >> 1][(ni & 1) * 2]);
                }
            }
        }
        __syncthreads();
    }

    const int grp = lane >> 2, qd = lane & 3;
#pragma unroll
    for (int mi = 0; mi < 4; mi++) {
#pragma unroll
        for (int ni = 0; ni < 4; ni++) {
            int row = m0 + wm * 64 + mi * 16 + grp;
            int col = n0 + wn * 32 + ni * 8 + qd * 2;
            float b0 = bias[col], b1 = bias[col + 1];
            float2 o0 = make_float2(acc[mi][ni][0] + b0, acc[mi][ni][1] + b1);
            float2 o1 = make_float2(acc[mi][ni][2] + b0, acc[mi][ni][3] + b1);
            *(float2*)&Co[(size_t)row * CC + col] = o0;
            *(float2*)&Co[(size_t)(row + 8) * CC + col] = o1;
        }
    }
}

// single-output GEMM (wo projection)
__global__ void __launch_bounds__(256, 1)
tc_gemm_kernel(const __nv_bfloat16* __restrict__ Ah,
               const __nv_bfloat16* __restrict__ Am,
               const __nv_bfloat16* __restrict__ Al,
               const __nv_bfloat16* __restrict__ Bh,
               const __nv_bfloat16* __restrict__ Bm,
               const __nv_bfloat16* __restrict__ Bl,
               const float* __restrict__ bias, float* __restrict__ Co) {
    extern __shared__ __align__(16) __nv_bfloat16 smb[];
    tc_gemm_body(Ah, Am, Al, Bh, Bm, Bl, bias, Co, smb,
                 blockIdx.y << 7, blockIdx.x << 7);
}

// batched QKV GEMM: grid.z = 0/1/2 -> (wq->q), (wk->k), (wv->v)
__global__ void __launch_bounds__(256, 1)
tc_gemm3_kernel(const __nv_bfloat16* __restrict__ Ah,
                const __nv_bfloat16* __restrict__ Am,
                const __nv_bfloat16* __restrict__ Al,
                const __nv_bfloat16* __restrict__ WT,
                const float* __restrict__ bq, const float* __restrict__ bk,
                const float* __restrict__ bv,
                float* __restrict__ Q, float* __restrict__ K,
                float* __restrict__ V) {
    extern __shared__ __align__(16) __nv_bfloat16 smb[];
    const int z = blockIdx.z;
    const __nv_bfloat16* B = WT + (size_t)(3 * z) * CC * CC;
    const float* bias = (z == 0) ? bq : (z == 1) ? bk : bv;
    float* Co = (z == 0) ? Q : (z == 1) ? K : V;
    tc_gemm_body(Ah, Am, Al, B, B + (size_t)CC * CC, B + (size_t)2 * CC * CC,
                 bias, Co, smb, blockIdx.y << 7, blockIdx.x << 7);
}

// ----------------------------------------------------------------------------
// split-store helpers (pack 16 bf16 -> 2x uint4 per split level)
// ----------------------------------------------------------------------------
__device__ __forceinline__ void writeSplit3(__nv_bfloat16* dst, const float* v) {
    u32 hw[8], mw[8], lw[8];
#pragma unroll
    for (int c = 0; c < 8; c++) {
        float a = v[2 * c], b = v[2 * c + 1];
        __nv_bfloat16 h0 = __float2bfloat16(a);
        __nv_bfloat16 h1 = __float2bfloat16(b);
        float r0 = a - __bfloat162float(h0);
        float r1 = b - __bfloat162float(h1);
        __nv_bfloat16 m0 = __float2bfloat16(r0);
        __nv_bfloat16 m1 = __float2bfloat16(r1);
        hw[c] = bpack(h0, h1);
        mw[c] = bpack(m0, m1);
        lw[c] = bpack(__float2bfloat16(r0 - __bfloat162float(m0)),
                      __float2bfloat16(r1 - __bfloat162float(m1)));
    }
    *(uint4*)(dst)              = make_uint4(hw[0], hw[1], hw[2], hw[3]);
    *(uint4*)(dst + 8)          = make_uint4(hw[4], hw[5], hw[6], hw[7]);
    *(uint4*)(dst + QSZ)        = make_uint4(mw[0], mw[1], mw[2], mw[3]);
    *(uint4*)(dst + QSZ + 8)    = make_uint4(mw[4], mw[5], mw[6], mw[7]);
    *(uint4*)(dst + 2 * QSZ)     = make_uint4(lw[0], lw[1], lw[2], lw[3]);
    *(uint4*)(dst + 2 * QSZ + 8) = make_uint4(lw[4], lw[5], lw[6], lw[7]);
}
__device__ __forceinline__ void writeSplit2(__nv_bfloat16* dst, const float* v) {
    u32 hw[8], mw[8];
#pragma unroll
    for (int c = 0; c < 8; c++) {
        float a = v[2 * c], b = v[2 * c + 1];
        __nv_bfloat16 h0 = __float2bfloat16(a);
        __nv_bfloat16 h1 = __float2bfloat16(b);
        hw[c] = bpack(h0, h1);
        mw[c] = bpack(__float2bfloat16(a - __bfloat162float(h0)),
                      __float2bfloat16(b - __bfloat162float(h1)));
    }
    *(uint4*)(dst)           = make_uint4(hw[0], hw[1], hw[2], hw[3]);
    *(uint4*)(dst + 8)       = make_uint4(hw[4], hw[5], hw[6], hw[7]);
    *(uint4*)(dst + QSZ)     = make_uint4(mw[0], mw[1], mw[2], mw[3]);
    *(uint4*)(dst + QSZ + 8) = make_uint4(mw[4], mw[5], mw[6], mw[7]);
}

// ----------------------------------------------------------------------------
// Batched FFT with real-pair packing; epilogue emits bf16 split arrays:
// Q -> g_qs (x1/8, r h/m/l + i h/m/l), K -> g_ks (r h/m/l + (-i) h/m/l),
// V -> g_vs (h/m).
// ----------------------------------------------------------------------------
#define FSTR 9
__global__ void __launch_bounds__(256, 1)
fft_filter_kernel(const float* __restrict__ inQ, const float* __restrict__ inK,
                  const float* __restrict__ inV,
                  __nv_bfloat16* __restrict__ Qs,
                  __nv_bfloat16* __restrict__ Ks,
                  __nv_bfloat16* __restrict__ Vs,
                  const float* __restrict__ fd,
                  const float* __restrict__ alpha,
                  const float* __restrict__ fas) {
    extern __shared__ __align__(16) float2 sh[];   // sh[t*FSTR + c], c<8
    const int dg = blockIdx.x;          // 16-dim group 0..3
    const int which = blockIdx.y >> 4;  // 0=Q 1=K 2=V
    const int h = blockIdx.y & 15;
    const int b = blockIdx.z;
    const float* in = (which == 0) ? inQ : (which == 1) ? inK : inV;

    const int col0 = h * HDIM + dg * 16;
    const float* src = in + (size_t)b * TT * CC + col0;
    const int tid = threadIdx.x;

#pragma unroll
    for (int i = 0; i < 32; i++) {
        int e = tid + i * 256;
        int t = e >> 2, pr = e & 3;
        float4 v = *(const float4*)&src[(size_t)t * CC + pr * 4];
        unsigned r = __brev((unsigned)t) >> (32 - LOG2T);
        sh[r * FSTR + pr * 2]     = make_float2(v.x, v.y);
        sh[r * FSTR + pr * 2 + 1] = make_float2(v.z, v.w);
    }
    __syncthreads();

    for (int st = 1; st <= LOG2T; st++) {
        const int half = 1 << (st - 1);
        const float wstep = -6.283185307179586f / (float)(half * 2);
#pragma unroll
        for (int w = 0; w < 4; w++) {
            int idx = tid + w * 256;
            int pos = idx & (half - 1);
            int grp = idx >> (st - 1);
            int i0 = (grp << st) + pos;
            int i1 = i0 + half;
            float sn, cs;
            __sincosf(wstep * (float)pos, &sn, &cs);
            float2* p0 = &sh[i0 * FSTR];
            float2* p1 = &sh[i1 * FSTR];
#pragma unroll
            for (int c = 0; c < 8; c++) {
                float2 u = p0[c], v = p1[c];
                float tr = cs * v.x - sn * v.y;
                float ti = cs * v.y + sn * v.x;
                p0[c] = make_float2(u.x + tr, u.y + ti);
                p1[c] = make_float2(u.x - tr, u.y - ti);
            }
        }
        __syncthreads();
    }

    const float aal = alpha[0] + fas[0] * (fd[0] - 1.5f);
    const size_t obase = ((size_t)(b * HH + h)) * TT * HDIM + dg * 16;
#pragma unroll
    for (int i = 0; i < 8; i++) {
        int t = tid + i * 256;
        int tm = (TT - t) & (TT - 1);
        float fr = (float)(t < TT / 2 ? t : t - TT) * (1.0f / (float)TT);
        float phase = aal * atanf(logf(fabsf(fr) + 1e-10f));
        float sp, cp;
        sincosf(phase, &sp, &cp);
        const float2* pz = &sh[t * FSTR];
        const float2* pw = &sh[tm * FSTR];
        float re[16], im[16];
#pragma unroll
        for (int c = 0; c < 8; c++) {
            float2 Z = pz[c], W = pw[c];
            float Xr = 0.5f * (Z.x + W.x);
            float Xi = 0.5f * (Z.y - W.y);
            float Yr = 0.5f * (Z.y + W.y);
            float Yi = 0.5f * (W.x - Z.x);
            re[2 * c]     = Xr * cp - Xi * sp;
            im[2 * c]     = Xr * sp + Xi * cp;
            re[2 * c + 1] = Yr * cp - Yi * sp;
            im[2 * c + 1] = Yr * sp + Yi * cp;
        }
        size_t o = obase + (size_t)t * HDIM;
        if (which == 0) {
#pragma unroll
            for (int c = 0; c < 16; c++) { re[c] *= 0.125f; im[c] *= 0.125f; }
            writeSplit3(Qs + o, re);
            writeSplit3(Qs + 3 * QSZ + o, im);
        } else if (which == 1) {
#pragma unroll
            for (int c = 0; c < 16; c++) im[c] = -im[c];
            writeSplit3(Ks + o, re);
            writeSplit3(Ks + 3 * QSZ + o, im);
        } else {
            writeSplit2(Vs + o, re);
        }
    }
}

// ----------------------------------------------------------------------------
// Tensor-core flash attention per (b,h). Tiles ingested as precomputed bf16
// splits via cp.async (no in-kernel conversion). t-tile 128, s-tile 64,
// 256 threads. S: 12 chained bf16 mma passes; PV: 3 passes.
// ----------------------------------------------------------------------------
#define KSTR 72                 // smem row stride in bf16 elems (144 B)
#define OQRH 0
#define OQRM 9216
#define OQRL 18432
#define OQIH 27648
#define OQIM 36864
#define OQIL 46080
#define OKRH 55296
#define OKRM 59904
#define OKRL 64512
#define OKIH 69120
#define OKIM 73728
#define OKIL 78336
#define OVH  82944
#define OVM  87552
#define OPH  92160
#define OPM  101376
#define ATTN_SMEM_BYTES (110592 * 2)   // 221184

__global__ void __launch_bounds__(256, 1)
attn_kernel(const __nv_bfloat16* __restrict__ Qs,
            const __nv_bfloat16* __restrict__ Ks,
            const __nv_bfloat16* __restrict__ Vs,
            __nv_bfloat16* __restrict__ Oh, __nv_bfloat16* __restrict__ Om,
            __nv_bfloat16* __restrict__ Ol) {
    extern __shared__ __align__(16) __nv_bfloat16 sm[];
    const u32 smU = smem_u32(sm);
    const int tid = threadIdx.x;
    const int wid = tid >> 5, lane = tid & 31;
    const int grp = lane >> 2, qd = lane & 3;
    const int t0 = blockIdx.x << 7;
    const int h = blockIdx.y, b = blockIdx.z;
    const size_t base = ((size_t)(b * HH + h)) * TT * HDIM;

    const u32 aOff = (u32)(((lane & 7) + ((lane >> 3) & 1) * 8) * (KSTR * 2) +
                           ((lane >> 4) & 1) * 16);
    const u32 bOff = (u32)(((lane & 7) + ((lane >> 4) & 1) * 8) * (KSTR * 2) +
                           ((lane >> 3) & 1) * 16);
    const u32 aWarp = (u32)(wid * 16 * (KSTR * 2));

    const int QO6[6] = {OQRH, OQRM, OQRL, OQIH, OQIM, OQIL};
    const int KO6[6] = {OKRH, OKRM, OKRL, OKIH, OKIM, OKIL};

    // ---- Q tile: cp.async all 6 splits (128 rows x 64 d) ----
#pragma unroll
    for (int i = 0; i < 4; i++) {
        int e = tid + i * 256;          // 0..1023 units of 8 bf16
        int r = e >> 3, c8 = (e & 7) << 3;
        size_t g = base + (size_t)(t0 + r) * HDIM + c8;
        u32 d = (u32)((r * KSTR + c8) * 2);
#pragma unroll
        for (int s = 0; s < 6; s++)
            cpasync16(smU + (u32)(QO6[s] * 2) + d, Qs + (size_t)s * QSZ + g);
    }
    cpcommit();

    float m0 = -INFINITY, m1 = -INFINITY, l0 = 0.f, l1 = 0.f;
    float Oacc[8][4];
#pragma unroll
    for (int ni = 0; ni < 8; ni++)
#pragma unroll
        for (int j = 0; j < 4; j++) Oacc[ni][j] = 0.f;

    for (int s0 = 0; s0 < TT; s0 += 64) {
        __syncthreads();   // previous tile fully consumed
        // ---- K: cp.async 6 splits; V: load + transpose store ----
#pragma unroll
        for (int i = 0; i < 2; i++) {
            int e = tid + i * 256;      // 0..511 units
            int r = e >> 3, c8 = (e & 7) << 3;
            size_t g = base + (size_t)(s0 + r) * HDIM + c8;
            u32 d = (u32)((r * KSTR + c8) * 2);
#pragma unroll
            for (int s = 0; s < 6; s++)
                cpasync16(smU + (u32)(KO6[s] * 2) + d, Ks + (size_t)s * QSZ + g);
        }
        cpcommit();
#pragma unroll
        for (int i = 0; i < 2; i++) {
            int e = tid + i * 256;
            int r = e >> 3, c8 = (e & 7) << 3;
            size_t g = base + (size_t)(s0 + r) * HDIM + c8;
            float4 vh4 = *(const float4*)(Vs + g);
            float4 vm4 = *(const float4*)(Vs + QSZ + g);
            const __nv_bfloat16* ph = (const __nv_bfloat16*)&vh4;
            const __nv_bfloat16* pm = (const __nv_bfloat16*)&vm4;
#pragma unroll
            for (int j = 0; j < 8; j++) {
                sm[OVH + (c8 + j) * KSTR + r] = ph[j];
                sm[OVM + (c8 + j) * KSTR + r] = pm[j];
            }
        }
        cpwait0();
        __syncthreads();

        // ---- S phase: 12 accumulate-chained bf16 mma passes ----
        float Sacc[8][4];
#pragma unroll
        for (int ni = 0; ni < 8; ni++)
#pragma unroll
            for (int j = 0; j < 4; j++) Sacc[ni][j] = 0.f;

#pragma unroll
        for (int part = 0; part < 2; part++) {
#pragma unroll
            for (int bk = 0; bk < 3; bk++) {
                const int nA = 3 - bk;
                const u32 kb = smU + (u32)(KO6[part * 3 + bk] * 2);
#pragma unroll
                for (int ks = 0; ks < 4; ks++) {
                    u32 bfr[4][4];
#pragma unroll
                    for (int np = 0; np < 4; np++)
                        ldsm_x4(bfr[np][0], bfr[np][1], bfr[np][2], bfr[np][3],
                                kb + (u32)(np * 16 * (KSTR * 2)) + bOff +
                                    (u32)(ks * 32));
#pragma unroll
                    for (int ia = 0; ia < 3; ia++) {
                        if (ia >= nA) break;
                        u32 af[4];
                        ldsm_x4(af[0], af[1], af[2], af[3],
                                smU + (u32)(QO6[part * 3 + ia] * 2) + aWarp +
                                    aOff + (u32)(ks * 32));
#pragma unroll
                        for (int ni = 0; ni < 8; ni++)
                            mma_bf16(Sacc[ni], af, &bfr[ni >> 1][(ni & 1) * 2]);
                    }
                }
            }
        }

        // ---- online softmax on fragments; P -> bf16x2 smem ----
        float mx0 = Sacc[0][0], mx1 = Sacc[0][2];
#pragma unroll
        for (int ni = 0; ni < 8; ni++) {
            mx0 = fmaxf(mx0, fmaxf(Sacc[ni][0], Sacc[ni][1]));
            mx1 = fmaxf(mx1, fmaxf(Sacc[ni][2], Sacc[ni][3]));
        }
        mx0 = fmaxf(mx0, __shfl_xor_sync(0xffffffffu, mx0, 1));
        mx0 = fmaxf(mx0, __shfl_xor_sync(0xffffffffu, mx0, 2));
        mx1 = fmaxf(mx1, __shfl_xor_sync(0xffffffffu, mx1, 1));
        mx1 = fmaxf(mx1, __shfl_xor_sync(0xffffffffu, mx1, 2));
        float mn0 = fmaxf(m0, mx0), mn1 = fmaxf(m1, mx1);
        float c0 = __expf(m0 - mn0), c1 = __expf(m1 - mn1);
        m0 = mn0; m1 = mn1;
        float ps0 = 0.f, ps1 = 0.f;
        const int r0 = wid * 16 + grp;
#pragma unroll
        for (int ni = 0; ni < 8; ni++) {
            float p00 = __expf(Sacc[ni][0] - mn0);
            float p01 = __expf(Sacc[ni][1] - mn0);
            float p10 = __expf(Sacc[ni][2] - mn1);
            float p11 = __expf(Sacc[ni][3] - mn1);
            ps0 += p00 + p01;
            ps1 += p10 + p11;
            int col = ni * 8 + qd * 2;
            __nv_bfloat16 h00 = __float2bfloat16(p00);
            __nv_bfloat16 h01 = __float2bfloat16(p01);
            __nv_bfloat16 h10 = __float2bfloat16(p10);
            __nv_bfloat16 h11 = __float2bfloat16(p11);
            st2h(sm + OPH + r0 * KSTR + col, h00, h01);
            st2h(sm + OPH + (r0 + 8) * KSTR + col, h10, h11);
            st2h(sm + OPM + r0 * KSTR + col,
                 __float2bfloat16(p00 - __bfloat162float(h00)),
                 __float2bfloat16(p01 - __bfloat162float(h01)));
            st2h(sm + OPM + (r0 + 8) * KSTR + col,
                 __float2bfloat16(p10 - __bfloat162float(h10)),
                 __float2bfloat16(p11 - __bfloat162float(h11)));
        }
        ps0 += __shfl_xor_sync(0xffffffffu, ps0, 1);
        ps0 += __shfl_xor_sync(0xffffffffu, ps0, 2);
        ps1 += __shfl_xor_sync(0xffffffffu, ps1, 1);
        ps1 += __shfl_xor_sync(0xffffffffu, ps1, 2);
        l0 = l0 * c0 + ps0;
        l1 = l1 * c1 + ps1;
#pragma unroll
        for (int ni = 0; ni < 8; ni++) {
            Oacc[ni][0] *= c0; Oacc[ni][1] *= c0;
            Oacc[ni][2] *= c1; Oacc[ni][3] *= c1;
        }
        __syncwarp();   // P stores visible to this warp's ldmatrix

        // ---- PV: O += P @ V (bf16x2 x bf16x2: hh, hm, mh) ----
#pragma unroll
        for (int vp = 0; vp < 3; vp++) {
            const u32 pb = smU + (u32)(((vp == 2) ? OPM : OPH) * 2) + aWarp;
            const u32 vb = smU + (u32)(((vp == 1) ? OVM : OVH) * 2);
#pragma unroll
            for (int ks = 0; ks < 4; ks++) {
                u32 bfr[4][4];
#pragma unroll
                for (int np = 0; np < 4; np++)
                    ldsm_x4(bfr[np][0], bfr[np][1], bfr[np][2], bfr[np][3],
                            vb + (u32)(np * 16 * (KSTR * 2)) + bOff +
                                (u32)(ks * 32));
                u32 af[4];
                ldsm_x4(af[0], af[1], af[2], af[3], pb + aOff + (u32)(ks * 32));
#pragma unroll
                for (int ni = 0; ni < 8; ni++)
                    mma_bf16(Oacc[ni], af, &bfr[ni >> 1][(ni & 1) * 2]);
            }
        }
    }

    // ---- epilogue: normalize, split bf16x3, write [b, t, h*64+d] ----
    float il0 = 1.f / l0, il1 = 1.f / l1;
    const int r0e = wid * 16 + grp;
#pragma unroll
    for (int ni = 0; ni < 8; ni++) {
        int col = h * HDIM + ni * 8 + qd * 2;
#pragma unroll
        for (int rr = 0; rr < 2; rr++) {
            int row = r0e + rr * 8;
            float sc = rr ? il1 : il0;
            float v0 = Oacc[ni][rr * 2 + 0] * sc;
            float v1 = Oacc[ni][rr * 2 + 1] * sc;
            size_t off = ((size_t)(b * TT + t0 + row)) * CC + col;
            __nv_bfloat16 h0 = __float2bfloat16(v0);
            __nv_bfloat16 h1 = __float2bfloat16(v1);
            float r0f = v0 - __bfloat162float(h0);
            float r1f = v1 - __bfloat162float(h1);
            __nv_bfloat16 mm0 = __float2bfloat16(r0f);
            __nv_bfloat16 mm1 = __float2bfloat16(r1f);
            st2h(&Oh[off], h0, h1);
            st2h(&Om[off], mm0, mm1);
            st2h(&Ol[off], __float2bfloat16(r0f - __bfloat162float(mm0)),
                 __float2bfloat16(r1f - __bfloat162float(mm1)));
        }
    }
}

// ----------------------------------------------------------------------------
// Final energy ratio: out = Y * (inE / (||Y row|| + 1e-8)) * energy_normalizer
// ----------------------------------------------------------------------------
__global__ void finalize_kernel(const float* __restrict__ Y,
                                const float* __restrict__ enorm,
                                float* __restrict__ out) {
    int row = blockIdx.x;
    const float* yr = Y + (size_t)row * CC;
    float s = 0.f;
    for (int c = threadIdx.x; c < CC; c += 256) {
        float v = yr[c];
        s += v * v;
    }
    float tot = blockReduceSum256(s);
    __shared__ float ratio;
    if (threadIdx.x == 0)
        ratio = g_inE[row] / (sqrtf(tot) + 1e-8f) * enorm[0];
    __syncthreads();
    for (int c = threadIdx.x; c < CC; c += 256)
        out[(size_t)row * CC + c] = yr[c] * ratio;
}

// ----------------------------------------------------------------------------
// Launch
// ----------------------------------------------------------------------------
extern "C" void kernel_launch(void* const* d_in, const int* in_sizes, int n_in,
                              void* d_out, int out_size) {
    const float* x      = (const float*)d_in[0];
    const float* fd     = (const float*)d_in[1];
    const float* wq     = (const float*)d_in[2];
    const float* bq     = (const float*)d_in[3];
    const float* wk     = (const float*)d_in[4];
    const float* bk     = (const float*)d_in[5];
    const float* wv     = (const float*)d_in[6];
    const float* bv     = (const float*)d_in[7];
    const float* wo     = (const float*)d_in[8];
    const float* bo     = (const float*)d_in[9];
    const float* alpha  = (const float*)d_in[10];
    const float* fas    = (const float*)d_in[11];
    const float* enorm  = (const float*)d_in[12];
    float* out = (float*)d_out;

    float *q, *k, *v, *y;
    __nv_bfloat16 *xh, *xm, *xl, *wt, *qs, *ks, *vs;
    cudaGetSymbolAddress((void**)&q,  g_q);
    cudaGetSymbolAddress((void**)&k,  g_k);
    cudaGetSymbolAddress((void**)&v,  g_v);
    cudaGetSymbolAddress((void**)&y,  g_y);
    cudaGetSymbolAddress((void**)&xh, g_xh);
    cudaGetSymbolAddress((void**)&xm, g_xm);
    cudaGetSymbolAddress((void**)&xl, g_xl);
    cudaGetSymbolAddress((void**)&wt, g_wt);
    cudaGetSymbolAddress((void**)&qs, g_qs);
    cudaGetSymbolAddress((void**)&ks, g_ks);
    cudaGetSymbolAddress((void**)&vs, g_vs);
    const size_t WSZ = (size_t)CC * CC;

    // fused: input energies + x split
    energy_split_kernel<<<BT, 256>>>(x, xh, xm, xl);

    // weight transpose+split (all 4 weights, one launch)
    dim3 wg(32, 32, 4), wb(32, 8);
    wsplit4_kernel<<<wg, wb>>>(wq, wk, wv, wo, wt);

    // QKV projections on tensor cores (one batched launch)
    static const int kTcSmem = 2 * 3 * 2 * 128 * ASTRIDE * (int)sizeof(__nv_bfloat16);
    cudaFuncSetAttribute(tc_gemm3_kernel,
                         cudaFuncAttributeMaxDynamicSharedMemorySize, kTcSmem);
    cudaFuncSetAttribute(tc_gemm_kernel,
                         cudaFuncAttributeMaxDynamicSharedMemorySize, kTcSmem);
    dim3 gg3(CC / 128, BT / 128, 3);
    tc_gemm3_kernel<<<gg3, 256, kTcSmem>>>(xh, xm, xl, wt, bq, bk, bv, q, k, v);

    // FFT + spectral filter -> bf16 split operands for attention
    static const int kFftSmem = TT * FSTR * (int)sizeof(float2);  // 147456
    cudaFuncSetAttribute(fft_filter_kernel,
                         cudaFuncAttributeMaxDynamicSharedMemorySize, kFftSmem);
    dim3 gf(HDIM / 16, HH * 3, BB);
    fft_filter_kernel<<<gf, 256, kFftSmem>>>(q, k, v, qs, ks, vs,
                                             fd, alpha, fas);

    // tensor-core attention (reads precomputed splits; writes O splits)
    cudaFuncSetAttribute(attn_kernel, cudaFuncAttributeMaxDynamicSharedMemorySize,
                         ATTN_SMEM_BYTES);
    dim3 ga(TT / 128, HH, BB);
    attn_kernel<<<ga, 256, ATTN_SMEM_BYTES>>>(qs, ks, vs, xh, xm, xl);

    // output projection
    dim3 gg(CC / 128, BT / 128);
    tc_gemm_kernel<<<gg, 256, kTcSmem>>>(xh, xm, xl,
                                         wt + 9 * WSZ, wt + 10 * WSZ, wt + 11 * WSZ,
                                         bo, y);

    // energy-ratio epilogue
    finalize_kernel<<<BT, 256>>>(y, enorm, out);
}

// round 16
// speedup vs baseline: 1.9116x; 1.1105x over previous
#include <cuda_runtime.h>
#include <cuda_bf16.h>
#include <math.h>
#include <cstdint>

// Problem constants
#define BB 2
#define TT 2048
#define CC 1024
#define HH 16
#define HDIM 64
#define BT (BB * TT)      // 4096 rows
#define LOG2T 11

typedef unsigned long long u64;
typedef unsigned int u32;

// ---------------------------------------------------------------------------
// helpers
// ---------------------------------------------------------------------------
__device__ __forceinline__ u32 smem_u32(const void* p) {
    u32 a;
    asm("{ .reg .u64 t; cvta.to.shared.u64 t, %1; cvt.u32.u64 %0, t; }"
        : "=r"(a) : "l"(p));
    return a;
}
__device__ __forceinline__ void cpasync16(u32 smem_dst, const void* gptr) {
    asm volatile("cp.async.ca.shared.global [%0], [%1], 16;"
                 :: "r"(smem_dst), "l"(gptr));
}
__device__ __forceinline__ void cpcommit() {
    asm volatile("cp.async.commit_group;");
}
__device__ __forceinline__ void cpwait0() {
    asm volatile("cp.async.wait_group 0;");
}
__device__ __forceinline__ void ldsm_x4(u32& r0, u32& r1, u32& r2, u32& r3,
                                        u32 addr) {
    asm volatile("ldmatrix.sync.aligned.m8n8.x4.shared.b16 {%0,%1,%2,%3}, [%4];"
                 : "=r"(r0), "=r"(r1), "=r"(r2), "=r"(r3) : "r"(addr));
}
__device__ __forceinline__ void mma_bf16(float* c, const u32* a, const u32* b) {
    asm volatile(
        "mma.sync.aligned.m16n8k16.row.col.f32.bf16.bf16.f32 "
        "{%0,%1,%2,%3}, {%4,%5,%6,%7}, {%8,%9}, {%0,%1,%2,%3};"
        : "+f"(c[0]), "+f"(c[1]), "+f"(c[2]), "+f"(c[3])
        : "r"(a[0]), "r"(a[1]), "r"(a[2]), "r"(a[3]), "r"(b[0]), "r"(b[1]));
}
__device__ __forceinline__ void st2h(__nv_bfloat16* p, __nv_bfloat16 a,
                                     __nv_bfloat16 b) {
    __nv_bfloat162 t;
    t.x = a; t.y = b;
    *(__nv_bfloat162*)p = t;
}
__device__ __forceinline__ u32 bpack(__nv_bfloat16 a, __nv_bfloat16 b) {
    __nv_bfloat162 t;
    t.x = a; t.y = b;
    return *(u32*)&t;
}

// ----------------------------------------------------------------------------
// Device scratch (static; no allocations allowed)
// ----------------------------------------------------------------------------
static __device__ float g_q[BT * CC];
static __device__ float g_k[BT * CC];
static __device__ float g_v[BT * CC];
static __device__ float g_y[BT * CC];
static __device__ float g_inE[BT];
static __device__ __nv_bfloat16 g_xh[BT * CC];
static __device__ __nv_bfloat16 g_xm[BT * CC];
static __device__ __nv_bfloat16 g_xl[BT * CC];
static __device__ __nv_bfloat16 g_wt[12 * CC * CC];   // 4 weights x {h,m,l}, [N][K]
static __device__ __nv_bfloat16 g_qs[6 * BT * CC];
static __device__ __nv_bfloat16 g_ks[6 * BT * CC];
static __device__ __nv_bfloat16 g_vs[2 * BT * CC];
#define QSZ ((size_t)BT * CC)

// ----------------------------------------------------------------------------
// Reductions
// ----------------------------------------------------------------------------
__device__ __forceinline__ float blockReduceSum256(float v) {
    __shared__ float red[8];
    int lane = threadIdx.x & 31;
    int w = threadIdx.x >> 5;
#pragma unroll
    for (int o = 16; o >= 1; o >>= 1)
        v += __shfl_xor_sync(0xffffffffu, v, o);
    if (lane == 0) red[w] = v;
    __syncthreads();
    if (w == 0) {
        v = (lane < 8) ? red[lane] : 0.f;
#pragma unroll
        for (int o = 4; o >= 1; o >>= 1)
            v += __shfl_xor_sync(0xffffffffu, v, o);
    }
    return v;  // valid in thread 0
}

// ----------------------------------------------------------------------------
// Fused: input energy ||x[row,:]|| + bf16x3 split of x
// ----------------------------------------------------------------------------
__global__ void energy_split_kernel(const float* __restrict__ x,
                                    __nv_bfloat16* __restrict__ H,
                                    __nv_bfloat16* __restrict__ M,
                                    __nv_bfloat16* __restrict__ L) {
    int row = blockIdx.x;
    const float* xr = x + (size_t)row * CC;
    float s = 0.f;
    for (int c = threadIdx.x; c < CC; c += 256) {
        float v = xr[c];
        s += v * v;
        __nv_bfloat16 h = __float2bfloat16(v);
        float r = v - __bfloat162float(h);
        __nv_bfloat16 m = __float2bfloat16(r);
        r -= __bfloat162float(m);
        size_t o = (size_t)row * CC + c;
        H[o] = h; M[o] = m; L[o] = __float2bfloat16(r);
    }
    float tot = blockReduceSum256(s);
    if (threadIdx.x == 0) g_inE[row] = sqrtf(tot);
}

// ----------------------------------------------------------------------------
// Transpose + split W[k][n] -> WT{h,m,l}[n][k] bf16; grid.z selects weight
// ----------------------------------------------------------------------------
__global__ void wsplit4_kernel(const float* __restrict__ W0,
                               const float* __restrict__ W1,
                               const float* __restrict__ W2,
                               const float* __restrict__ W3,
                               __nv_bfloat16* __restrict__ WT) {
    __shared__ float t[32][33];
    const int wsel = blockIdx.z;
    const float* W = (wsel == 0) ? W0 : (wsel == 1) ? W1 : (wsel == 2) ? W2 : W3;
    __nv_bfloat16* H = WT + (size_t)(3 * wsel + 0) * CC * CC;
    __nv_bfloat16* M = WT + (size_t)(3 * wsel + 1) * CC * CC;
    __nv_bfloat16* L = WT + (size_t)(3 * wsel + 2) * CC * CC;
    int n0 = blockIdx.x << 5, k0 = blockIdx.y << 5;
    int tx = threadIdx.x, ty = threadIdx.y;
#pragma unroll
    for (int i = 0; i < 4; i++)
        t[ty + i * 8][tx] = W[(size_t)(k0 + ty + i * 8) * CC + n0 + tx];
    __syncthreads();
#pragma unroll
    for (int i = 0; i < 4; i++) {
        int n = n0 + ty + i * 8;
        float x = t[tx][ty + i * 8];
        __nv_bfloat16 h = __float2bfloat16(x);
        float r = x - __bfloat162float(h);
        __nv_bfloat16 m = __float2bfloat16(r);
        r -= __bfloat162float(m);
        size_t o = (size_t)n * CC + k0 + tx;
        H[o] = h; M[o] = m; L[o] = __float2bfloat16(r);
    }
}

// ----------------------------------------------------------------------------
// Tensor-core GEMM body via mma.sync bf16 splits.
// maxSum=3 -> 6 products (hh,hm,mh,mm,hl,lh), nSplit=3.
// maxSum=2 -> 3 products (hh,hm,mh), nSplit=2 (l-splits never touched).
// ----------------------------------------------------------------------------
#define ASTRIDE 40
#define SPLITB (2 * 128 * ASTRIDE * 2)   // bytes per split (both buffers)
#define BUFB   (128 * ASTRIDE * 2)       // bytes per buffer

__device__ __forceinline__ void tc_gemm_body(
    const __nv_bfloat16* __restrict__ Ah, const __nv_bfloat16* __restrict__ Am,
    const __nv_bfloat16* __restrict__ Al, const __nv_bfloat16* __restrict__ Bh,
    const __nv_bfloat16* __restrict__ Bm, const __nv_bfloat16* __restrict__ Bl,
    const float* __restrict__ bias, float* __restrict__ Co,
    __nv_bfloat16* smb, int m0, int n0, int nSplit, int maxSum) {
    __nv_bfloat16* sB = smb + 3 * 2 * 128 * ASTRIDE;
    const u32 sAu = smem_u32(smb);
    const u32 sBu = smem_u32(sB);

    const int tid = threadIdx.x;
    const int wid = tid >> 5, lane = tid & 31;
    const int wm = wid >> 2, wn = wid & 3;        // warps 2 (m) x 4 (n)

    const __nv_bfloat16* Asrc[3] = {Ah, Am, Al};
    const __nv_bfloat16* Bsrc[3] = {Bh, Bm, Bl};

    float acc[4][4][4];
#pragma unroll
    for (int i = 0; i < 4; i++)
#pragma unroll
        for (int j = 0; j < 4; j++)
#pragma unroll
            for (int r = 0; r < 4; r++) acc[i][j][r] = 0.f;

    const int ldr0 = tid >> 2, ldk0 = (tid & 3) << 3;
    const int ldr1 = (tid + 256) >> 2, ldk1 = ((tid + 256) & 3) << 3;

    const u32 aRowB = (u32)(((lane & 7) + ((lane >> 3) & 1) * 8) * (ASTRIDE * 2));
    const u32 aKB   = (u32)(((lane >> 4) & 1) * 16);
    const u32 bRowB = (u32)(((lane & 7) + ((lane >> 4) & 1) * 8) * (ASTRIDE * 2));
    const u32 bKB   = (u32)(((lane >> 3) & 1) * 16);

#define ISSUE_CHUNK(c, buf)                                                     \
    do {                                                                        \
        for (int t_ = 0; t_ < nSplit; t_++) {                                   \
            const __nv_bfloat16* ga = Asrc[t_] + (size_t)(m0 + ldr0) * CC +     \
                                      (c) * 32 + ldk0;                          \
            const __nv_bfloat16* ga1 = Asrc[t_] + (size_t)(m0 + ldr1) * CC +    \
                                       (c) * 32 + ldk1;                         \
            const __nv_bfloat16* gb = Bsrc[t_] + (size_t)(n0 + ldr0) * CC +     \
                                      (c) * 32 + ldk0;                          \
            const __nv_bfloat16* gb1 = Bsrc[t_] + (size_t)(n0 + ldr1) * CC +    \
                                       (c) * 32 + ldk1;                         \
            u32 d0 = (u32)(t_ * SPLITB + (buf) * BUFB +                         \
                           (ldr0 * ASTRIDE + ldk0) * 2);                        \
            u32 d1 = (u32)(t_ * SPLITB + (buf) * BUFB +                         \
                           (ldr1 * ASTRIDE + ldk1) * 2);                        \
            cpasync16(sAu + d0, ga);                                            \
            cpasync16(sAu + d1, ga1);                                           \
            cpasync16(sBu + d0, gb);                                            \
            cpasync16(sBu + d1, gb1);                                           \
        }                                                                       \
        cpcommit();                                                             \
    } while (0)

    ISSUE_CHUNK(0, 0);

    for (int c = 0; c < 32; c++) {
        const int buf = c & 1;
        cpwait0();
        __syncthreads();
        if (c + 1 < 32) ISSUE_CHUNK(c + 1, buf ^ 1);

#pragma unroll
        for (int ks = 0; ks < 2; ks++) {
            u32 af[3][4][4];
            for (int t = 0; t < nSplit; t++)
#pragma unroll
                for (int mi = 0; mi < 4; mi++) {
                    u32 addr = sAu + (u32)(t * SPLITB + buf * BUFB) +
                               (u32)((wm * 64 + mi * 16) * (ASTRIDE * 2)) +
                               aRowB + (u32)(ks * 32) + aKB;
                    ldsm_x4(af[t][mi][0], af[t][mi][1], af[t][mi][2],
                            af[t][mi][3], addr);
                }
            for (int bt = 0; bt < 3; bt++) {
                const int nA = maxSum - bt;
                if (nA <= 0) break;
                u32 bfr[2][4];
#pragma unroll
                for (int np = 0; np < 2; np++) {
                    u32 addr = sBu + (u32)(bt * SPLITB + buf * BUFB) +
                               (u32)((wn * 32 + np * 16) * (ASTRIDE * 2)) +
                               bRowB + (u32)(ks * 32) + bKB;
                    ldsm_x4(bfr[np][0], bfr[np][1], bfr[np][2], bfr[np][3],
                            addr);
                }
                for (int ia = 0; ia < nA; ia++) {
#pragma unroll
                    for (int mi = 0; mi < 4; mi++)
#pragma unroll
                        for (int ni = 0; ni < 4; ni++)
                            mma_bf16(acc[mi][ni], af[ia][mi],
                                     &bfr[ni >> 1][(ni & 1) * 2]);
                }
            }
        }
        __syncthreads();
    }

    const int grp = lane >> 2, qd = lane & 3;
#pragma unroll
    for (int mi = 0; mi < 4; mi++) {
#pragma unroll
        for (int ni = 0; ni < 4; ni++) {
            int row = m0 + wm * 64 + mi * 16 + grp;
            int col = n0 + wn * 32 + ni * 8 + qd * 2;
            float b0 = bias[col], b1 = bias[col + 1];
            float2 o0 = make_float2(acc[mi][ni][0] + b0, acc[mi][ni][1] + b1);
            float2 o1 = make_float2(acc[mi][ni][2] + b0, acc[mi][ni][3] + b1);
            *(float2*)&Co[(size_t)row * CC + col] = o0;
            *(float2*)&Co[(size_t)(row + 8) * CC + col] = o1;
        }
    }
}

// wo projection: linear in output -> 3-pass (hh,hm,mh) suffices
__global__ void __launch_bounds__(256, 1)
tc_gemm_kernel(const __nv_bfloat16* __restrict__ Ah,
               const __nv_bfloat16* __restrict__ Am,
               const __nv_bfloat16* __restrict__ Al,
               const __nv_bfloat16* __restrict__ Bh,
               const __nv_bfloat16* __restrict__ Bm,
               const __nv_bfloat16* __restrict__ Bl,
               const float* __restrict__ bias, float* __restrict__ Co) {
    extern __shared__ __align__(16) __nv_bfloat16 smb[];
    tc_gemm_body(Ah, Am, Al, Bh, Bm, Bl, bias, Co, smb,
                 blockIdx.y << 7, blockIdx.x << 7, 2, 2);
}

// batched QKV GEMM: z=0/1 (Q,K logit path) full 6 products; z=2 (V) 3 products
__global__ void __launch_bounds__(256, 1)
tc_gemm3_kernel(const __nv_bfloat16* __restrict__ Ah,
                const __nv_bfloat16* __restrict__ Am,
                const __nv_bfloat16* __restrict__ Al,
                const __nv_bfloat16* __restrict__ WT,
                const float* __restrict__ bq, const float* __restrict__ bk,
                const float* __restrict__ bv,
                float* __restrict__ Q, float* __restrict__ K,
                float* __restrict__ V) {
    extern __shared__ __align__(16) __nv_bfloat16 smb[];
    const int z = blockIdx.z;
    const __nv_bfloat16* B = WT + (size_t)(3 * z) * CC * CC;
    const float* bias = (z == 0) ? bq : (z == 1) ? bk : bv;
    float* Co = (z == 0) ? Q : (z == 1) ? K : V;
    const int full = (z < 2);
    tc_gemm_body(Ah, Am, Al, B, B + (size_t)CC * CC, B + (size_t)2 * CC * CC,
                 bias, Co, smb, blockIdx.y << 7, blockIdx.x << 7,
                 full ? 3 : 2, full ? 3 : 2);
}

// ----------------------------------------------------------------------------
// split-store helpers
// ----------------------------------------------------------------------------
__device__ __forceinline__ void writeSplit3(__nv_bfloat16* dst, const float* v) {
    u32 hw[8], mw[8], lw[8];
#pragma unroll
    for (int c = 0; c < 8; c++) {
        float a = v[2 * c], b = v[2 * c + 1];
        __nv_bfloat16 h0 = __float2bfloat16(a);
        __nv_bfloat16 h1 = __float2bfloat16(b);
        float r0 = a - __bfloat162float(h0);
        float r1 = b - __bfloat162float(h1);
        __nv_bfloat16 m0 = __float2bfloat16(r0);
        __nv_bfloat16 m1 = __float2bfloat16(r1);
        hw[c] = bpack(h0, h1);
        mw[c] = bpack(m0, m1);
        lw[c] = bpack(__float2bfloat16(r0 - __bfloat162float(m0)),
                      __float2bfloat16(r1 - __bfloat162float(m1)));
    }
    *(uint4*)(dst)              = make_uint4(hw[0], hw[1], hw[2], hw[3]);
    *(uint4*)(dst + 8)          = make_uint4(hw[4], hw[5], hw[6], hw[7]);
    *(uint4*)(dst + QSZ)        = make_uint4(mw[0], mw[1], mw[2], mw[3]);
    *(uint4*)(dst + QSZ + 8)    = make_uint4(mw[4], mw[5], mw[6], mw[7]);
    *(uint4*)(dst + 2 * QSZ)     = make_uint4(lw[0], lw[1], lw[2], lw[3]);
    *(uint4*)(dst + 2 * QSZ + 8) = make_uint4(lw[4], lw[5], lw[6], lw[7]);
}
__device__ __forceinline__ void writeSplit2(__nv_bfloat16* dst, const float* v) {
    u32 hw[8], mw[8];
#pragma unroll
    for (int c = 0; c < 8; c++) {
        float a = v[2 * c], b = v[2 * c + 1];
        __nv_bfloat16 h0 = __float2bfloat16(a);
        __nv_bfloat16 h1 = __float2bfloat16(b);
        hw[c] = bpack(h0, h1);
        mw[c] = bpack(__float2bfloat16(a - __bfloat162float(h0)),
                      __float2bfloat16(b - __bfloat162float(h1)));
    }
    *(uint4*)(dst)           = make_uint4(hw[0], hw[1], hw[2], hw[3]);
    *(uint4*)(dst + 8)       = make_uint4(hw[4], hw[5], hw[6], hw[7]);
    *(uint4*)(dst + QSZ)     = make_uint4(mw[0], mw[1], mw[2], mw[3]);
    *(uint4*)(dst + QSZ + 8) = make_uint4(mw[4], mw[5], mw[6], mw[7]);
}

// ----------------------------------------------------------------------------
// Batched FFT with real-pair packing; epilogue emits bf16 split arrays.
// ----------------------------------------------------------------------------
#define FSTR 9
__global__ void __launch_bounds__(256, 1)
fft_filter_kernel(const float* __restrict__ inQ, const float* __restrict__ inK,
                  const float* __restrict__ inV,
                  __nv_bfloat16* __restrict__ Qs,
                  __nv_bfloat16* __restrict__ Ks,
                  __nv_bfloat16* __restrict__ Vs,
                  const float* __restrict__ fd,
                  const float* __restrict__ alpha,
                  const float* __restrict__ fas) {
    extern __shared__ __align__(16) float2 sh[];   // sh[t*FSTR + c], c<8
    const int dg = blockIdx.x;          // 16-dim group 0..3
    const int which = blockIdx.y >> 4;  // 0=Q 1=K 2=V
    const int h = blockIdx.y & 15;
    const int b = blockIdx.z;
    const float* in = (which == 0) ? inQ : (which == 1) ? inK : inV;

    const int col0 = h * HDIM + dg * 16;
    const float* src = in + (size_t)b * TT * CC + col0;
    const int tid = threadIdx.x;

#pragma unroll
    for (int i = 0; i < 32; i++) {
        int e = tid + i * 256;
        int t = e >> 2, pr = e & 3;
        float4 v = *(const float4*)&src[(size_t)t * CC + pr * 4];
        unsigned r = __brev((unsigned)t) >> (32 - LOG2T);
        sh[r * FSTR + pr * 2]     = make_float2(v.x, v.y);
        sh[r * FSTR + pr * 2 + 1] = make_float2(v.z, v.w);
    }
    __syncthreads();

    for (int st = 1; st <= LOG2T; st++) {
        const int half = 1 << (st - 1);
        const float wstep = -6.283185307179586f / (float)(half * 2);
#pragma unroll
        for (int w = 0; w < 4; w++) {
            int idx = tid + w * 256;
            int pos = idx & (half - 1);
            int grp = idx >> (st - 1);
            int i0 = (grp << st) + pos;
            int i1 = i0 + half;
            float sn, cs;
            __sincosf(wstep * (float)pos, &sn, &cs);
            float2* p0 = &sh[i0 * FSTR];
            float2* p1 = &sh[i1 * FSTR];
#pragma unroll
            for (int c = 0; c < 8; c++) {
                float2 u = p0[c], v = p1[c];
                float tr = cs * v.x - sn * v.y;
                float ti = cs * v.y + sn * v.x;
                p0[c] = make_float2(u.x + tr, u.y + ti);
                p1[c] = make_float2(u.x - tr, u.y - ti);
            }
        }
        __syncthreads();
    }

    const float aal = alpha[0] + fas[0] * (fd[0] - 1.5f);
    const size_t obase = ((size_t)(b * HH + h)) * TT * HDIM + dg * 16;
#pragma unroll
    for (int i = 0; i < 8; i++) {
        int t = tid + i * 256;
        int tm = (TT - t) & (TT - 1);
        float fr = (float)(t < TT / 2 ? t : t - TT) * (1.0f / (float)TT);
        float phase = aal * atanf(logf(fabsf(fr) + 1e-10f));
        float sp, cp;
        sincosf(phase, &sp, &cp);
        const float2* pz = &sh[t * FSTR];
        const float2* pw = &sh[tm * FSTR];
        float re[16], im[16];
#pragma unroll
        for (int c = 0; c < 8; c++) {
            float2 Z = pz[c], W = pw[c];
            float Xr = 0.5f * (Z.x + W.x);
            float Xi = 0.5f * (Z.y - W.y);
            float Yr = 0.5f * (Z.y + W.y);
            float Yi = 0.5f * (W.x - Z.x);
            re[2 * c]     = Xr * cp - Xi * sp;
            im[2 * c]     = Xr * sp + Xi * cp;
            re[2 * c + 1] = Yr * cp - Yi * sp;
            im[2 * c + 1] = Yr * sp + Yi * cp;
        }
        size_t o = obase + (size_t)t * HDIM;
        if (which == 0) {
#pragma unroll
            for (int c = 0; c < 16; c++) { re[c] *= 0.125f; im[c] *= 0.125f; }
            writeSplit3(Qs + o, re);
            writeSplit3(Qs + 3 * QSZ + o, im);
        } else if (which == 1) {
#pragma unroll
            for (int c = 0; c < 16; c++) im[c] = -im[c];
            writeSplit3(Ks + o, re);
            writeSplit3(Ks + 3 * QSZ + o, im);
        } else {
            writeSplit2(Vs + o, re);
        }
    }
}

// ----------------------------------------------------------------------------
// Tensor-core flash attention per (b,h). t-tile 128, s-tile 64, 256 threads.
// S: 12 chained bf16 mma passes (Q fragments loaded once per ks); PV: 3.
// Epilogue emits O splits h/m only (wo GEMM is 3-pass).
// ----------------------------------------------------------------------------
#define KSTR 72
#define OQRH 0
#define OQRM 9216
#define OQRL 18432
#define OQIH 27648
#define OQIM 36864
#define OQIL 46080
#define OKRH 55296
#define OKRM 59904
#define OKRL 64512
#define OKIH 69120
#define OKIM 73728
#define OKIL 78336
#define OVH  82944
#define OVM  87552
#define OPH  92160
#define OPM  101376
#define ATTN_SMEM_BYTES (110592 * 2)   // 221184

__global__ void __launch_bounds__(256, 1)
attn_kernel(const __nv_bfloat16* __restrict__ Qs,
            const __nv_bfloat16* __restrict__ Ks,
            const __nv_bfloat16* __restrict__ Vs,
            __nv_bfloat16* __restrict__ Oh, __nv_bfloat16* __restrict__ Om) {
    extern __shared__ __align__(16) __nv_bfloat16 sm[];
    const u32 smU = smem_u32(sm);
    const int tid = threadIdx.x;
    const int wid = tid >> 5, lane = tid & 31;
    const int grp = lane >> 2, qd = lane & 3;
    const int t0 = blockIdx.x << 7;
    const int h = blockIdx.y, b = blockIdx.z;
    const size_t base = ((size_t)(b * HH + h)) * TT * HDIM;

    const u32 aOff = (u32)(((lane & 7) + ((lane >> 3) & 1) * 8) * (KSTR * 2) +
                           ((lane >> 4) & 1) * 16);
    const u32 bOff = (u32)(((lane & 7) + ((lane >> 4) & 1) * 8) * (KSTR * 2) +
                           ((lane >> 3) & 1) * 16);
    const u32 aWarp = (u32)(wid * 16 * (KSTR * 2));

    const int QO6[6] = {OQRH, OQRM, OQRL, OQIH, OQIM, OQIL};
    const int KO6[6] = {OKRH, OKRM, OKRL, OKIH, OKIM, OKIL};

    // ---- Q tile: cp.async all 6 splits ----
#pragma unroll
    for (int i = 0; i < 4; i++) {
        int e = tid + i * 256;
        int r = e >> 3, c8 = (e & 7) << 3;
        size_t g = base + (size_t)(t0 + r) * HDIM + c8;
        u32 d = (u32)((r * KSTR + c8) * 2);
#pragma unroll
        for (int s = 0; s < 6; s++)
            cpasync16(smU + (u32)(QO6[s] * 2) + d, Qs + (size_t)s * QSZ + g);
    }
    cpcommit();

    float m0 = -INFINITY, m1 = -INFINITY, l0 = 0.f, l1 = 0.f;
    float Oacc[8][4];
#pragma unroll
    for (int ni = 0; ni < 8; ni++)
#pragma unroll
        for (int j = 0; j < 4; j++) Oacc[ni][j] = 0.f;

    for (int s0 = 0; s0 < TT; s0 += 64) {
        __syncthreads();
#pragma unroll
        for (int i = 0; i < 2; i++) {
            int e = tid + i * 256;
            int r = e >> 3, c8 = (e & 7) << 3;
            size_t g = base + (size_t)(s0 + r) * HDIM + c8;
            u32 d = (u32)((r * KSTR + c8) * 2);
#pragma unroll
            for (int s = 0; s < 6; s++)
                cpasync16(smU + (u32)(KO6[s] * 2) + d, Ks + (size_t)s * QSZ + g);
        }
        cpcommit();
#pragma unroll
        for (int i = 0; i < 2; i++) {
            int e = tid + i * 256;
            int r = e >> 3, c8 = (e & 7) << 3;
            size_t g = base + (size_t)(s0 + r) * HDIM + c8;
            float4 vh4 = *(const float4*)(Vs + g);
            float4 vm4 = *(const float4*)(Vs + QSZ + g);
            const __nv_bfloat16* ph = (const __nv_bfloat16*)&vh4;
            const __nv_bfloat16* pm = (const __nv_bfloat16*)&vm4;
#pragma unroll
            for (int j = 0; j < 8; j++) {
                sm[OVH + (c8 + j) * KSTR + r] = ph[j];
                sm[OVM + (c8 + j) * KSTR + r] = pm[j];
            }
        }
        cpwait0();
        __syncthreads();

        // ---- S phase: Q fragments loaded once per ks, 12 mma passes ----
        float Sacc[8][4];
#pragma unroll
        for (int ni = 0; ni < 8; ni++)
#pragma unroll
            for (int j = 0; j < 4; j++) Sacc[ni][j] = 0.f;

#pragma unroll
        for (int ks = 0; ks < 4; ks++) {
            u32 af[6][4];
#pragma unroll
            for (int s = 0; s < 6; s++)
                ldsm_x4(af[s][0], af[s][1], af[s][2], af[s][3],
                        smU + (u32)(QO6[s] * 2) + aWarp + aOff + (u32)(ks * 32));
#pragma unroll
            for (int part = 0; part < 2; part++) {
#pragma unroll
                for (int bk = 0; bk < 3; bk++) {
                    const int nA = 3 - bk;
                    const u32 kb = smU + (u32)(KO6[part * 3 + bk] * 2);
                    u32 bfr[4][4];
#pragma unroll
                    for (int np = 0; np < 4; np++)
                        ldsm_x4(bfr[np][0], bfr[np][1], bfr[np][2], bfr[np][3],
                                kb + (u32)(np * 16 * (KSTR * 2)) + bOff +
                                    (u32)(ks * 32));
#pragma unroll
                    for (int ia = 0; ia < 3; ia++) {
                        if (ia >= nA) break;
#pragma unroll
                        for (int ni = 0; ni < 8; ni++)
                            mma_bf16(Sacc[ni], af[part * 3 + ia],
                                     &bfr[ni >> 1][(ni & 1) * 2]);
                    }
                }
            }
        }

        // ---- online softmax; P -> bf16x2 smem ----
        float mx0 = Sacc[0][0], mx1 = Sacc[0][2];
#pragma unroll
        for (int ni = 0; ni < 8; ni++) {
            mx0 = fmaxf(mx0, fmaxf(Sacc[ni][0], Sacc[ni][1]));
            mx1 = fmaxf(mx1, fmaxf(Sacc[ni][2], Sacc[ni][3]));
        }
        mx0 = fmaxf(mx0, __shfl_xor_sync(0xffffffffu, mx0, 1));
        mx0 = fmaxf(mx0, __shfl_xor_sync(0xffffffffu, mx0, 2));
        mx1 = fmaxf(mx1, __shfl_xor_sync(0xffffffffu, mx1, 1));
        mx1 = fmaxf(mx1, __shfl_xor_sync(0xffffffffu, mx1, 2));
        float mn0 = fmaxf(m0, mx0), mn1 = fmaxf(m1, mx1);
        float c0 = __expf(m0 - mn0), c1 = __expf(m1 - mn1);
        m0 = mn0; m1 = mn1;
        float ps0 = 0.f, ps1 = 0.f;
        const int r0 = wid * 16 + grp;
#pragma unroll
        for (int ni = 0; ni < 8; ni++) {
            float p00 = __expf(Sacc[ni][0] - mn0);
            float p01 = __expf(Sacc[ni][1] - mn0);
            float p10 = __expf(Sacc[ni][2] - mn1);
            float p11 = __expf(Sacc[ni][3] - mn1);
            ps0 += p00 + p01;
            ps1 += p10 + p11;
            int col = ni * 8 + qd * 2;
            __nv_bfloat16 h00 = __float2bfloat16(p00);
            __nv_bfloat16 h01 = __float2bfloat16(p01);
            __nv_bfloat16 h10 = __float2bfloat16(p10);
            __nv_bfloat16 h11 = __float2bfloat16(p11);
            st2h(sm + OPH + r0 * KSTR + col, h00, h01);
            st2h(sm + OPH + (r0 + 8) * KSTR + col, h10, h11);
            st2h(sm + OPM + r0 * KSTR + col,
                 __float2bfloat16(p00 - __bfloat162float(h00)),
                 __float2bfloat16(p01 - __bfloat162float(h01)));
            st2h(sm + OPM + (r0 + 8) * KSTR + col,
                 __float2bfloat16(p10 - __bfloat162float(h10)),
                 __float2bfloat16(p11 - __bfloat162float(h11)));
        }
        ps0 += __shfl_xor_sync(0xffffffffu, ps0, 1);
        ps0 += __shfl_xor_sync(0xffffffffu, ps0, 2);
        ps1 += __shfl_xor_sync(0xffffffffu, ps1, 1);
        ps1 += __shfl_xor_sync(0xffffffffu, ps1, 2);
        l0 = l0 * c0 + ps0;
        l1 = l1 * c1 + ps1;
#pragma unroll
        for (int ni = 0; ni < 8; ni++) {
            Oacc[ni][0] *= c0; Oacc[ni][1] *= c0;
            Oacc[ni][2] *= c1; Oacc[ni][3] *= c1;
        }
        __syncwarp();

        // ---- PV: O += P @ V (hh, hm, mh) ----
#pragma unroll
        for (int vp = 0; vp < 3; vp++) {
            const u32 pb = smU + (u32)(((vp == 2) ? OPM : OPH) * 2) + aWarp;
            const u32 vb = smU + (u32)(((vp == 1) ? OVM : OVH) * 2);
#pragma unroll
            for (int ks = 0; ks < 4; ks++) {
                u32 bfr[4][4];
#pragma unroll
                for (int np = 0; np < 4; np++)
                    ldsm_x4(bfr[np][0], bfr[np][1], bfr[np][2], bfr[np][3],
                            vb + (u32)(np * 16 * (KSTR * 2)) + bOff +
                                (u32)(ks * 32));
                u32 af[4];
                ldsm_x4(af[0], af[1], af[2], af[3], pb + aOff + (u32)(ks * 32));
#pragma unroll
                for (int ni = 0; ni < 8; ni++)
                    mma_bf16(Oacc[ni], af, &bfr[ni >> 1][(ni & 1) * 2]);
            }
        }
    }

    // ---- epilogue: normalize, split bf16 h/m, write [b, t, h*64+d] ----
    float il0 = 1.f / l0, il1 = 1.f / l1;
    const int r0e = wid * 16 + grp;
#pragma unroll
    for (int ni = 0; ni < 8; ni++) {
        int col = h * HDIM + ni * 8 + qd * 2;
#pragma unroll
        for (int rr = 0; rr < 2; rr++) {
            int row = r0e + rr * 8;
            float sc = rr ? il1 : il0;
            float v0 = Oacc[ni][rr * 2 + 0] * sc;
            float v1 = Oacc[ni][rr * 2 + 1] * sc;
            size_t off = ((size_t)(b * TT + t0 + row)) * CC + col;
            __nv_bfloat16 h0 = __float2bfloat16(v0);
            __nv_bfloat16 h1 = __float2bfloat16(v1);
            st2h(&Oh[off], h0, h1);
            st2h(&Om[off], __float2bfloat16(v0 - __bfloat162float(h0)),
                 __float2bfloat16(v1 - __bfloat162float(h1)));
        }
    }
}

// ----------------------------------------------------------------------------
// Final energy ratio
// ----------------------------------------------------------------------------
__global__ void finalize_kernel(const float* __restrict__ Y,
                                const float* __restrict__ enorm,
                                float* __restrict__ out) {
    int row = blockIdx.x;
    const float* yr = Y + (size_t)row * CC;
    float s = 0.f;
    for (int c = threadIdx.x; c < CC; c += 256) {
        float v = yr[c];
        s += v * v;
    }
    float tot = blockReduceSum256(s);
    __shared__ float ratio;
    if (threadIdx.x == 0)
        ratio = g_inE[row] / (sqrtf(tot) + 1e-8f) * enorm[0];
    __syncthreads();
    for (int c = threadIdx.x; c < CC; c += 256)
        out[(size_t)row * CC + c] = yr[c] * ratio;
}

// ----------------------------------------------------------------------------
// Launch
// ----------------------------------------------------------------------------
extern "C" void kernel_launch(void* const* d_in, const int* in_sizes, int n_in,
                              void* d_out, int out_size) {
    const float* x      = (const float*)d_in[0];
    const float* fd     = (const float*)d_in[1];
    const float* wq     = (const float*)d_in[2];
    const float* bq     = (const float*)d_in[3];
    const float* wk     = (const float*)d_in[4];
    const float* bk     = (const float*)d_in[5];
    const float* wv     = (const float*)d_in[6];
    const float* bv     = (const float*)d_in[7];
    const float* wo     = (const float*)d_in[8];
    const float* bo     = (const float*)d_in[9];
    const float* alpha  = (const float*)d_in[10];
    const float* fas    = (const float*)d_in[11];
    const float* enorm  = (const float*)d_in[12];
    float* out = (float*)d_out;

    float *q, *k, *v, *y;
    __nv_bfloat16 *xh, *xm, *xl, *wt, *qs, *ks, *vs;
    cudaGetSymbolAddress((void**)&q,  g_q);
    cudaGetSymbolAddress((void**)&k,  g_k);
    cudaGetSymbolAddress((void**)&v,  g_v);
    cudaGetSymbolAddress((void**)&y,  g_y);
    cudaGetSymbolAddress((void**)&xh, g_xh);
    cudaGetSymbolAddress((void**)&xm, g_xm);
    cudaGetSymbolAddress((void**)&xl, g_xl);
    cudaGetSymbolAddress((void**)&wt, g_wt);
    cudaGetSymbolAddress((void**)&qs, g_qs);
    cudaGetSymbolAddress((void**)&ks, g_ks);
    cudaGetSymbolAddress((void**)&vs, g_vs);
    const size_t WSZ = (size_t)CC * CC;

    // fused: input energies + x split
    energy_split_kernel<<<BT, 256>>>(x, xh, xm, xl);

    // weight transpose+split (all 4 weights, one launch)
    dim3 wg(32, 32, 4), wb(32, 8);
    wsplit4_kernel<<<wg, wb>>>(wq, wk, wv, wo, wt);

    // QKV projections on tensor cores
    static const int kTcSmem = 2 * 3 * 2 * 128 * ASTRIDE * (int)sizeof(__nv_bfloat16);
    cudaFuncSetAttribute(tc_gemm3_kernel,
                         cudaFuncAttributeMaxDynamicSharedMemorySize, kTcSmem);
    cudaFuncSetAttribute(tc_gemm_kernel,
                         cudaFuncAttributeMaxDynamicSharedMemorySize, kTcSmem);
    dim3 gg3(CC / 128, BT / 128, 3);
    tc_gemm3_kernel<<<gg3, 256, kTcSmem>>>(xh, xm, xl, wt, bq, bk, bv, q, k, v);

    // FFT + spectral filter -> bf16 split operands for attention
    static const int kFftSmem = TT * FSTR * (int)sizeof(float2);
    cudaFuncSetAttribute(fft_filter_kernel,
                         cudaFuncAttributeMaxDynamicSharedMemorySize, kFftSmem);
    dim3 gf(HDIM / 16, HH * 3, BB);
    fft_filter_kernel<<<gf, 256, kFftSmem>>>(q, k, v, qs, ks, vs,
                                             fd, alpha, fas);

    // tensor-core attention (writes O splits h/m into xh/xm)
    cudaFuncSetAttribute(attn_kernel, cudaFuncAttributeMaxDynamicSharedMemorySize,
                         ATTN_SMEM_BYTES);
    dim3 ga(TT / 128, HH, BB);
    attn_kernel<<<ga, 256, ATTN_SMEM_BYTES>>>(qs, ks, vs, xh, xm);

    // output projection (3-pass: hh, hm, mh)
    dim3 gg(CC / 128, BT / 128);
    tc_gemm_kernel<<<gg, 256, kTcSmem>>>(xh, xm, xl,
                                         wt + 9 * WSZ, wt + 10 * WSZ, wt + 11 * WSZ,
                                         bo, y);

    // energy-ratio epilogue
    finalize_kernel<<<BT, 256>>>(y, enorm, out);
}

// round 17
// speedup vs baseline: 2.5649x; 1.3418x over previous
#include <cuda_runtime.h>
#include <cuda_bf16.h>
#include <math.h>
#include <cstdint>

// Problem constants
#define BB 2
#define TT 2048
#define CC 1024
#define HH 16
#define HDIM 64
#define BT (BB * TT)      // 4096 rows
#define LOG2T 11

typedef unsigned long long u64;
typedef unsigned int u32;

// ---------------------------------------------------------------------------
// helpers
// ---------------------------------------------------------------------------
__device__ __forceinline__ u32 smem_u32(const void* p) {
    u32 a;
    asm("{ .reg .u64 t; cvta.to.shared.u64 t, %1; cvt.u32.u64 %0, t; }"
        : "=r"(a) : "l"(p));
    return a;
}
__device__ __forceinline__ void cpasync16(u32 smem_dst, const void* gptr) {
    asm volatile("cp.async.ca.shared.global [%0], [%1], 16;"
                 :: "r"(smem_dst), "l"(gptr));
}
__device__ __forceinline__ void cpcommit() {
    asm volatile("cp.async.commit_group;");
}
__device__ __forceinline__ void cpwait0() {
    asm volatile("cp.async.wait_group 0;");
}
__device__ __forceinline__ void ldsm_x4(u32& r0, u32& r1, u32& r2, u32& r3,
                                        u32 addr) {
    asm volatile("ldmatrix.sync.aligned.m8n8.x4.shared.b16 {%0,%1,%2,%3}, [%4];"
                 : "=r"(r0), "=r"(r1), "=r"(r2), "=r"(r3) : "r"(addr));
}
__device__ __forceinline__ void mma_bf16(float* c, const u32* a, const u32* b) {
    asm volatile(
        "mma.sync.aligned.m16n8k16.row.col.f32.bf16.bf16.f32 "
        "{%0,%1,%2,%3}, {%4,%5,%6,%7}, {%8,%9}, {%0,%1,%2,%3};"
        : "+f"(c[0]), "+f"(c[1]), "+f"(c[2]), "+f"(c[3])
        : "r"(a[0]), "r"(a[1]), "r"(a[2]), "r"(a[3]), "r"(b[0]), "r"(b[1]));
}
__device__ __forceinline__ void st2h(__nv_bfloat16* p, __nv_bfloat16 a,
                                     __nv_bfloat16 b) {
    __nv_bfloat162 t;
    t.x = a; t.y = b;
    *(__nv_bfloat162*)p = t;
}
__device__ __forceinline__ u32 bpack(__nv_bfloat16 a, __nv_bfloat16 b) {
    __nv_bfloat162 t;
    t.x = a; t.y = b;
    return *(u32*)&t;
}

// ----------------------------------------------------------------------------
// Device scratch (static; no allocations allowed)
// ----------------------------------------------------------------------------
static __device__ float g_q[BT * CC];
static __device__ float g_k[BT * CC];
static __device__ float g_v[BT * CC];
static __device__ float g_y[BT * CC];
static __device__ float g_inE[BT];
static __device__ __nv_bfloat16 g_xh[BT * CC];
static __device__ __nv_bfloat16 g_xm[BT * CC];
static __device__ __nv_bfloat16 g_wt[12 * CC * CC];   // 4 weights x {h,m,l}, [N][K]
static __device__ __nv_bfloat16 g_qs[4 * BT * CC];    // rh, rm, ih, im (x1/8)
static __device__ __nv_bfloat16 g_ks[4 * BT * CC];    // rh, rm, -ih, -im
static __device__ __nv_bfloat16 g_vs[2 * BT * CC];    // h, m
#define QSZ ((size_t)BT * CC)

// ----------------------------------------------------------------------------
// Reductions
// ----------------------------------------------------------------------------
__device__ __forceinline__ float blockReduceSum256(float v) {
    __shared__ float red[8];
    int lane = threadIdx.x & 31;
    int w = threadIdx.x >> 5;
#pragma unroll
    for (int o = 16; o >= 1; o >>= 1)
        v += __shfl_xor_sync(0xffffffffu, v, o);
    if (lane == 0) red[w] = v;
    __syncthreads();
    if (w == 0) {
        v = (lane < 8) ? red[lane] : 0.f;
#pragma unroll
        for (int o = 4; o >= 1; o >>= 1)
            v += __shfl_xor_sync(0xffffffffu, v, o);
    }
    return v;  // valid in thread 0
}

// ----------------------------------------------------------------------------
// Fused: input energy ||x[row,:]|| + bf16 (h,m) split of x
// ----------------------------------------------------------------------------
__global__ void energy_split_kernel(const float* __restrict__ x,
                                    __nv_bfloat16* __restrict__ H,
                                    __nv_bfloat16* __restrict__ M) {
    int row = blockIdx.x;
    const float* xr = x + (size_t)row * CC;
    float s = 0.f;
    for (int c = threadIdx.x; c < CC; c += 256) {
        float v = xr[c];
        s += v * v;
        __nv_bfloat16 h = __float2bfloat16(v);
        float r = v - __bfloat162float(h);
        size_t o = (size_t)row * CC + c;
        H[o] = h; M[o] = __float2bfloat16(r);
    }
    float tot = blockReduceSum256(s);
    if (threadIdx.x == 0) g_inE[row] = sqrtf(tot);
}

// ----------------------------------------------------------------------------
// Transpose + split W[k][n] -> WT{h,m}[n][k] bf16; grid.z selects weight
// ----------------------------------------------------------------------------
__global__ void wsplit4_kernel(const float* __restrict__ W0,
                               const float* __restrict__ W1,
                               const float* __restrict__ W2,
                               const float* __restrict__ W3,
                               __nv_bfloat16* __restrict__ WT) {
    __shared__ float t[32][33];
    const int wsel = blockIdx.z;
    const float* W = (wsel == 0) ? W0 : (wsel == 1) ? W1 : (wsel == 2) ? W2 : W3;
    __nv_bfloat16* H = WT + (size_t)(3 * wsel + 0) * CC * CC;
    __nv_bfloat16* M = WT + (size_t)(3 * wsel + 1) * CC * CC;
    int n0 = blockIdx.x << 5, k0 = blockIdx.y << 5;
    int tx = threadIdx.x, ty = threadIdx.y;
#pragma unroll
    for (int i = 0; i < 4; i++)
        t[ty + i * 8][tx] = W[(size_t)(k0 + ty + i * 8) * CC + n0 + tx];
    __syncthreads();
#pragma unroll
    for (int i = 0; i < 4; i++) {
        int n = n0 + ty + i * 8;
        float x = t[tx][ty + i * 8];
        __nv_bfloat16 h = __float2bfloat16(x);
        float r = x - __bfloat162float(h);
        size_t o = (size_t)n * CC + k0 + tx;
        H[o] = h; M[o] = __float2bfloat16(r);
    }
}

// ----------------------------------------------------------------------------
// Tensor-core GEMM body via mma.sync bf16 2-split, 3 products (hh, hm, mh).
// ----------------------------------------------------------------------------
#define ASTRIDE 40
#define SPLITB (2 * 128 * ASTRIDE * 2)   // bytes per split (both buffers)
#define BUFB   (128 * ASTRIDE * 2)       // bytes per buffer

__device__ __forceinline__ void tc_gemm_body(
    const __nv_bfloat16* __restrict__ Ah, const __nv_bfloat16* __restrict__ Am,
    const __nv_bfloat16* __restrict__ Bh, const __nv_bfloat16* __restrict__ Bm,
    const float* __restrict__ bias, float* __restrict__ Co,
    __nv_bfloat16* smb, int m0, int n0) {
    __nv_bfloat16* sB = smb + 2 * 2 * 128 * ASTRIDE;
    const u32 sAu = smem_u32(smb);
    const u32 sBu = smem_u32(sB);

    const int tid = threadIdx.x;
    const int wid = tid >> 5, lane = tid & 31;
    const int wm = wid >> 2, wn = wid & 3;        // warps 2 (m) x 4 (n)

    const __nv_bfloat16* Asrc[2] = {Ah, Am};
    const __nv_bfloat16* Bsrc[2] = {Bh, Bm};

    float acc[4][4][4];
#pragma unroll
    for (int i = 0; i < 4; i++)
#pragma unroll
        for (int j = 0; j < 4; j++)
#pragma unroll
            for (int r = 0; r < 4; r++) acc[i][j][r] = 0.f;

    const int ldr0 = tid >> 2, ldk0 = (tid & 3) << 3;
    const int ldr1 = (tid + 256) >> 2, ldk1 = ((tid + 256) & 3) << 3;

    const u32 aRowB = (u32)(((lane & 7) + ((lane >> 3) & 1) * 8) * (ASTRIDE * 2));
    const u32 aKB   = (u32)(((lane >> 4) & 1) * 16);
    const u32 bRowB = (u32)(((lane & 7) + ((lane >> 4) & 1) * 8) * (ASTRIDE * 2));
    const u32 bKB   = (u32)(((lane >> 3) & 1) * 16);

#define ISSUE_CHUNK(c, buf)                                                     \
    do {                                                                        \
        _Pragma("unroll")                                                       \
        for (int t_ = 0; t_ < 2; t_++) {                                        \
            const __nv_bfloat16* ga = Asrc[t_] + (size_t)(m0 + ldr0) * CC +     \
                                      (c) * 32 + ldk0;                          \
            const __nv_bfloat16* ga1 = Asrc[t_] + (size_t)(m0 + ldr1) * CC +    \
                                       (c) * 32 + ldk1;                         \
            const __nv_bfloat16* gb = Bsrc[t_] + (size_t)(n0 + ldr0) * CC +     \
                                      (c) * 32 + ldk0;                          \
            const __nv_bfloat16* gb1 = Bsrc[t_] + (size_t)(n0 + ldr1) * CC +    \
                                       (c) * 32 + ldk1;                         \
            u32 d0 = (u32)(t_ * SPLITB + (buf) * BUFB +                         \
                           (ldr0 * ASTRIDE + ldk0) * 2);                        \
            u32 d1 = (u32)(t_ * SPLITB + (buf) * BUFB +                         \
                           (ldr1 * ASTRIDE + ldk1) * 2);                        \
            cpasync16(sAu + d0, ga);                                            \
            cpasync16(sAu + d1, ga1);                                           \
            cpasync16(sBu + d0, gb);                                            \
            cpasync16(sBu + d1, gb1);                                           \
        }                                                                       \
        cpcommit();                                                             \
    } while (0)

    ISSUE_CHUNK(0, 0);

    for (int c = 0; c < 32; c++) {
        const int buf = c & 1;
        cpwait0();
        __syncthreads();
        if (c + 1 < 32) ISSUE_CHUNK(c + 1, buf ^ 1);

#pragma unroll
        for (int ks = 0; ks < 2; ks++) {
            u32 af[2][4][4];
#pragma unroll
            for (int t = 0; t < 2; t++)
#pragma unroll
                for (int mi = 0; mi < 4; mi++) {
                    u32 addr = sAu + (u32)(t * SPLITB + buf * BUFB) +
                               (u32)((wm * 64 + mi * 16) * (ASTRIDE * 2)) +
                               aRowB + (u32)(ks * 32) + aKB;
                    ldsm_x4(af[t][mi][0], af[t][mi][1], af[t][mi][2],
                            af[t][mi][3], addr);
                }
#pragma unroll
            for (int bt = 0; bt < 2; bt++) {
                const int nA = 2 - bt;
                u32 bfr[2][4];
#pragma unroll
                for (int np = 0; np < 2; np++) {
                    u32 addr = sBu + (u32)(bt * SPLITB + buf * BUFB) +
                               (u32)((wn * 32 + np * 16) * (ASTRIDE * 2)) +
                               bRowB + (u32)(ks * 32) + bKB;
                    ldsm_x4(bfr[np][0], bfr[np][1], bfr[np][2], bfr[np][3],
                            addr);
                }
#pragma unroll
                for (int ia = 0; ia < 2; ia++) {
                    if (ia >= nA) break;
#pragma unroll
                    for (int mi = 0; mi < 4; mi++)
#pragma unroll
                        for (int ni = 0; ni < 4; ni++)
                            mma_bf16(acc[mi][ni], af[ia][mi],
                                     &bfr[ni >> 1][(ni & 1) * 2]);
                }
            }
        }
        __syncthreads();
    }

    const int grp = lane >> 2, qd = lane & 3;
#pragma unroll
    for (int mi = 0; mi < 4; mi++) {
#pragma unroll
        for (int ni = 0; ni < 4; ni++) {
            int row = m0 + wm * 64 + mi * 16 + grp;
            int col = n0 + wn * 32 + ni * 8 + qd * 2;
            float b0 = bias[col], b1 = bias[col + 1];
            float2 o0 = make_float2(acc[mi][ni][0] + b0, acc[mi][ni][1] + b1);
            float2 o1 = make_float2(acc[mi][ni][2] + b0, acc[mi][ni][3] + b1);
            *(float2*)&Co[(size_t)row * CC + col] = o0;
            *(float2*)&Co[(size_t)(row + 8) * CC + col] = o1;
        }
    }
}

// wo projection
__global__ void __launch_bounds__(256, 1)
tc_gemm_kernel(const __nv_bfloat16* __restrict__ Ah,
               const __nv_bfloat16* __restrict__ Am,
               const __nv_bfloat16* __restrict__ Bh,
               const __nv_bfloat16* __restrict__ Bm,
               const float* __restrict__ bias, float* __restrict__ Co) {
    extern __shared__ __align__(16) __nv_bfloat16 smb[];
    tc_gemm_body(Ah, Am, Bh, Bm, bias, Co, smb,
                 blockIdx.y << 7, blockIdx.x << 7);
}

// batched QKV GEMM
__global__ void __launch_bounds__(256, 1)
tc_gemm3_kernel(const __nv_bfloat16* __restrict__ Ah,
                const __nv_bfloat16* __restrict__ Am,
                const __nv_bfloat16* __restrict__ WT,
                const float* __restrict__ bq, const float* __restrict__ bk,
                const float* __restrict__ bv,
                float* __restrict__ Q, float* __restrict__ K,
                float* __restrict__ V) {
    extern __shared__ __align__(16) __nv_bfloat16 smb[];
    const int z = blockIdx.z;
    const __nv_bfloat16* B = WT + (size_t)(3 * z) * CC * CC;
    const float* bias = (z == 0) ? bq : (z == 1) ? bk : bv;
    float* Co = (z == 0) ? Q : (z == 1) ? K : V;
    tc_gemm_body(Ah, Am, B, B + (size_t)CC * CC, bias, Co, smb,
                 blockIdx.y << 7, blockIdx.x << 7);
}

// ----------------------------------------------------------------------------
// split-store helper (h,m)
// ----------------------------------------------------------------------------
__device__ __forceinline__ void writeSplit2(__nv_bfloat16* dst, const float* v) {
    u32 hw[8], mw[8];
#pragma unroll
    for (int c = 0; c < 8; c++) {
        float a = v[2 * c], b = v[2 * c + 1];
        __nv_bfloat16 h0 = __float2bfloat16(a);
        __nv_bfloat16 h1 = __float2bfloat16(b);
        hw[c] = bpack(h0, h1);
        mw[c] = bpack(__float2bfloat16(a - __bfloat162float(h0)),
                      __float2bfloat16(b - __bfloat162float(h1)));
    }
    *(uint4*)(dst)           = make_uint4(hw[0], hw[1], hw[2], hw[3]);
    *(uint4*)(dst + 8)       = make_uint4(hw[4], hw[5], hw[6], hw[7]);
    *(uint4*)(dst + QSZ)     = make_uint4(mw[0], mw[1], mw[2], mw[3]);
    *(uint4*)(dst + QSZ + 8) = make_uint4(mw[4], mw[5], mw[6], mw[7]);
}

// ----------------------------------------------------------------------------
// Batched FFT with real-pair packing; emits (h,m) bf16 splits:
// Q -> g_qs {rh, rm, ih, im} (x1/8), K -> g_ks {rh, rm, -ih, -im}, V -> {h,m}.
// ----------------------------------------------------------------------------
#define FSTR 9
__global__ void __launch_bounds__(256, 1)
fft_filter_kernel(const float* __restrict__ inQ, const float* __restrict__ inK,
                  const float* __restrict__ inV,
                  __nv_bfloat16* __restrict__ Qs,
                  __nv_bfloat16* __restrict__ Ks,
                  __nv_bfloat16* __restrict__ Vs,
                  const float* __restrict__ fd,
                  const float* __restrict__ alpha,
                  const float* __restrict__ fas) {
    extern __shared__ __align__(16) float2 sh[];   // sh[t*FSTR + c], c<8
    const int dg = blockIdx.x;          // 16-dim group 0..3
    const int which = blockIdx.y >> 4;  // 0=Q 1=K 2=V
    const int h = blockIdx.y & 15;
    const int b = blockIdx.z;
    const float* in = (which == 0) ? inQ : (which == 1) ? inK : inV;

    const int col0 = h * HDIM + dg * 16;
    const float* src = in + (size_t)b * TT * CC + col0;
    const int tid = threadIdx.x;

#pragma unroll
    for (int i = 0; i < 32; i++) {
        int e = tid + i * 256;
        int t = e >> 2, pr = e & 3;
        float4 v = *(const float4*)&src[(size_t)t * CC + pr * 4];
        unsigned r = __brev((unsigned)t) >> (32 - LOG2T);
        sh[r * FSTR + pr * 2]     = make_float2(v.x, v.y);
        sh[r * FSTR + pr * 2 + 1] = make_float2(v.z, v.w);
    }
    __syncthreads();

    for (int st = 1; st <= LOG2T; st++) {
        const int half = 1 << (st - 1);
        const float wstep = -6.283185307179586f / (float)(half * 2);
#pragma unroll
        for (int w = 0; w < 4; w++) {
            int idx = tid + w * 256;
            int pos = idx & (half - 1);
            int grp = idx >> (st - 1);
            int i0 = (grp << st) + pos;
            int i1 = i0 + half;
            float sn, cs;
            __sincosf(wstep * (float)pos, &sn, &cs);
            float2* p0 = &sh[i0 * FSTR];
            float2* p1 = &sh[i1 * FSTR];
#pragma unroll
            for (int c = 0; c < 8; c++) {
                float2 u = p0[c], v = p1[c];
                float tr = cs * v.x - sn * v.y;
                float ti = cs * v.y + sn * v.x;
                p0[c] = make_float2(u.x + tr, u.y + ti);
                p1[c] = make_float2(u.x - tr, u.y - ti);
            }
        }
        __syncthreads();
    }

    const float aal = alpha[0] + fas[0] * (fd[0] - 1.5f);
    const size_t obase = ((size_t)(b * HH + h)) * TT * HDIM + dg * 16;
#pragma unroll
    for (int i = 0; i < 8; i++) {
        int t = tid + i * 256;
        int tm = (TT - t) & (TT - 1);
        float fr = (float)(t < TT / 2 ? t : t - TT) * (1.0f / (float)TT);
        float phase = aal * atanf(logf(fabsf(fr) + 1e-10f));
        float sp, cp;
        sincosf(phase, &sp, &cp);
        const float2* pz = &sh[t * FSTR];
        const float2* pw = &sh[tm * FSTR];
        float re[16], im[16];
#pragma unroll
        for (int c = 0; c < 8; c++) {
            float2 Z = pz[c], W = pw[c];
            float Xr = 0.5f * (Z.x + W.x);
            float Xi = 0.5f * (Z.y - W.y);
            float Yr = 0.5f * (Z.y + W.y);
            float Yi = 0.5f * (W.x - Z.x);
            re[2 * c]     = Xr * cp - Xi * sp;
            im[2 * c]     = Xr * sp + Xi * cp;
            re[2 * c + 1] = Yr * cp - Yi * sp;
            im[2 * c + 1] = Yr * sp + Yi * cp;
        }
        size_t o = obase + (size_t)t * HDIM;
        if (which == 0) {
#pragma unroll
            for (int c = 0; c < 16; c++) { re[c] *= 0.125f; im[c] *= 0.125f; }
            writeSplit2(Qs + o, re);
            writeSplit2(Qs + 2 * QSZ + o, im);
        } else if (which == 1) {
#pragma unroll
            for (int c = 0; c < 16; c++) im[c] = -im[c];
            writeSplit2(Ks + o, re);
            writeSplit2(Ks + 2 * QSZ + o, im);
        } else {
            writeSplit2(Vs + o, re);
        }
    }
}

// ----------------------------------------------------------------------------
// Tensor-core flash attention per (b,h). t-tile 128, s-tile 64, 256 threads.
// S: 6 chained bf16 mma passes (2 parts x {hh, mh, hm}); PV: 3 passes.
// ----------------------------------------------------------------------------
#define KSTR 72
#define OQRH 0
#define OQRM 9216
#define OQIH 18432
#define OQIM 27648
#define OKRH 36864
#define OKRM 41472
#define OKIH 46080
#define OKIM 50688
#define OVH  55296
#define OVM  59904
#define OPH  64512
#define OPM  73728
#define ATTN_SMEM_BYTES (82944 * 2)   // 165888

__global__ void __launch_bounds__(256, 1)
attn_kernel(const __nv_bfloat16* __restrict__ Qs,
            const __nv_bfloat16* __restrict__ Ks,
            const __nv_bfloat16* __restrict__ Vs,
            __nv_bfloat16* __restrict__ Oh, __nv_bfloat16* __restrict__ Om) {
    extern __shared__ __align__(16) __nv_bfloat16 sm[];
    const u32 smU = smem_u32(sm);
    const int tid = threadIdx.x;
    const int wid = tid >> 5, lane = tid & 31;
    const int grp = lane >> 2, qd = lane & 3;
    const int t0 = blockIdx.x << 7;
    const int h = blockIdx.y, b = blockIdx.z;
    const size_t base = ((size_t)(b * HH + h)) * TT * HDIM;

    const u32 aOff = (u32)(((lane & 7) + ((lane >> 3) & 1) * 8) * (KSTR * 2) +
                           ((lane >> 4) & 1) * 16);
    const u32 bOff = (u32)(((lane & 7) + ((lane >> 4) & 1) * 8) * (KSTR * 2) +
                           ((lane >> 3) & 1) * 16);
    const u32 aWarp = (u32)(wid * 16 * (KSTR * 2));

    const int QO4[4] = {OQRH, OQRM, OQIH, OQIM};
    const int KO4[4] = {OKRH, OKRM, OKIH, OKIM};

    // ---- Q tile: cp.async 4 splits ----
#pragma unroll
    for (int i = 0; i < 4; i++) {
        int e = tid + i * 256;
        int r = e >> 3, c8 = (e & 7) << 3;
        size_t g = base + (size_t)(t0 + r) * HDIM + c8;
        u32 d = (u32)((r * KSTR + c8) * 2);
#pragma unroll
        for (int s = 0; s < 4; s++)
            cpasync16(smU + (u32)(QO4[s] * 2) + d, Qs + (size_t)s * QSZ + g);
    }
    cpcommit();

    float m0 = -INFINITY, m1 = -INFINITY, l0 = 0.f, l1 = 0.f;
    float Oacc[8][4];
#pragma unroll
    for (int ni = 0; ni < 8; ni++)
#pragma unroll
        for (int j = 0; j < 4; j++) Oacc[ni][j] = 0.f;

    for (int s0 = 0; s0 < TT; s0 += 64) {
        __syncthreads();
#pragma unroll
        for (int i = 0; i < 2; i++) {
            int e = tid + i * 256;
            int r = e >> 3, c8 = (e & 7) << 3;
            size_t g = base + (size_t)(s0 + r) * HDIM + c8;
            u32 d = (u32)((r * KSTR + c8) * 2);
#pragma unroll
            for (int s = 0; s < 4; s++)
                cpasync16(smU + (u32)(KO4[s] * 2) + d, Ks + (size_t)s * QSZ + g);
        }
        cpcommit();
#pragma unroll
        for (int i = 0; i < 2; i++) {
            int e = tid + i * 256;
            int r = e >> 3, c8 = (e & 7) << 3;
            size_t g = base + (size_t)(s0 + r) * HDIM + c8;
            float4 vh4 = *(const float4*)(Vs + g);
            float4 vm4 = *(const float4*)(Vs + QSZ + g);
            const __nv_bfloat16* ph = (const __nv_bfloat16*)&vh4;
            const __nv_bfloat16* pm = (const __nv_bfloat16*)&vm4;
#pragma unroll
            for (int j = 0; j < 8; j++) {
                sm[OVH + (c8 + j) * KSTR + r] = ph[j];
                sm[OVM + (c8 + j) * KSTR + r] = pm[j];
            }
        }
        cpwait0();
        __syncthreads();

        // ---- S phase: 6 mma passes (per part: hh, mh, hm) ----
        float Sacc[8][4];
#pragma unroll
        for (int ni = 0; ni < 8; ni++)
#pragma unroll
            for (int j = 0; j < 4; j++) Sacc[ni][j] = 0.f;

#pragma unroll
        for (int ks = 0; ks < 4; ks++) {
            u32 af[4][4];
#pragma unroll
            for (int s = 0; s < 4; s++)
                ldsm_x4(af[s][0], af[s][1], af[s][2], af[s][3],
                        smU + (u32)(QO4[s] * 2) + aWarp + aOff + (u32)(ks * 32));
#pragma unroll
            for (int part = 0; part < 2; part++) {
#pragma unroll
                for (int bk = 0; bk < 2; bk++) {
                    const int nA = 2 - bk;
                    const u32 kb = smU + (u32)(KO4[part * 2 + bk] * 2);
                    u32 bfr[4][4];
#pragma unroll
                    for (int np = 0; np < 4; np++)
                        ldsm_x4(bfr[np][0], bfr[np][1], bfr[np][2], bfr[np][3],
                                kb + (u32)(np * 16 * (KSTR * 2)) + bOff +
                                    (u32)(ks * 32));
#pragma unroll
                    for (int ia = 0; ia < 2; ia++) {
                        if (ia >= nA) break;
#pragma unroll
                        for (int ni = 0; ni < 8; ni++)
                            mma_bf16(Sacc[ni], af[part * 2 + ia],
                                     &bfr[ni >> 1][(ni & 1) * 2]);
                    }
                }
            }
        }

        // ---- online softmax; P -> bf16x2 smem ----
        float mx0 = Sacc[0][0], mx1 = Sacc[0][2];
#pragma unroll
        for (int ni = 0; ni < 8; ni++) {
            mx0 = fmaxf(mx0, fmaxf(Sacc[ni][0], Sacc[ni][1]));
            mx1 = fmaxf(mx1, fmaxf(Sacc[ni][2], Sacc[ni][3]));
        }
        mx0 = fmaxf(mx0, __shfl_xor_sync(0xffffffffu, mx0, 1));
        mx0 = fmaxf(mx0, __shfl_xor_sync(0xffffffffu, mx0, 2));
        mx1 = fmaxf(mx1, __shfl_xor_sync(0xffffffffu, mx1, 1));
        mx1 = fmaxf(mx1, __shfl_xor_sync(0xffffffffu, mx1, 2));
        float mn0 = fmaxf(m0, mx0), mn1 = fmaxf(m1, mx1);
        float c0 = __expf(m0 - mn0), c1 = __expf(m1 - mn1);
        m0 = mn0; m1 = mn1;
        float ps0 = 0.f, ps1 = 0.f;
        const int r0 = wid * 16 + grp;
#pragma unroll
        for (int ni = 0; ni < 8; ni++) {
            float p00 = __expf(Sacc[ni][0] - mn0);
            float p01 = __expf(Sacc[ni][1] - mn0);
            float p10 = __expf(Sacc[ni][2] - mn1);
            float p11 = __expf(Sacc[ni][3] - mn1);
            ps0 += p00 + p01;
            ps1 += p10 + p11;
            int col = ni * 8 + qd * 2;
            __nv_bfloat16 h00 = __float2bfloat16(p00);
            __nv_bfloat16 h01 = __float2bfloat16(p01);
            __nv_bfloat16 h10 = __float2bfloat16(p10);
            __nv_bfloat16 h11 = __float2bfloat16(p11);
            st2h(sm + OPH + r0 * KSTR + col, h00, h01);
            st2h(sm + OPH + (r0 + 8) * KSTR + col, h10, h11);
            st2h(sm + OPM + r0 * KSTR + col,
                 __float2bfloat16(p00 - __bfloat162float(h00)),
                 __float2bfloat16(p01 - __bfloat162float(h01)));
            st2h(sm + OPM + (r0 + 8) * KSTR + col,
                 __float2bfloat16(p10 - __bfloat162float(h10)),
                 __float2bfloat16(p11 - __bfloat162float(h11)));
        }
        ps0 += __shfl_xor_sync(0xffffffffu, ps0, 1);
        ps0 += __shfl_xor_sync(0xffffffffu, ps0, 2);
        ps1 += __shfl_xor_sync(0xffffffffu, ps1, 1);
        ps1 += __shfl_xor_sync(0xffffffffu, ps1, 2);
        l0 = l0 * c0 + ps0;
        l1 = l1 * c1 + ps1;
#pragma unroll
        for (int ni = 0; ni < 8; ni++) {
            Oacc[ni][0] *= c0; Oacc[ni][1] *= c0;
            Oacc[ni][2] *= c1; Oacc[ni][3] *= c1;
        }
        __syncwarp();

        // ---- PV: O += P @ V (hh, hm, mh) ----
#pragma unroll
        for (int vp = 0; vp < 3; vp++) {
            const u32 pb = smU + (u32)(((vp == 2) ? OPM : OPH) * 2) + aWarp;
            const u32 vb = smU + (u32)(((vp == 1) ? OVM : OVH) * 2);
#pragma unroll
            for (int ks = 0; ks < 4; ks++) {
                u32 bfr[4][4];
#pragma unroll
                for (int np = 0; np < 4; np++)
                    ldsm_x4(bfr[np][0], bfr[np][1], bfr[np][2], bfr[np][3],
                            vb + (u32)(np * 16 * (KSTR * 2)) + bOff +
                                (u32)(ks * 32));
                u32 af[4];
                ldsm_x4(af[0], af[1], af[2], af[3], pb + aOff + (u32)(ks * 32));
#pragma unroll
                for (int ni = 0; ni < 8; ni++)
                    mma_bf16(Oacc[ni], af, &bfr[ni >> 1][(ni & 1) * 2]);
            }
        }
    }

    // ---- epilogue: normalize, split bf16 h/m, write [b, t, h*64+d] ----
    float il0 = 1.f / l0, il1 = 1.f / l1;
    const int r0e = wid * 16 + grp;
#pragma unroll
    for (int ni = 0; ni < 8; ni++) {
        int col = h * HDIM + ni * 8 + qd * 2;
#pragma unroll
        for (int rr = 0; rr < 2; rr++) {
            int row = r0e + rr * 8;
            float sc = rr ? il1 : il0;
            float v0 = Oacc[ni][rr * 2 + 0] * sc;
            float v1 = Oacc[ni][rr * 2 + 1] * sc;
            size_t off = ((size_t)(b * TT + t0 + row)) * CC + col;
            __nv_bfloat16 h0 = __float2bfloat16(v0);
            __nv_bfloat16 h1 = __float2bfloat16(v1);
            st2h(&Oh[off], h0, h1);
            st2h(&Om[off], __float2bfloat16(v0 - __bfloat162float(h0)),
                 __float2bfloat16(v1 - __bfloat162float(h1)));
        }
    }
}

// ----------------------------------------------------------------------------
// Final energy ratio
// ----------------------------------------------------------------------------
__global__ void finalize_kernel(const float* __restrict__ Y,
                                const float* __restrict__ enorm,
                                float* __restrict__ out) {
    int row = blockIdx.x;
    const float* yr = Y + (size_t)row * CC;
    float s = 0.f;
    for (int c = threadIdx.x; c < CC; c += 256) {
        float v = yr[c];
        s += v * v;
    }
    float tot = blockReduceSum256(s);
    __shared__ float ratio;
    if (threadIdx.x == 0)
        ratio = g_inE[row] / (sqrtf(tot) + 1e-8f) * enorm[0];
    __syncthreads();
    for (int c = threadIdx.x; c < CC; c += 256)
        out[(size_t)row * CC + c] = yr[c] * ratio;
}

// ----------------------------------------------------------------------------
// Launch
// ----------------------------------------------------------------------------
extern "C" void kernel_launch(void* const* d_in, const int* in_sizes, int n_in,
                              void* d_out, int out_size) {
    const float* x      = (const float*)d_in[0];
    const float* fd     = (const float*)d_in[1];
    const float* wq     = (const float*)d_in[2];
    const float* bq     = (const float*)d_in[3];
    const float* wk     = (const float*)d_in[4];
    const float* bk     = (const float*)d_in[5];
    const float* wv     = (const float*)d_in[6];
    const float* bv     = (const float*)d_in[7];
    const float* wo     = (const float*)d_in[8];
    const float* bo     = (const float*)d_in[9];
    const float* alpha  = (const float*)d_in[10];
    const float* fas    = (const float*)d_in[11];
    const float* enorm  = (const float*)d_in[12];
    float* out = (float*)d_out;

    float *q, *k, *v, *y;
    __nv_bfloat16 *xh, *xm, *wt, *qs, *ks, *vs;
    cudaGetSymbolAddress((void**)&q,  g_q);
    cudaGetSymbolAddress((void**)&k,  g_k);
    cudaGetSymbolAddress((void**)&v,  g_v);
    cudaGetSymbolAddress((void**)&y,  g_y);
    cudaGetSymbolAddress((void**)&xh, g_xh);
    cudaGetSymbolAddress((void**)&xm, g_xm);
    cudaGetSymbolAddress((void**)&wt, g_wt);
    cudaGetSymbolAddress((void**)&qs, g_qs);
    cudaGetSymbolAddress((void**)&ks, g_ks);
    cudaGetSymbolAddress((void**)&vs, g_vs);
    const size_t WSZ = (size_t)CC * CC;

    // fused: input energies + x split (h,m)
    energy_split_kernel<<<BT, 256>>>(x, xh, xm);

    // weight transpose+split (all 4 weights, one launch; h,m only)
    dim3 wg(32, 32, 4), wb(32, 8);
    wsplit4_kernel<<<wg, wb>>>(wq, wk, wv, wo, wt);

    // QKV projections on tensor cores (3-pass each)
    static const int kTcSmem = 2 * 2 * 2 * 128 * ASTRIDE * (int)sizeof(__nv_bfloat16);
    cudaFuncSetAttribute(tc_gemm3_kernel,
                         cudaFuncAttributeMaxDynamicSharedMemorySize, kTcSmem);
    cudaFuncSetAttribute(tc_gemm_kernel,
                         cudaFuncAttributeMaxDynamicSharedMemorySize, kTcSmem);
    dim3 gg3(CC / 128, BT / 128, 3);
    tc_gemm3_kernel<<<gg3, 256, kTcSmem>>>(xh, xm, wt, bq, bk, bv, q, k, v);

    // FFT + spectral filter -> bf16 (h,m) split operands for attention
    static const int kFftSmem = TT * FSTR * (int)sizeof(float2);
    cudaFuncSetAttribute(fft_filter_kernel,
                         cudaFuncAttributeMaxDynamicSharedMemorySize, kFftSmem);
    dim3 gf(HDIM / 16, HH * 3, BB);
    fft_filter_kernel<<<gf, 256, kFftSmem>>>(q, k, v, qs, ks, vs,
                                             fd, alpha, fas);

    // tensor-core attention
    cudaFuncSetAttribute(attn_kernel, cudaFuncAttributeMaxDynamicSharedMemorySize,
                         ATTN_SMEM_BYTES);
    dim3 ga(TT / 128, HH, BB);
    attn_kernel<<<ga, 256, ATTN_SMEM_BYTES>>>(qs, ks, vs, xh, xm);

    // output projection (3-pass)
    dim3 gg(CC / 128, BT / 128);
    tc_gemm_kernel<<<gg, 256, kTcSmem>>>(xh, xm,
                                         wt + 9 * WSZ, wt + 10 * WSZ,
                                         bo, y);

    // energy-ratio epilogue
    finalize_kernel<<<BT, 256>>>(y, enorm, out);
}